// round 1
// baseline (speedup 1.0000x reference)
#include <cuda_runtime.h>

// ---------------- problem dims ----------------
#define Bc   1024
#define Tc   100
#define Dc   256
#define Hc   256   // encoder hidden
#define Gc   1024  // 4*Hc
#define Mc   64    // decoder hidden / bottleneck
#define GMc  256   // 4*Mc

// ---------------- device scratch (no allocs allowed) ----------------
__device__ float g_xg  [(size_t)Bc * Tc * Gc];   // xg0, then xg1 (419 MB)
__device__ float g_mid [(size_t)Bc * Tc * Hc];   // h_enc0, then xg_dec1 (105 MB)
__device__ float g_bufA[(size_t)Bc * Tc * Mc];   // h0, then d0 (26 MB)
__device__ float g_bufB[(size_t)Bc * Tc * Mc];   // d1 (26 MB)
__device__ float g_z   [Bc * Hc];
__device__ float g_xgd0[Bc * GMc];
__device__ float g_wTe0[Hc * Gc];
__device__ float g_wTe1[Hc * Gc];
__device__ float g_wTd0[Mc * GMc];
__device__ float g_wTd1[Mc * GMc];

// ---------------- f32x2 helpers ----------------
__device__ __forceinline__ unsigned long long pack2f(float x, float y) {
    unsigned long long r;
    asm("mov.b64 %0, {%1, %2};" : "=l"(r) : "f"(x), "f"(y));
    return r;
}
__device__ __forceinline__ float2 unpack2f(unsigned long long v) {
    float2 r;
    asm("mov.b64 {%0, %1}, %2;" : "=f"(r.x), "=f"(r.y) : "l"(v));
    return r;
}
__device__ __forceinline__ unsigned long long fma2f(unsigned long long a,
                                                    unsigned long long b,
                                                    unsigned long long c) {
    unsigned long long d;
    asm("fma.rn.f32x2 %0, %1, %2, %3;" : "=l"(d) : "l"(a), "l"(b), "l"(c));
    return d;
}

__device__ __forceinline__ float sigmoidf_(float x) {
    return 1.0f / (1.0f + expf(-x));
}

// ---------------- transpose (R x C) -> (C x R) ----------------
__global__ void transpose32(const float* __restrict__ src, float* __restrict__ dst,
                            int R, int C) {
    __shared__ float tile[32][33];
    int bx = blockIdx.x * 32;  // col offset in src
    int by = blockIdx.y * 32;  // row offset in src
    int x = threadIdx.x, y = threadIdx.y;
#pragma unroll
    for (int i = 0; i < 32; i += 8)
        tile[y + i][x] = src[(size_t)(by + y + i) * C + bx + x];
    __syncthreads();
#pragma unroll
    for (int i = 0; i < 32; i += 8)
        dst[(size_t)(bx + y + i) * R + by + x] = tile[x][y + i];
}

// ---------------- GEMM: C[M,N] = act(A[M,K] @ W[N,K]^T + b1 (+ b2)) ----------------
// BM=128, BN=64, BK=16, 256 threads, 8x4 micro-tile, f32x2 accumulation.
template <bool RELU, bool HASB2>
__global__ void __launch_bounds__(256) gemm_tn(
    const float* __restrict__ A, const float* __restrict__ W,
    const float* __restrict__ b1, const float* __restrict__ b2,
    float* __restrict__ C, int Mdim, int Ndim, int Kdim) {
    constexpr int BM = 128, BN = 64, BK = 16;
    __shared__ float As[BK][BM];
    __shared__ float Ws[BK][BN];

    const int tid = threadIdx.x;
    const int tx = tid & 15;   // 0..15 -> 4 cols
    const int ty = tid >> 4;   // 0..15 -> 8 rows
    const size_t bm = (size_t)blockIdx.x * BM;
    const size_t bn = (size_t)blockIdx.y * BN;

    const int lr = tid >> 2;          // 0..63
    const int lk = (tid & 3) << 2;    // 0,4,8,12

    unsigned long long acc[4][4];
#pragma unroll
    for (int i = 0; i < 4; i++)
#pragma unroll
        for (int j = 0; j < 4; j++) acc[i][j] = 0ull;

    const float* Ap0 = A + (bm + lr) * (size_t)Kdim + lk;
    const float* Ap1 = A + (bm + lr + 64) * (size_t)Kdim + lk;
    const float* Wp  = W + (bn + lr) * (size_t)Kdim + lk;

    for (int k0 = 0; k0 < Kdim; k0 += BK) {
        float4 av0 = *(const float4*)(Ap0 + k0);
        float4 av1 = *(const float4*)(Ap1 + k0);
        float4 wv  = *(const float4*)(Wp + k0);
        __syncthreads();
        As[lk + 0][lr] = av0.x; As[lk + 1][lr] = av0.y;
        As[lk + 2][lr] = av0.z; As[lk + 3][lr] = av0.w;
        As[lk + 0][lr + 64] = av1.x; As[lk + 1][lr + 64] = av1.y;
        As[lk + 2][lr + 64] = av1.z; As[lk + 3][lr + 64] = av1.w;
        Ws[lk + 0][lr] = wv.x; Ws[lk + 1][lr] = wv.y;
        Ws[lk + 2][lr] = wv.z; Ws[lk + 3][lr] = wv.w;
        __syncthreads();
#pragma unroll
        for (int kk = 0; kk < BK; kk++) {
            float4 a0 = *(const float4*)&As[kk][ty * 8];
            float4 a1 = *(const float4*)&As[kk][ty * 8 + 4];
            float4 w4 = *(const float4*)&Ws[kk][tx * 4];
            unsigned long long a2[4] = {pack2f(a0.x, a0.y), pack2f(a0.z, a0.w),
                                        pack2f(a1.x, a1.y), pack2f(a1.z, a1.w)};
            unsigned long long w2[4] = {pack2f(w4.x, w4.x), pack2f(w4.y, w4.y),
                                        pack2f(w4.z, w4.z), pack2f(w4.w, w4.w)};
#pragma unroll
            for (int i = 0; i < 4; i++)
#pragma unroll
                for (int j = 0; j < 4; j++)
                    acc[i][j] = fma2f(a2[i], w2[j], acc[i][j]);
        }
    }

    float bias[4];
#pragma unroll
    for (int j = 0; j < 4; j++) {
        bias[j] = b1[bn + tx * 4 + j];
        if (HASB2) bias[j] += b2[bn + tx * 4 + j];
    }
#pragma unroll
    for (int i = 0; i < 4; i++) {
        float2 v0 = unpack2f(acc[i][0]);
        float2 v1 = unpack2f(acc[i][1]);
        float2 v2 = unpack2f(acc[i][2]);
        float2 v3 = unpack2f(acc[i][3]);
        float4 o0 = make_float4(v0.x + bias[0], v1.x + bias[1], v2.x + bias[2], v3.x + bias[3]);
        float4 o1 = make_float4(v0.y + bias[0], v1.y + bias[1], v2.y + bias[2], v3.y + bias[3]);
        if (RELU) {
            o0.x = fmaxf(o0.x, 0.f); o0.y = fmaxf(o0.y, 0.f);
            o0.z = fmaxf(o0.z, 0.f); o0.w = fmaxf(o0.w, 0.f);
            o1.x = fmaxf(o1.x, 0.f); o1.y = fmaxf(o1.y, 0.f);
            o1.z = fmaxf(o1.z, 0.f); o1.w = fmaxf(o1.w, 0.f);
        }
        size_t r0 = bm + ty * 8 + 2 * i;
        *(float4*)&C[r0 * Ndim + bn + tx * 4]       = o0;
        *(float4*)&C[(r0 + 1) * Ndim + bn + tx * 4] = o1;
    }
}

// ---------------- encoder LSTM layer (H=256), persistent, 8 rows/CTA ----------------
// xg: (B,T,1024) precomputed x@Wih^T + bih + bhh. wT: (256,1024) = Whh^T (transposed).
// h_all (B,T,256) optional; z_last (B,256) optional (written at t=T-1).
__global__ void __launch_bounds__(256) lstm_enc_kernel(
    const float* __restrict__ xg, const float* __restrict__ wT,
    float* __restrict__ h_all, float* __restrict__ z_last) {
    constexpr int ROWS = 8;
    const int b0 = blockIdx.x * ROWS;
    const int j = threadIdx.x;  // hidden unit 0..255 (owns gates j, 256+j, 512+j, 768+j)

    __shared__ float2 sh_h[Hc][ROWS / 2];  // [k][row-pair] = 8 KB

    float c[ROWS];
#pragma unroll
    for (int r = 0; r < ROWS; r++) c[r] = 0.f;
#pragma unroll
    for (int rp = 0; rp < ROWS / 2; rp++) sh_h[j][rp] = make_float2(0.f, 0.f);
    __syncthreads();

#pragma unroll 1
    for (int t = 0; t < Tc; t++) {
        unsigned long long acc[4][ROWS / 2];
#pragma unroll
        for (int g4 = 0; g4 < 4; g4++)
#pragma unroll
            for (int rp = 0; rp < ROWS / 2; rp++) {
                float lo = xg[((size_t)(b0 + 2 * rp) * Tc + t) * Gc + g4 * Hc + j];
                float hi = xg[((size_t)(b0 + 2 * rp + 1) * Tc + t) * Gc + g4 * Hc + j];
                acc[g4][rp] = pack2f(lo, hi);
            }

#pragma unroll 2
        for (int k = 0; k < Hc; k++) {
            unsigned long long h2[ROWS / 2];
#pragma unroll
            for (int rp = 0; rp < ROWS / 2; rp++) {
                float2 v = sh_h[k][rp];
                h2[rp] = pack2f(v.x, v.y);
            }
            const float* wrow = wT + (size_t)k * Gc + j;
#pragma unroll
            for (int g4 = 0; g4 < 4; g4++) {
                float w = __ldg(wrow + g4 * Hc);
                unsigned long long w2 = pack2f(w, w);
#pragma unroll
                for (int rp = 0; rp < ROWS / 2; rp++)
                    acc[g4][rp] = fma2f(h2[rp], w2, acc[g4][rp]);
            }
        }
        __syncthreads();  // all reads of sh_h done

#pragma unroll
        for (int rp = 0; rp < ROWS / 2; rp++) {
            float2 iv = unpack2f(acc[0][rp]);
            float2 fv = unpack2f(acc[1][rp]);
            float2 gv = unpack2f(acc[2][rp]);
            float2 ov = unpack2f(acc[3][rp]);
            float2 hv;
            {
                float i_ = sigmoidf_(iv.x), f_ = sigmoidf_(fv.x);
                float g_ = tanhf(gv.x),     o_ = sigmoidf_(ov.x);
                c[2 * rp] = f_ * c[2 * rp] + i_ * g_;
                hv.x = o_ * tanhf(c[2 * rp]);
            }
            {
                float i_ = sigmoidf_(iv.y), f_ = sigmoidf_(fv.y);
                float g_ = tanhf(gv.y),     o_ = sigmoidf_(ov.y);
                c[2 * rp + 1] = f_ * c[2 * rp + 1] + i_ * g_;
                hv.y = o_ * tanhf(c[2 * rp + 1]);
            }
            sh_h[j][rp] = hv;
            if (h_all) {
                h_all[((size_t)(b0 + 2 * rp) * Tc + t) * Hc + j]     = hv.x;
                h_all[((size_t)(b0 + 2 * rp + 1) * Tc + t) * Hc + j] = hv.y;
            }
            if (z_last && t == Tc - 1) {
                z_last[(size_t)(b0 + 2 * rp) * Hc + j]     = hv.x;
                z_last[(size_t)(b0 + 2 * rp + 1) * Hc + j] = hv.y;
            }
        }
        __syncthreads();  // sh_h writes visible for next step
    }
}

// ---------------- decoder LSTM layer (H=64), persistent, 8 rows/CTA ----------------
// xg: (B,GM) if !xg_per_t (constant input), else (B,T,GM). wT: (64,256) = Whh^T.
// h_out: (B,T,64).
__global__ void __launch_bounds__(256) lstm_dec_kernel(
    const float* __restrict__ xg, const float* __restrict__ wT,
    float* __restrict__ h_out, int xg_per_t) {
    constexpr int ROWS = 8;
    const int b0 = blockIdx.x * ROWS;
    const int j = threadIdx.x & 63;   // hidden unit 0..63
    const int rg = threadIdx.x >> 6;  // row group 0..3 -> rows rg, rg+4

    __shared__ float sh_h[Mc][ROWS];  // [k][row] = 2 KB
    for (int idx = threadIdx.x; idx < Mc * ROWS; idx += 256)
        ((float*)sh_h)[idx] = 0.f;

    float c[2] = {0.f, 0.f};
    float base[4][2];
    if (!xg_per_t) {
#pragma unroll
        for (int g4 = 0; g4 < 4; g4++)
#pragma unroll
            for (int ri = 0; ri < 2; ri++)
                base[g4][ri] = xg[(size_t)(b0 + rg + 4 * ri) * GMc + g4 * Mc + j];
    }
    __syncthreads();

#pragma unroll 1
    for (int t = 0; t < Tc; t++) {
        float acc[4][2];
        if (xg_per_t) {
#pragma unroll
            for (int g4 = 0; g4 < 4; g4++)
#pragma unroll
                for (int ri = 0; ri < 2; ri++)
                    acc[g4][ri] = xg[((size_t)(b0 + rg + 4 * ri) * Tc + t) * GMc + g4 * Mc + j];
        } else {
#pragma unroll
            for (int g4 = 0; g4 < 4; g4++)
#pragma unroll
                for (int ri = 0; ri < 2; ri++) acc[g4][ri] = base[g4][ri];
        }

#pragma unroll 4
        for (int k = 0; k < Mc; k++) {
            float h0 = sh_h[k][rg];
            float h1 = sh_h[k][rg + 4];
            const float* wrow = wT + (size_t)k * GMc + j;
#pragma unroll
            for (int g4 = 0; g4 < 4; g4++) {
                float w = __ldg(wrow + g4 * Mc);
                acc[g4][0] = fmaf(h0, w, acc[g4][0]);
                acc[g4][1] = fmaf(h1, w, acc[g4][1]);
            }
        }
        __syncthreads();

#pragma unroll
        for (int ri = 0; ri < 2; ri++) {
            int r = rg + 4 * ri;
            float i_ = sigmoidf_(acc[0][ri]), f_ = sigmoidf_(acc[1][ri]);
            float g_ = tanhf(acc[2][ri]),     o_ = sigmoidf_(acc[3][ri]);
            c[ri] = f_ * c[ri] + i_ * g_;
            float h = o_ * tanhf(c[ri]);
            sh_h[j][r] = h;
            h_out[((size_t)(b0 + r) * Tc + t) * Mc + j] = h;
        }
        __syncthreads();
    }
}

// ---------------- launch ----------------
extern "C" void kernel_launch(void* const* d_in, const int* in_sizes, int n_in,
                              void* d_out, int out_size) {
    const float* x    = (const float*)d_in[0];
    const float* in_W = (const float*)d_in[1];
    const float* in_b = (const float*)d_in[2];
    const float* eW0i = (const float*)d_in[3];
    const float* eW0h = (const float*)d_in[4];
    const float* eb0i = (const float*)d_in[5];
    const float* eb0h = (const float*)d_in[6];
    const float* eW1i = (const float*)d_in[7];
    const float* eW1h = (const float*)d_in[8];
    const float* eb1i = (const float*)d_in[9];
    const float* eb1h = (const float*)d_in[10];
    const float* dW0i = (const float*)d_in[11];
    const float* dW0h = (const float*)d_in[12];
    const float* db0i = (const float*)d_in[13];
    const float* db0h = (const float*)d_in[14];
    const float* dW1i = (const float*)d_in[15];
    const float* dW1h = (const float*)d_in[16];
    const float* db1i = (const float*)d_in[17];
    const float* db1h = (const float*)d_in[18];
    const float* outW = (const float*)d_in[19];
    const float* outb = (const float*)d_in[20];
    float* out = (float*)d_out;

    float *xg, *mid, *bufA, *bufB, *z, *xgd0, *wTe0, *wTe1, *wTd0, *wTd1;
    cudaGetSymbolAddress((void**)&xg,   g_xg);
    cudaGetSymbolAddress((void**)&mid,  g_mid);
    cudaGetSymbolAddress((void**)&bufA, g_bufA);
    cudaGetSymbolAddress((void**)&bufB, g_bufB);
    cudaGetSymbolAddress((void**)&z,    g_z);
    cudaGetSymbolAddress((void**)&xgd0, g_xgd0);
    cudaGetSymbolAddress((void**)&wTe0, g_wTe0);
    cudaGetSymbolAddress((void**)&wTe1, g_wTe1);
    cudaGetSymbolAddress((void**)&wTd0, g_wTd0);
    cudaGetSymbolAddress((void**)&wTd1, g_wTd1);

    const int MT = Bc * Tc;  // 102400

    // Weight transposes for coalesced recurrent reads
    transpose32<<<dim3(Hc / 32, Gc / 32), dim3(32, 8)>>>(eW0h, wTe0, Gc, Hc);
    transpose32<<<dim3(Hc / 32, Gc / 32), dim3(32, 8)>>>(eW1h, wTe1, Gc, Hc);
    transpose32<<<dim3(Mc / 32, GMc / 32), dim3(32, 8)>>>(dW0h, wTd0, GMc, Mc);
    transpose32<<<dim3(Mc / 32, GMc / 32), dim3(32, 8)>>>(dW1h, wTd1, GMc, Mc);

    // 1) h0 = relu(x @ in_W^T + in_b)                : (102400,64)
    gemm_tn<true, false><<<dim3(MT / 128, Mc / 64), 256>>>(x, in_W, in_b, nullptr, bufA, MT, Mc, Dc);
    // 2) xg0 = h0 @ eW0i^T + eb0i + eb0h             : (102400,1024)
    gemm_tn<false, true><<<dim3(MT / 128, Gc / 64), 256>>>(bufA, eW0i, eb0i, eb0h, xg, MT, Gc, Mc);
    // 3) enc0 recurrence -> h_enc0                    : (102400,256)
    lstm_enc_kernel<<<Bc / 8, 256>>>(xg, wTe0, mid, nullptr);
    // 4) xg1 = h_enc0 @ eW1i^T + eb1i + eb1h         : (102400,1024)
    gemm_tn<false, true><<<dim3(MT / 128, Gc / 64), 256>>>(mid, eW1i, eb1i, eb1h, xg, MT, Gc, Hc);
    // 5) enc1 recurrence -> z (last h only)           : (1024,256)
    lstm_enc_kernel<<<Bc / 8, 256>>>(xg, wTe1, nullptr, z);
    // 6) xg_dec0 = z @ dW0i^T + db0i + db0h (t-const!): (1024,256)
    gemm_tn<false, true><<<dim3(Bc / 128, GMc / 64), 256>>>(z, dW0i, db0i, db0h, xgd0, Bc, GMc, Hc);
    // 7) dec0 recurrence -> d0                        : (102400,64)
    lstm_dec_kernel<<<Bc / 8, 256>>>(xgd0, wTd0, bufA, 0);
    // 8) xg_dec1 = d0 @ dW1i^T + db1i + db1h         : (102400,256)
    gemm_tn<false, true><<<dim3(MT / 128, GMc / 64), 256>>>(bufA, dW1i, db1i, db1h, mid, MT, GMc, Mc);
    // 9) dec1 recurrence -> d1                        : (102400,64)
    lstm_dec_kernel<<<Bc / 8, 256>>>(mid, wTd1, bufB, 1);
    // 10) out = d1 @ out_W^T + out_b                  : (102400,256)
    gemm_tn<false, false><<<dim3(MT / 128, Dc / 64), 256>>>(bufB, outW, outb, nullptr, out, MT, Dc, Mc);
}

// round 2
// speedup vs baseline: 2.4068x; 2.4068x over previous
#include <cuda_runtime.h>

// ---------------- problem dims ----------------
#define Bc   1024
#define Tc   100
#define Dc   256
#define Hc   256   // encoder hidden
#define Gc   1024  // 4*Hc
#define Mc   64    // decoder hidden / bottleneck
#define GMc  256   // 4*Mc

typedef unsigned long long ull;

// ---------------- device scratch (no allocs allowed) ----------------
__device__ float g_xg  [(size_t)Bc * Tc * Gc];   // xg0 / xg1 (419 MB)
__device__ float g_mid [(size_t)Bc * Tc * Hc];   // h_enc0, then xg_dec1
__device__ float g_bufA[(size_t)Bc * Tc * Mc];   // h0, then d0
__device__ float g_bufB[(size_t)Bc * Tc * Mc];   // d1
__device__ float g_z   [Bc * Hc];
__device__ float g_xgd0[Bc * GMc];
// interleaved float4 weights [k][j] = {w_i, w_f, w_g, w_o}; padded for prefetch overread
__device__ float g_w4e0[(Hc * Hc + 2048) * 4];
__device__ float g_w4e1[(Hc * Hc + 2048) * 4];
__device__ float g_w4d0[(Mc * Mc + 1024) * 4];
__device__ float g_w4d1[(Mc * Mc + 1024) * 4];

// ---------------- f32x2 helpers ----------------
__device__ __forceinline__ ull pack2f(float x, float y) {
    ull r; asm("mov.b64 %0, {%1, %2};" : "=l"(r) : "f"(x), "f"(y)); return r;
}
__device__ __forceinline__ float2 unpack2f(ull v) {
    float2 r; asm("mov.b64 {%0, %1}, %2;" : "=f"(r.x), "=f"(r.y) : "l"(v)); return r;
}
__device__ __forceinline__ ull fma2f(ull a, ull b, ull c) {
    ull d; asm("fma.rn.f32x2 %0, %1, %2, %3;" : "=l"(d) : "l"(a), "l"(b), "l"(c)); return d;
}

__device__ __forceinline__ float sigf(float x) {
    return __fdividef(1.0f, 1.0f + __expf(-x));
}
// NaN-safe fast tanh: 1 - 2/(e^{2x}+1); e->inf => 1, e->0 => -1
__device__ __forceinline__ float tanh_(float x) {
    return 1.0f - __fdividef(2.0f, __expf(2.0f * x) + 1.0f);
}

// ---------------- weight prep: src (4H x H) -> dst float4[H][H] ----------------
// dst[(k*H + j)*4 + g] = src[(g*H + j)*H + k]
__global__ void prep_w4(const float* __restrict__ src, float* __restrict__ dst, int H) {
    __shared__ float tile[32][33];
    int g = blockIdx.z;
    int k0 = blockIdx.x * 32, j0 = blockIdx.y * 32;
    int x = threadIdx.x, y = threadIdx.y;
#pragma unroll
    for (int i = 0; i < 32; i += 8)
        tile[y + i][x] = src[(size_t)(g * H + j0 + y + i) * H + k0 + x];
    __syncthreads();
#pragma unroll
    for (int i = 0; i < 32; i += 8)
        dst[((size_t)(k0 + y + i) * H + (j0 + x)) * 4 + g] = tile[x][y + i];
}

// ---------------- GEMM (BM=128, BN=64) for N=64 case ----------------
template <bool RELU, bool HASB2>
__global__ void __launch_bounds__(256) gemm64(
    const float* __restrict__ A, const float* __restrict__ W,
    const float* __restrict__ b1, const float* __restrict__ b2,
    float* __restrict__ C, int Mdim, int Ndim, int Kdim) {
    constexpr int BK = 16;
    __shared__ float As[BK][128];
    __shared__ float Ws[BK][64];

    const int tid = threadIdx.x;
    const int tx = tid & 15;
    const int ty = tid >> 4;
    const size_t bm = (size_t)blockIdx.x * 128;
    const size_t bn = (size_t)blockIdx.y * 64;
    const int lr = tid >> 2;
    const int lk = (tid & 3) << 2;

    ull acc[4][4];
#pragma unroll
    for (int i = 0; i < 4; i++)
#pragma unroll
        for (int j = 0; j < 4; j++) acc[i][j] = 0ull;

    const float* Ap0 = A + (bm + lr) * (size_t)Kdim + lk;
    const float* Ap1 = A + (bm + lr + 64) * (size_t)Kdim + lk;
    const float* Wp  = W + (bn + lr) * (size_t)Kdim + lk;

    for (int k0 = 0; k0 < Kdim; k0 += BK) {
        float4 av0 = *(const float4*)(Ap0 + k0);
        float4 av1 = *(const float4*)(Ap1 + k0);
        float4 wv  = *(const float4*)(Wp + k0);
        __syncthreads();
        As[lk + 0][lr] = av0.x; As[lk + 1][lr] = av0.y;
        As[lk + 2][lr] = av0.z; As[lk + 3][lr] = av0.w;
        As[lk + 0][lr + 64] = av1.x; As[lk + 1][lr + 64] = av1.y;
        As[lk + 2][lr + 64] = av1.z; As[lk + 3][lr + 64] = av1.w;
        Ws[lk + 0][lr] = wv.x; Ws[lk + 1][lr] = wv.y;
        Ws[lk + 2][lr] = wv.z; Ws[lk + 3][lr] = wv.w;
        __syncthreads();
#pragma unroll
        for (int kk = 0; kk < BK; kk++) {
            float4 a0 = *(const float4*)&As[kk][ty * 8];
            float4 a1 = *(const float4*)&As[kk][ty * 8 + 4];
            float4 w4 = *(const float4*)&Ws[kk][tx * 4];
            ull a2[4] = {pack2f(a0.x, a0.y), pack2f(a0.z, a0.w),
                         pack2f(a1.x, a1.y), pack2f(a1.z, a1.w)};
            ull w2[4] = {pack2f(w4.x, w4.x), pack2f(w4.y, w4.y),
                         pack2f(w4.z, w4.z), pack2f(w4.w, w4.w)};
#pragma unroll
            for (int i = 0; i < 4; i++)
#pragma unroll
                for (int j = 0; j < 4; j++)
                    acc[i][j] = fma2f(a2[i], w2[j], acc[i][j]);
        }
    }

    float bias[4];
#pragma unroll
    for (int j = 0; j < 4; j++) {
        bias[j] = b1[bn + tx * 4 + j];
        if (HASB2) bias[j] += b2[bn + tx * 4 + j];
    }
#pragma unroll
    for (int i = 0; i < 4; i++) {
        float2 v0 = unpack2f(acc[i][0]);
        float2 v1 = unpack2f(acc[i][1]);
        float2 v2 = unpack2f(acc[i][2]);
        float2 v3 = unpack2f(acc[i][3]);
        float4 o0 = make_float4(v0.x + bias[0], v1.x + bias[1], v2.x + bias[2], v3.x + bias[3]);
        float4 o1 = make_float4(v0.y + bias[0], v1.y + bias[1], v2.y + bias[2], v3.y + bias[3]);
        if (RELU) {
            o0.x = fmaxf(o0.x, 0.f); o0.y = fmaxf(o0.y, 0.f);
            o0.z = fmaxf(o0.z, 0.f); o0.w = fmaxf(o0.w, 0.f);
            o1.x = fmaxf(o1.x, 0.f); o1.y = fmaxf(o1.y, 0.f);
            o1.z = fmaxf(o1.z, 0.f); o1.w = fmaxf(o1.w, 0.f);
        }
        size_t r0 = bm + ty * 8 + 2 * i;
        *(float4*)&C[r0 * Ndim + bn + tx * 4]       = o0;
        *(float4*)&C[(r0 + 1) * Ndim + bn + tx * 4] = o1;
    }
}

// ---------------- GEMM (BM=128, BN=128), 8x8 micro-tile, f32x2 ----------------
template <bool RELU, bool HASB2>
__global__ void __launch_bounds__(256) gemm128(
    const float* __restrict__ A, const float* __restrict__ W,
    const float* __restrict__ b1, const float* __restrict__ b2,
    float* __restrict__ C, int Mdim, int Ndim, int Kdim) {
    constexpr int BK = 16;
    __shared__ float As[BK][128];
    __shared__ float Ws[BK][128];

    const int tid = threadIdx.x;
    const int tx = tid & 15;    // 0..15 -> 8 cols
    const int ty = tid >> 4;    // 0..15 -> 8 rows
    const size_t bm = (size_t)blockIdx.x * 128;
    const size_t bn = (size_t)blockIdx.y * 128;
    const int lr = tid >> 2;         // 0..63
    const int lk = (tid & 3) << 2;   // 0,4,8,12

    ull acc[4][8];
#pragma unroll
    for (int i = 0; i < 4; i++)
#pragma unroll
        for (int j = 0; j < 8; j++) acc[i][j] = 0ull;

    const float* Ap0 = A + (bm + lr) * (size_t)Kdim + lk;
    const float* Ap1 = A + (bm + lr + 64) * (size_t)Kdim + lk;
    const float* Wp0 = W + (bn + lr) * (size_t)Kdim + lk;
    const float* Wp1 = W + (bn + lr + 64) * (size_t)Kdim + lk;

    for (int k0 = 0; k0 < Kdim; k0 += BK) {
        float4 a0 = *(const float4*)(Ap0 + k0);
        float4 a1 = *(const float4*)(Ap1 + k0);
        float4 w0 = *(const float4*)(Wp0 + k0);
        float4 w1 = *(const float4*)(Wp1 + k0);
        __syncthreads();
        As[lk + 0][lr] = a0.x; As[lk + 1][lr] = a0.y;
        As[lk + 2][lr] = a0.z; As[lk + 3][lr] = a0.w;
        As[lk + 0][lr + 64] = a1.x; As[lk + 1][lr + 64] = a1.y;
        As[lk + 2][lr + 64] = a1.z; As[lk + 3][lr + 64] = a1.w;
        Ws[lk + 0][lr] = w0.x; Ws[lk + 1][lr] = w0.y;
        Ws[lk + 2][lr] = w0.z; Ws[lk + 3][lr] = w0.w;
        Ws[lk + 0][lr + 64] = w1.x; Ws[lk + 1][lr + 64] = w1.y;
        Ws[lk + 2][lr + 64] = w1.z; Ws[lk + 3][lr + 64] = w1.w;
        __syncthreads();
#pragma unroll
        for (int kk = 0; kk < BK; kk++) {
            float4 av0 = *(const float4*)&As[kk][ty * 8];
            float4 av1 = *(const float4*)&As[kk][ty * 8 + 4];
            float4 wv0 = *(const float4*)&Ws[kk][tx * 8];
            float4 wv1 = *(const float4*)&Ws[kk][tx * 8 + 4];
            ull ar[4] = {pack2f(av0.x, av0.y), pack2f(av0.z, av0.w),
                         pack2f(av1.x, av1.y), pack2f(av1.z, av1.w)};
            ull wc[8] = {pack2f(wv0.x, wv0.x), pack2f(wv0.y, wv0.y),
                         pack2f(wv0.z, wv0.z), pack2f(wv0.w, wv0.w),
                         pack2f(wv1.x, wv1.x), pack2f(wv1.y, wv1.y),
                         pack2f(wv1.z, wv1.z), pack2f(wv1.w, wv1.w)};
#pragma unroll
            for (int i = 0; i < 4; i++)
#pragma unroll
                for (int j = 0; j < 8; j++)
                    acc[i][j] = fma2f(ar[i], wc[j], acc[i][j]);
        }
    }

    float bias[8];
#pragma unroll
    for (int j = 0; j < 8; j++) {
        bias[j] = b1[bn + tx * 8 + j];
        if (HASB2) bias[j] += b2[bn + tx * 8 + j];
    }
#pragma unroll
    for (int i = 0; i < 4; i++) {
        float lo[8], hi[8];
#pragma unroll
        for (int j = 0; j < 8; j++) {
            float2 v = unpack2f(acc[i][j]);
            lo[j] = v.x + bias[j];
            hi[j] = v.y + bias[j];
            if (RELU) { lo[j] = fmaxf(lo[j], 0.f); hi[j] = fmaxf(hi[j], 0.f); }
        }
        size_t r0 = bm + ty * 8 + 2 * i;
        float* p0 = &C[r0 * Ndim + bn + tx * 8];
        float* p1 = &C[(r0 + 1) * Ndim + bn + tx * 8];
        *(float4*)p0       = make_float4(lo[0], lo[1], lo[2], lo[3]);
        *(float4*)(p0 + 4) = make_float4(lo[4], lo[5], lo[6], lo[7]);
        *(float4*)p1       = make_float4(hi[0], hi[1], hi[2], hi[3]);
        *(float4*)(p1 + 4) = make_float4(hi[4], hi[5], hi[6], hi[7]);
    }
}

// ---------------- encoder LSTM (H=256), 8 rows/CTA, float4 weights ----------------
#define EPROC(KK, WV)                                                              \
    {                                                                              \
        float4 hA = *(const float4*)&shc[(KK)][0];                                 \
        float4 hB = *(const float4*)&shc[(KK)][2];                                 \
        ull h0 = pack2f(hA.x, hA.y), h1 = pack2f(hA.z, hA.w);                      \
        ull h2 = pack2f(hB.x, hB.y), h3 = pack2f(hB.z, hB.w);                      \
        ull wi = pack2f((WV).x, (WV).x), wf = pack2f((WV).y, (WV).y);              \
        ull wg = pack2f((WV).z, (WV).z), wo = pack2f((WV).w, (WV).w);              \
        acc[0][0] = fma2f(h0, wi, acc[0][0]); acc[0][1] = fma2f(h1, wi, acc[0][1]);\
        acc[0][2] = fma2f(h2, wi, acc[0][2]); acc[0][3] = fma2f(h3, wi, acc[0][3]);\
        acc[1][0] = fma2f(h0, wf, acc[1][0]); acc[1][1] = fma2f(h1, wf, acc[1][1]);\
        acc[1][2] = fma2f(h2, wf, acc[1][2]); acc[1][3] = fma2f(h3, wf, acc[1][3]);\
        acc[2][0] = fma2f(h0, wg, acc[2][0]); acc[2][1] = fma2f(h1, wg, acc[2][1]);\
        acc[2][2] = fma2f(h2, wg, acc[2][2]); acc[2][3] = fma2f(h3, wg, acc[2][3]);\
        acc[3][0] = fma2f(h0, wo, acc[3][0]); acc[3][1] = fma2f(h1, wo, acc[3][1]);\
        acc[3][2] = fma2f(h2, wo, acc[3][2]); acc[3][3] = fma2f(h3, wo, acc[3][3]);\
    }

__global__ void __launch_bounds__(256) lstm_enc(
    const float4* __restrict__ w4, const float* __restrict__ xg,
    float* __restrict__ h_all, float* __restrict__ z_last) {
    const int b0 = blockIdx.x * 8;
    const int j = threadIdx.x;

    __shared__ __align__(16) float2 shh[2][Hc][4];

    float c[8];
#pragma unroll
    for (int r = 0; r < 8; r++) c[r] = 0.f;
#pragma unroll
    for (int rp = 0; rp < 4; rp++) shh[0][j][rp] = make_float2(0.f, 0.f);
    __syncthreads();

    const float4* wj = w4 + j;
    int cur = 0;

#pragma unroll 1
    for (int t = 0; t < Tc; t++) {
        ull acc[4][4];
#pragma unroll
        for (int g = 0; g < 4; g++)
#pragma unroll
            for (int rp = 0; rp < 4; rp++) {
                float lo = xg[((size_t)(b0 + 2 * rp) * Tc + t) * Gc + g * Hc + j];
                float hi = xg[((size_t)(b0 + 2 * rp + 1) * Tc + t) * Gc + g * Hc + j];
                acc[g][rp] = pack2f(lo, hi);
            }

        const float2(*shc)[4] = shh[cur];
        float4 wA[8], wB[8];
#pragma unroll
        for (int u = 0; u < 8; u++) wA[u] = __ldg(wj + u * Hc);
#pragma unroll 1
        for (int k = 0; k < Hc; k += 16) {
#pragma unroll
            for (int u = 0; u < 8; u++) wB[u] = __ldg(wj + (k + 8 + u) * Hc);
#pragma unroll
            for (int u = 0; u < 8; u++) EPROC(k + u, wA[u]);
#pragma unroll
            for (int u = 0; u < 8; u++) wA[u] = __ldg(wj + (k + 16 + u) * Hc);
#pragma unroll
            for (int u = 0; u < 8; u++) EPROC(k + 8 + u, wB[u]);
        }

        int nxt = cur ^ 1;
#pragma unroll
        for (int rp = 0; rp < 4; rp++) {
            float2 iv = unpack2f(acc[0][rp]);
            float2 fv = unpack2f(acc[1][rp]);
            float2 gv = unpack2f(acc[2][rp]);
            float2 ov = unpack2f(acc[3][rp]);
            float2 hv;
            {
                float ii = sigf(iv.x), ff = sigf(fv.x);
                float gg = tanh_(gv.x), oo = sigf(ov.x);
                c[2 * rp] = ff * c[2 * rp] + ii * gg;
                hv.x = oo * tanh_(c[2 * rp]);
            }
            {
                float ii = sigf(iv.y), ff = sigf(fv.y);
                float gg = tanh_(gv.y), oo = sigf(ov.y);
                c[2 * rp + 1] = ff * c[2 * rp + 1] + ii * gg;
                hv.y = oo * tanh_(c[2 * rp + 1]);
            }
            shh[nxt][j][rp] = hv;
            if (h_all) {
                h_all[((size_t)(b0 + 2 * rp) * Tc + t) * Hc + j]     = hv.x;
                h_all[((size_t)(b0 + 2 * rp + 1) * Tc + t) * Hc + j] = hv.y;
            }
            if (z_last && t == Tc - 1) {
                z_last[(size_t)(b0 + 2 * rp) * Hc + j]     = hv.x;
                z_last[(size_t)(b0 + 2 * rp + 1) * Hc + j] = hv.y;
            }
        }
        __syncthreads();
        cur = nxt;
    }
}

// ---------------- decoder LSTM (H=64), 8 rows/CTA ----------------
#define DPROC(KK, WV)                                                \
    {                                                                \
        float2 h = shc[(KK)][rg];                                    \
        ull h2 = pack2f(h.x, h.y);                                   \
        acc[0] = fma2f(h2, pack2f((WV).x, (WV).x), acc[0]);          \
        acc[1] = fma2f(h2, pack2f((WV).y, (WV).y), acc[1]);          \
        acc[2] = fma2f(h2, pack2f((WV).z, (WV).z), acc[2]);          \
        acc[3] = fma2f(h2, pack2f((WV).w, (WV).w), acc[3]);          \
    }

__global__ void __launch_bounds__(256) lstm_dec(
    const float4* __restrict__ w4, const float* __restrict__ xg,
    float* __restrict__ h_out, int per_t) {
    const int b0 = blockIdx.x * 8;
    const int j = threadIdx.x & 63;
    const int rg = threadIdx.x >> 6;  // rows rg, rg+4

    __shared__ __align__(16) float2 shh[2][Mc][4];
    shh[0][j][rg] = make_float2(0.f, 0.f);
    __syncthreads();

    float c0 = 0.f, c1 = 0.f;
    ull base[4];
    if (!per_t) {
#pragma unroll
        for (int g = 0; g < 4; g++)
            base[g] = pack2f(xg[(size_t)(b0 + rg) * GMc + g * Mc + j],
                             xg[(size_t)(b0 + rg + 4) * GMc + g * Mc + j]);
    }

    const float4* wj = w4 + j;
    int cur = 0;

#pragma unroll 1
    for (int t = 0; t < Tc; t++) {
        ull acc[4];
        if (per_t) {
#pragma unroll
            for (int g = 0; g < 4; g++)
                acc[g] = pack2f(xg[((size_t)(b0 + rg) * Tc + t) * GMc + g * Mc + j],
                                xg[((size_t)(b0 + rg + 4) * Tc + t) * GMc + g * Mc + j]);
        } else {
#pragma unroll
            for (int g = 0; g < 4; g++) acc[g] = base[g];
        }

        const float2(*shc)[4] = shh[cur];
        float4 wA[8], wB[8];
#pragma unroll
        for (int u = 0; u < 8; u++) wA[u] = __ldg(wj + u * Mc);
#pragma unroll 1
        for (int k = 0; k < Mc; k += 16) {
#pragma unroll
            for (int u = 0; u < 8; u++) wB[u] = __ldg(wj + (k + 8 + u) * Mc);
#pragma unroll
            for (int u = 0; u < 8; u++) DPROC(k + u, wA[u]);
#pragma unroll
            for (int u = 0; u < 8; u++) wA[u] = __ldg(wj + (k + 16 + u) * Mc);
#pragma unroll
            for (int u = 0; u < 8; u++) DPROC(k + 8 + u, wB[u]);
        }

        float2 iv = unpack2f(acc[0]);
        float2 fv = unpack2f(acc[1]);
        float2 gv = unpack2f(acc[2]);
        float2 ov = unpack2f(acc[3]);
        c0 = sigf(fv.x) * c0 + sigf(iv.x) * tanh_(gv.x);
        float h0 = sigf(ov.x) * tanh_(c0);
        c1 = sigf(fv.y) * c1 + sigf(iv.y) * tanh_(gv.y);
        float h1 = sigf(ov.y) * tanh_(c1);

        int nxt = cur ^ 1;
        shh[nxt][j][rg] = make_float2(h0, h1);
        h_out[((size_t)(b0 + rg) * Tc + t) * Mc + j]     = h0;
        h_out[((size_t)(b0 + rg + 4) * Tc + t) * Mc + j] = h1;
        __syncthreads();
        cur = nxt;
    }
}

// ---------------- launch ----------------
extern "C" void kernel_launch(void* const* d_in, const int* in_sizes, int n_in,
                              void* d_out, int out_size) {
    const float* x    = (const float*)d_in[0];
    const float* in_W = (const float*)d_in[1];
    const float* in_b = (const float*)d_in[2];
    const float* eW0i = (const float*)d_in[3];
    const float* eW0h = (const float*)d_in[4];
    const float* eb0i = (const float*)d_in[5];
    const float* eb0h = (const float*)d_in[6];
    const float* eW1i = (const float*)d_in[7];
    const float* eW1h = (const float*)d_in[8];
    const float* eb1i = (const float*)d_in[9];
    const float* eb1h = (const float*)d_in[10];
    const float* dW0i = (const float*)d_in[11];
    const float* dW0h = (const float*)d_in[12];
    const float* db0i = (const float*)d_in[13];
    const float* db0h = (const float*)d_in[14];
    const float* dW1i = (const float*)d_in[15];
    const float* dW1h = (const float*)d_in[16];
    const float* db1i = (const float*)d_in[17];
    const float* db1h = (const float*)d_in[18];
    const float* outW = (const float*)d_in[19];
    const float* outb = (const float*)d_in[20];
    float* out = (float*)d_out;

    float *xg, *mid, *bufA, *bufB, *z, *xgd0, *w4e0, *w4e1, *w4d0, *w4d1;
    cudaGetSymbolAddress((void**)&xg,   g_xg);
    cudaGetSymbolAddress((void**)&mid,  g_mid);
    cudaGetSymbolAddress((void**)&bufA, g_bufA);
    cudaGetSymbolAddress((void**)&bufB, g_bufB);
    cudaGetSymbolAddress((void**)&z,    g_z);
    cudaGetSymbolAddress((void**)&xgd0, g_xgd0);
    cudaGetSymbolAddress((void**)&w4e0, g_w4e0);
    cudaGetSymbolAddress((void**)&w4e1, g_w4e1);
    cudaGetSymbolAddress((void**)&w4d0, g_w4d0);
    cudaGetSymbolAddress((void**)&w4d1, g_w4d1);

    const int MT = Bc * Tc;  // 102400

    // interleaved weight prep
    prep_w4<<<dim3(8, 8, 4), dim3(32, 8)>>>(eW0h, w4e0, Hc);
    prep_w4<<<dim3(8, 8, 4), dim3(32, 8)>>>(eW1h, w4e1, Hc);
    prep_w4<<<dim3(2, 2, 4), dim3(32, 8)>>>(dW0h, w4d0, Mc);
    prep_w4<<<dim3(2, 2, 4), dim3(32, 8)>>>(dW1h, w4d1, Mc);

    // 1) h0 = relu(x @ in_W^T + in_b)                 : (102400,64)
    gemm64<true, false><<<dim3(MT / 128, 1), 256>>>(x, in_W, in_b, nullptr, bufA, MT, Mc, Dc);
    // 2) xg0 = h0 @ eW0i^T + eb0i + eb0h              : (102400,1024)
    gemm128<false, true><<<dim3(MT / 128, Gc / 128), 256>>>(bufA, eW0i, eb0i, eb0h, xg, MT, Gc, Mc);
    // 3) enc0 recurrence -> h_enc0                     : (102400,256)
    lstm_enc<<<Bc / 8, 256>>>((const float4*)w4e0, xg, mid, nullptr);
    // 4) xg1 = h_enc0 @ eW1i^T + eb1i + eb1h          : (102400,1024)
    gemm128<false, true><<<dim3(MT / 128, Gc / 128), 256>>>(mid, eW1i, eb1i, eb1h, xg, MT, Gc, Hc);
    // 5) enc1 recurrence -> z (last h only)            : (1024,256)
    lstm_enc<<<Bc / 8, 256>>>((const float4*)w4e1, xg, nullptr, z);
    // 6) xg_dec0 = z @ dW0i^T + db0i + db0h (t-const)  : (1024,256)
    gemm128<false, true><<<dim3(Bc / 128, GMc / 128), 256>>>(z, dW0i, db0i, db0h, xgd0, Bc, GMc, Hc);
    // 7) dec0 recurrence -> d0                         : (102400,64)
    lstm_dec<<<Bc / 8, 256>>>((const float4*)w4d0, xgd0, bufA, 0);
    // 8) xg_dec1 = d0 @ dW1i^T + db1i + db1h          : (102400,256)
    gemm128<false, true><<<dim3(MT / 128, GMc / 128), 256>>>(bufA, dW1i, db1i, db1h, mid, MT, GMc, Mc);
    // 9) dec1 recurrence -> d1                         : (102400,64)
    lstm_dec<<<Bc / 8, 256>>>((const float4*)w4d1, mid, bufB, 1);
    // 10) out = d1 @ out_W^T + out_b                   : (102400,256)
    gemm128<false, false><<<dim3(MT / 128, Dc / 128), 256>>>(bufB, outW, outb, nullptr, out, MT, Dc, Mc);
}

// round 3
// speedup vs baseline: 2.8134x; 1.1689x over previous
#include <cuda_runtime.h>

// ---------------- problem dims ----------------
#define Bc   1024
#define Tc   100
#define Dc   256
#define Hc   256   // encoder hidden
#define Gc   1024  // 4*Hc
#define Mc   64    // decoder hidden / bottleneck
#define GMc  256   // 4*Mc
#define KC   48    // enc k-slices cached in smem (192 KB)

typedef unsigned long long ull;

// ---------------- device scratch (no allocs allowed) ----------------
__device__ float g_xg  [(size_t)Bc * Tc * Gc];
__device__ float g_mid [(size_t)Bc * Tc * Hc];
__device__ float g_bufA[(size_t)Bc * Tc * Mc];
__device__ float g_bufB[(size_t)Bc * Tc * Mc];
__device__ float g_z   [Bc * Hc];
__device__ float g_xgd0[Bc * GMc];
// interleaved float4 weights [k][j] = {w_i, w_f, w_g, w_o}; +2048 float4 pad for prefetch overread
__device__ float g_w4e0[(Hc * Hc + 2048) * 4];
__device__ float g_w4e1[(Hc * Hc + 2048) * 4];
__device__ float g_w4d0[(Mc * Mc + 1024) * 4];
__device__ float g_w4d1[(Mc * Mc + 1024) * 4];

// ---------------- f32x2 helpers ----------------
__device__ __forceinline__ ull pack2f(float x, float y) {
    ull r; asm("mov.b64 %0, {%1, %2};" : "=l"(r) : "f"(x), "f"(y)); return r;
}
__device__ __forceinline__ float2 unpack2f(ull v) {
    float2 r; asm("mov.b64 {%0, %1}, %2;" : "=f"(r.x), "=f"(r.y) : "l"(v)); return r;
}
__device__ __forceinline__ ull fma2f(ull a, ull b, ull c) {
    ull d; asm("fma.rn.f32x2 %0, %1, %2, %3;" : "=l"(d) : "l"(a), "l"(b), "l"(c)); return d;
}

__device__ __forceinline__ float sigf(float x) {
    return __fdividef(1.0f, 1.0f + __expf(-x));
}
__device__ __forceinline__ float tanh_(float x) {  // NaN-safe fast tanh
    return 1.0f - __fdividef(2.0f, __expf(2.0f * x) + 1.0f);
}

// ---------------- weight prep: src (4H x H) -> dst float4[k][j] ----------------
__global__ void prep_w4(const float* __restrict__ src, float* __restrict__ dst, int H) {
    __shared__ float tile[32][33];
    int g = blockIdx.z;
    int k0 = blockIdx.x * 32, j0 = blockIdx.y * 32;
    int x = threadIdx.x, y = threadIdx.y;
#pragma unroll
    for (int i = 0; i < 32; i += 8)
        tile[y + i][x] = src[(size_t)(g * H + j0 + y + i) * H + k0 + x];
    __syncthreads();
#pragma unroll
    for (int i = 0; i < 32; i += 8)
        dst[((size_t)(k0 + y + i) * H + (j0 + x)) * 4 + g] = tile[x][y + i];
}

// ---------------- GEMM (BM=128, BN=64) for N=64 ----------------
template <bool RELU, bool HASB2>
__global__ void __launch_bounds__(256) gemm64(
    const float* __restrict__ A, const float* __restrict__ W,
    const float* __restrict__ b1, const float* __restrict__ b2,
    float* __restrict__ C, int Mdim, int Ndim, int Kdim) {
    constexpr int BK = 16;
    __shared__ float As[BK][128];
    __shared__ float Ws[BK][64];

    const int tid = threadIdx.x;
    const int tx = tid & 15;
    const int ty = tid >> 4;
    const size_t bm = (size_t)blockIdx.x * 128;
    const size_t bn = (size_t)blockIdx.y * 64;
    const int lr = tid >> 2;
    const int lk = (tid & 3) << 2;

    ull acc[4][4];
#pragma unroll
    for (int i = 0; i < 4; i++)
#pragma unroll
        for (int j = 0; j < 4; j++) acc[i][j] = 0ull;

    const float* Ap0 = A + (bm + lr) * (size_t)Kdim + lk;
    const float* Ap1 = A + (bm + lr + 64) * (size_t)Kdim + lk;
    const float* Wp  = W + (bn + lr) * (size_t)Kdim + lk;

    for (int k0 = 0; k0 < Kdim; k0 += BK) {
        float4 av0 = *(const float4*)(Ap0 + k0);
        float4 av1 = *(const float4*)(Ap1 + k0);
        float4 wv  = *(const float4*)(Wp + k0);
        __syncthreads();
        As[lk + 0][lr] = av0.x; As[lk + 1][lr] = av0.y;
        As[lk + 2][lr] = av0.z; As[lk + 3][lr] = av0.w;
        As[lk + 0][lr + 64] = av1.x; As[lk + 1][lr + 64] = av1.y;
        As[lk + 2][lr + 64] = av1.z; As[lk + 3][lr + 64] = av1.w;
        Ws[lk + 0][lr] = wv.x; Ws[lk + 1][lr] = wv.y;
        Ws[lk + 2][lr] = wv.z; Ws[lk + 3][lr] = wv.w;
        __syncthreads();
#pragma unroll
        for (int kk = 0; kk < BK; kk++) {
            float4 a0 = *(const float4*)&As[kk][ty * 8];
            float4 a1 = *(const float4*)&As[kk][ty * 8 + 4];
            float4 w4 = *(const float4*)&Ws[kk][tx * 4];
            ull a2[4] = {pack2f(a0.x, a0.y), pack2f(a0.z, a0.w),
                         pack2f(a1.x, a1.y), pack2f(a1.z, a1.w)};
            ull w2[4] = {pack2f(w4.x, w4.x), pack2f(w4.y, w4.y),
                         pack2f(w4.z, w4.z), pack2f(w4.w, w4.w)};
#pragma unroll
            for (int i = 0; i < 4; i++)
#pragma unroll
                for (int j = 0; j < 4; j++)
                    acc[i][j] = fma2f(a2[i], w2[j], acc[i][j]);
        }
    }

    float bias[4];
#pragma unroll
    for (int j = 0; j < 4; j++) {
        bias[j] = b1[bn + tx * 4 + j];
        if (HASB2) bias[j] += b2[bn + tx * 4 + j];
    }
#pragma unroll
    for (int i = 0; i < 4; i++) {
        float2 v0 = unpack2f(acc[i][0]);
        float2 v1 = unpack2f(acc[i][1]);
        float2 v2 = unpack2f(acc[i][2]);
        float2 v3 = unpack2f(acc[i][3]);
        float4 o0 = make_float4(v0.x + bias[0], v1.x + bias[1], v2.x + bias[2], v3.x + bias[3]);
        float4 o1 = make_float4(v0.y + bias[0], v1.y + bias[1], v2.y + bias[2], v3.y + bias[3]);
        if (RELU) {
            o0.x = fmaxf(o0.x, 0.f); o0.y = fmaxf(o0.y, 0.f);
            o0.z = fmaxf(o0.z, 0.f); o0.w = fmaxf(o0.w, 0.f);
            o1.x = fmaxf(o1.x, 0.f); o1.y = fmaxf(o1.y, 0.f);
            o1.z = fmaxf(o1.z, 0.f); o1.w = fmaxf(o1.w, 0.f);
        }
        size_t r0 = bm + ty * 8 + 2 * i;
        *(float4*)&C[r0 * Ndim + bn + tx * 4]       = o0;
        *(float4*)&C[(r0 + 1) * Ndim + bn + tx * 4] = o1;
    }
}

// ---------------- GEMM (BM=128, BN=128), double-buffered, 8x8 f32x2 ----------------
template <bool RELU, bool HASB2>
__global__ void __launch_bounds__(256) gemm128(
    const float* __restrict__ A, const float* __restrict__ W,
    const float* __restrict__ b1, const float* __restrict__ b2,
    float* __restrict__ C, int Mdim, int Ndim, int Kdim) {
    constexpr int BK = 16;
    __shared__ float As[2][BK][128];
    __shared__ float Ws[2][BK][128];

    const int tid = threadIdx.x;
    const int tx = tid & 15;
    const int ty = tid >> 4;
    const size_t bm = (size_t)blockIdx.x * 128;
    const size_t bn = (size_t)blockIdx.y * 128;
    const int lr = tid >> 2;
    const int lk = (tid & 3) << 2;

    ull acc[4][8];
#pragma unroll
    for (int i = 0; i < 4; i++)
#pragma unroll
        for (int j = 0; j < 8; j++) acc[i][j] = 0ull;

    const float* Ap0 = A + (bm + lr) * (size_t)Kdim + lk;
    const float* Ap1 = A + (bm + lr + 64) * (size_t)Kdim + lk;
    const float* Wp0 = W + (bn + lr) * (size_t)Kdim + lk;
    const float* Wp1 = W + (bn + lr + 64) * (size_t)Kdim + lk;

    float4 a0, a1, w0, w1;

#define G128_LOAD(K0)                         \
    a0 = *(const float4*)(Ap0 + (K0));        \
    a1 = *(const float4*)(Ap1 + (K0));        \
    w0 = *(const float4*)(Wp0 + (K0));        \
    w1 = *(const float4*)(Wp1 + (K0));

#define G128_STORE(BUF)                                                 \
    As[BUF][lk + 0][lr] = a0.x; As[BUF][lk + 1][lr] = a0.y;             \
    As[BUF][lk + 2][lr] = a0.z; As[BUF][lk + 3][lr] = a0.w;             \
    As[BUF][lk + 0][lr + 64] = a1.x; As[BUF][lk + 1][lr + 64] = a1.y;   \
    As[BUF][lk + 2][lr + 64] = a1.z; As[BUF][lk + 3][lr + 64] = a1.w;   \
    Ws[BUF][lk + 0][lr] = w0.x; Ws[BUF][lk + 1][lr] = w0.y;             \
    Ws[BUF][lk + 2][lr] = w0.z; Ws[BUF][lk + 3][lr] = w0.w;             \
    Ws[BUF][lk + 0][lr + 64] = w1.x; Ws[BUF][lk + 1][lr + 64] = w1.y;   \
    Ws[BUF][lk + 2][lr + 64] = w1.z; Ws[BUF][lk + 3][lr + 64] = w1.w;

#define G128_COMPUTE(BUF)                                                    \
    _Pragma("unroll")                                                        \
    for (int kk = 0; kk < BK; kk++) {                                        \
        float4 av0 = *(const float4*)&As[BUF][kk][ty * 8];                   \
        float4 av1 = *(const float4*)&As[BUF][kk][ty * 8 + 4];               \
        float4 wv0 = *(const float4*)&Ws[BUF][kk][tx * 8];                   \
        float4 wv1 = *(const float4*)&Ws[BUF][kk][tx * 8 + 4];               \
        ull ar[4] = {pack2f(av0.x, av0.y), pack2f(av0.z, av0.w),             \
                     pack2f(av1.x, av1.y), pack2f(av1.z, av1.w)};            \
        ull wc[8] = {pack2f(wv0.x, wv0.x), pack2f(wv0.y, wv0.y),             \
                     pack2f(wv0.z, wv0.z), pack2f(wv0.w, wv0.w),             \
                     pack2f(wv1.x, wv1.x), pack2f(wv1.y, wv1.y),             \
                     pack2f(wv1.z, wv1.z), pack2f(wv1.w, wv1.w)};            \
        _Pragma("unroll")                                                    \
        for (int i = 0; i < 4; i++)                                          \
            _Pragma("unroll")                                                \
            for (int j = 0; j < 8; j++)                                      \
                acc[i][j] = fma2f(ar[i], wc[j], acc[i][j]);                  \
    }

    G128_LOAD(0);
    G128_STORE(0);
    __syncthreads();
    const int nb = Kdim / BK;
#pragma unroll 1
    for (int it = 1; it < nb; it++) {
        G128_LOAD(it * BK);
        G128_COMPUTE((it - 1) & 1);
        G128_STORE(it & 1);
        __syncthreads();
    }
    G128_COMPUTE((nb - 1) & 1);

    float bias[8];
#pragma unroll
    for (int j = 0; j < 8; j++) {
        bias[j] = b1[bn + tx * 8 + j];
        if (HASB2) bias[j] += b2[bn + tx * 8 + j];
    }
#pragma unroll
    for (int i = 0; i < 4; i++) {
        float lo[8], hi[8];
#pragma unroll
        for (int j = 0; j < 8; j++) {
            float2 v = unpack2f(acc[i][j]);
            lo[j] = v.x + bias[j];
            hi[j] = v.y + bias[j];
            if (RELU) { lo[j] = fmaxf(lo[j], 0.f); hi[j] = fmaxf(hi[j], 0.f); }
        }
        size_t r0 = bm + ty * 8 + 2 * i;
        float* p0 = &C[r0 * Ndim + bn + tx * 8];
        float* p1 = &C[(r0 + 1) * Ndim + bn + tx * 8];
        *(float4*)p0       = make_float4(lo[0], lo[1], lo[2], lo[3]);
        *(float4*)(p0 + 4) = make_float4(lo[4], lo[5], lo[6], lo[7]);
        *(float4*)p1       = make_float4(hi[0], hi[1], hi[2], hi[3]);
        *(float4*)(p1 + 4) = make_float4(hi[4], hi[5], hi[6], hi[7]);
    }
}

// ---------------- encoder LSTM (H=256), smem weight cache + packed h reads ----------------
#define EPROC(KK, WV)                                                              \
    {                                                                              \
        const ulonglong2* hp = (const ulonglong2*)&shc[(KK)][0];                   \
        ulonglong2 hA = hp[0], hB = hp[1];                                         \
        ull wi = pack2f((WV).x, (WV).x), wf = pack2f((WV).y, (WV).y);              \
        ull wg = pack2f((WV).z, (WV).z), wo = pack2f((WV).w, (WV).w);              \
        acc[0][0] = fma2f(hA.x, wi, acc[0][0]); acc[0][1] = fma2f(hA.y, wi, acc[0][1]); \
        acc[0][2] = fma2f(hB.x, wi, acc[0][2]); acc[0][3] = fma2f(hB.y, wi, acc[0][3]); \
        acc[1][0] = fma2f(hA.x, wf, acc[1][0]); acc[1][1] = fma2f(hA.y, wf, acc[1][1]); \
        acc[1][2] = fma2f(hB.x, wf, acc[1][2]); acc[1][3] = fma2f(hB.y, wf, acc[1][3]); \
        acc[2][0] = fma2f(hA.x, wg, acc[2][0]); acc[2][1] = fma2f(hA.y, wg, acc[2][1]); \
        acc[2][2] = fma2f(hB.x, wg, acc[2][2]); acc[2][3] = fma2f(hB.y, wg, acc[2][3]); \
        acc[3][0] = fma2f(hA.x, wo, acc[3][0]); acc[3][1] = fma2f(hA.y, wo, acc[3][1]); \
        acc[3][2] = fma2f(hB.x, wo, acc[3][2]); acc[3][3] = fma2f(hB.y, wo, acc[3][3]); \
    }

__global__ void __launch_bounds__(256, 1) lstm_enc(
    const float4* __restrict__ w4, const float* __restrict__ xg,
    float* __restrict__ h_all, float* __restrict__ z_last) {
    extern __shared__ __align__(16) char smraw[];
    float2 (*shh)[Hc][4] = (float2(*)[Hc][4])smraw;            // 2 x 8 KB
    float4* wc = (float4*)(smraw + 2 * Hc * 4 * sizeof(float2)); // KC*256 float4 = 192 KB

    const int b0 = blockIdx.x * 8;
    const int j = threadIdx.x;

    // preload first KC k-slices of weights into smem
    for (int idx = threadIdx.x; idx < KC * Hc; idx += 256)
        wc[idx] = w4[idx];

    float c[8];
#pragma unroll
    for (int r = 0; r < 8; r++) c[r] = 0.f;
#pragma unroll
    for (int rp = 0; rp < 4; rp++) shh[0][j][rp] = make_float2(0.f, 0.f);
    __syncthreads();

    const float4* wj = w4 + j;
    int cur = 0;

#pragma unroll 1
    for (int t = 0; t < Tc; t++) {
        ull acc[4][4];
#pragma unroll
        for (int g = 0; g < 4; g++)
#pragma unroll
            for (int rp = 0; rp < 4; rp++) {
                float lo = xg[((size_t)(b0 + 2 * rp) * Tc + t) * Gc + g * Hc + j];
                float hi = xg[((size_t)(b0 + 2 * rp + 1) * Tc + t) * Gc + g * Hc + j];
                acc[g][rp] = pack2f(lo, hi);
            }

        const float2(*shc)[4] = shh[cur];

        // --- k in [0, KC): weights from smem ---
#pragma unroll 1
        for (int k = 0; k < KC; k += 8) {
#pragma unroll
            for (int u = 0; u < 8; u++) {
                float4 wv = wc[(k + u) * Hc + j];
                EPROC(k + u, wv);
            }
        }

        // --- k in [KC, 256): weights from gmem, software-pipelined depth 8 ---
        float4 wA[8], wB[8];
#pragma unroll
        for (int u = 0; u < 8; u++) wA[u] = __ldg(wj + (KC + u) * Hc);
#pragma unroll 1
        for (int k = KC; k < Hc; k += 16) {
#pragma unroll
            for (int u = 0; u < 8; u++) wB[u] = __ldg(wj + (k + 8 + u) * Hc);
#pragma unroll
            for (int u = 0; u < 8; u++) EPROC(k + u, wA[u]);
#pragma unroll
            for (int u = 0; u < 8; u++) wA[u] = __ldg(wj + (k + 16 + u) * Hc);
#pragma unroll
            for (int u = 0; u < 8; u++) EPROC(k + 8 + u, wB[u]);
        }

        int nxt = cur ^ 1;
#pragma unroll
        for (int rp = 0; rp < 4; rp++) {
            float2 iv = unpack2f(acc[0][rp]);
            float2 fv = unpack2f(acc[1][rp]);
            float2 gv = unpack2f(acc[2][rp]);
            float2 ov = unpack2f(acc[3][rp]);
            float2 hv;
            {
                float ii = sigf(iv.x), ff = sigf(fv.x);
                float gg = tanh_(gv.x), oo = sigf(ov.x);
                c[2 * rp] = ff * c[2 * rp] + ii * gg;
                hv.x = oo * tanh_(c[2 * rp]);
            }
            {
                float ii = sigf(iv.y), ff = sigf(fv.y);
                float gg = tanh_(gv.y), oo = sigf(ov.y);
                c[2 * rp + 1] = ff * c[2 * rp + 1] + ii * gg;
                hv.y = oo * tanh_(c[2 * rp + 1]);
            }
            shh[nxt][j][rp] = hv;
            if (h_all) {
                h_all[((size_t)(b0 + 2 * rp) * Tc + t) * Hc + j]     = hv.x;
                h_all[((size_t)(b0 + 2 * rp + 1) * Tc + t) * Hc + j] = hv.y;
            }
            if (z_last && t == Tc - 1) {
                z_last[(size_t)(b0 + 2 * rp) * Hc + j]     = hv.x;
                z_last[(size_t)(b0 + 2 * rp + 1) * Hc + j] = hv.y;
            }
        }
        __syncthreads();
        cur = nxt;
    }
}

// ---------------- decoder LSTM (H=64), all weights in smem ----------------
__global__ void __launch_bounds__(256) lstm_dec(
    const float4* __restrict__ w4, const float* __restrict__ xg,
    float* __restrict__ h_out, int per_t) {
    extern __shared__ __align__(16) char smraw[];
    float2 (*shh)[Mc][4] = (float2(*)[Mc][4])smraw;             // 2 x 2 KB
    float4* wc = (float4*)(smraw + 2 * Mc * 4 * sizeof(float2)); // 64*64 float4 = 64 KB

    const int b0 = blockIdx.x * 8;
    const int j = threadIdx.x & 63;
    const int rg = threadIdx.x >> 6;

    for (int idx = threadIdx.x; idx < Mc * Mc; idx += 256)
        wc[idx] = w4[idx];
    shh[0][j][rg] = make_float2(0.f, 0.f);
    __syncthreads();

    float c0 = 0.f, c1 = 0.f;
    ull base[4];
    if (!per_t) {
#pragma unroll
        for (int g = 0; g < 4; g++)
            base[g] = pack2f(xg[(size_t)(b0 + rg) * GMc + g * Mc + j],
                             xg[(size_t)(b0 + rg + 4) * GMc + g * Mc + j]);
    }

    int cur = 0;
#pragma unroll 1
    for (int t = 0; t < Tc; t++) {
        ull acc[4];
        if (per_t) {
#pragma unroll
            for (int g = 0; g < 4; g++)
                acc[g] = pack2f(xg[((size_t)(b0 + rg) * Tc + t) * GMc + g * Mc + j],
                                xg[((size_t)(b0 + rg + 4) * Tc + t) * GMc + g * Mc + j]);
        } else {
#pragma unroll
            for (int g = 0; g < 4; g++) acc[g] = base[g];
        }

        const float2(*shc)[4] = shh[cur];
#pragma unroll 1
        for (int k = 0; k < Mc; k += 16) {
#pragma unroll
            for (int u = 0; u < 16; u++) {
                float4 wv = wc[(k + u) * Mc + j];
                ull h2 = *(const ull*)&shc[k + u][rg];
                acc[0] = fma2f(h2, pack2f(wv.x, wv.x), acc[0]);
                acc[1] = fma2f(h2, pack2f(wv.y, wv.y), acc[1]);
                acc[2] = fma2f(h2, pack2f(wv.z, wv.z), acc[2]);
                acc[3] = fma2f(h2, pack2f(wv.w, wv.w), acc[3]);
            }
        }

        float2 iv = unpack2f(acc[0]);
        float2 fv = unpack2f(acc[1]);
        float2 gv = unpack2f(acc[2]);
        float2 ov = unpack2f(acc[3]);
        c0 = sigf(fv.x) * c0 + sigf(iv.x) * tanh_(gv.x);
        float h0 = sigf(ov.x) * tanh_(c0);
        c1 = sigf(fv.y) * c1 + sigf(iv.y) * tanh_(gv.y);
        float h1 = sigf(ov.y) * tanh_(c1);

        int nxt = cur ^ 1;
        shh[nxt][j][rg] = make_float2(h0, h1);
        h_out[((size_t)(b0 + rg) * Tc + t) * Mc + j]     = h0;
        h_out[((size_t)(b0 + rg + 4) * Tc + t) * Mc + j] = h1;
        __syncthreads();
        cur = nxt;
    }
}

// ---------------- launch ----------------
extern "C" void kernel_launch(void* const* d_in, const int* in_sizes, int n_in,
                              void* d_out, int out_size) {
    const float* x    = (const float*)d_in[0];
    const float* in_W = (const float*)d_in[1];
    const float* in_b = (const float*)d_in[2];
    const float* eW0i = (const float*)d_in[3];
    const float* eW0h = (const float*)d_in[4];
    const float* eb0i = (const float*)d_in[5];
    const float* eb0h = (const float*)d_in[6];
    const float* eW1i = (const float*)d_in[7];
    const float* eW1h = (const float*)d_in[8];
    const float* eb1i = (const float*)d_in[9];
    const float* eb1h = (const float*)d_in[10];
    const float* dW0i = (const float*)d_in[11];
    const float* dW0h = (const float*)d_in[12];
    const float* db0i = (const float*)d_in[13];
    const float* db0h = (const float*)d_in[14];
    const float* dW1i = (const float*)d_in[15];
    const float* dW1h = (const float*)d_in[16];
    const float* db1i = (const float*)d_in[17];
    const float* db1h = (const float*)d_in[18];
    const float* outW = (const float*)d_in[19];
    const float* outb = (const float*)d_in[20];
    float* out = (float*)d_out;

    float *xg, *mid, *bufA, *bufB, *z, *xgd0, *w4e0, *w4e1, *w4d0, *w4d1;
    cudaGetSymbolAddress((void**)&xg,   g_xg);
    cudaGetSymbolAddress((void**)&mid,  g_mid);
    cudaGetSymbolAddress((void**)&bufA, g_bufA);
    cudaGetSymbolAddress((void**)&bufB, g_bufB);
    cudaGetSymbolAddress((void**)&z,    g_z);
    cudaGetSymbolAddress((void**)&xgd0, g_xgd0);
    cudaGetSymbolAddress((void**)&w4e0, g_w4e0);
    cudaGetSymbolAddress((void**)&w4e1, g_w4e1);
    cudaGetSymbolAddress((void**)&w4d0, g_w4d0);
    cudaGetSymbolAddress((void**)&w4d1, g_w4d1);

    const int MT = Bc * Tc;

    const int ENC_SMEM = 2 * Hc * 4 * sizeof(float2) + KC * Hc * sizeof(float4); // 16 KB + 192 KB
    const int DEC_SMEM = 2 * Mc * 4 * sizeof(float2) + Mc * Mc * sizeof(float4); // 4 KB + 64 KB
    static int configured = 0;
    if (!configured) {
        cudaFuncSetAttribute(lstm_enc, cudaFuncAttributeMaxDynamicSharedMemorySize, ENC_SMEM);
        cudaFuncSetAttribute(lstm_dec, cudaFuncAttributeMaxDynamicSharedMemorySize, DEC_SMEM);
        configured = 1;
    }

    // weight preps
    prep_w4<<<dim3(8, 8, 4), dim3(32, 8)>>>(eW0h, w4e0, Hc);
    prep_w4<<<dim3(8, 8, 4), dim3(32, 8)>>>(eW1h, w4e1, Hc);
    prep_w4<<<dim3(2, 2, 4), dim3(32, 8)>>>(dW0h, w4d0, Mc);
    prep_w4<<<dim3(2, 2, 4), dim3(32, 8)>>>(dW1h, w4d1, Mc);

    // 1) h0 = relu(x @ in_W^T + in_b)                 : (102400,64)
    gemm64<true, false><<<dim3(MT / 128, 1), 256>>>(x, in_W, in_b, nullptr, bufA, MT, Mc, Dc);
    // 2) xg0 = h0 @ eW0i^T + eb0i + eb0h              : (102400,1024)
    gemm128<false, true><<<dim3(MT / 128, Gc / 128), 256>>>(bufA, eW0i, eb0i, eb0h, xg, MT, Gc, Mc);
    // 3) enc0 recurrence -> h_enc0                     : (102400,256)
    lstm_enc<<<Bc / 8, 256, ENC_SMEM>>>((const float4*)w4e0, xg, mid, nullptr);
    // 4) xg1 = h_enc0 @ eW1i^T + eb1i + eb1h          : (102400,1024)
    gemm128<false, true><<<dim3(MT / 128, Gc / 128), 256>>>(mid, eW1i, eb1i, eb1h, xg, MT, Gc, Hc);
    // 5) enc1 recurrence -> z                          : (1024,256)
    lstm_enc<<<Bc / 8, 256, ENC_SMEM>>>((const float4*)w4e1, xg, nullptr, z);
    // 6) xg_dec0 = z @ dW0i^T + db0i + db0h            : (1024,256)
    gemm128<false, true><<<dim3(Bc / 128, GMc / 128), 256>>>(z, dW0i, db0i, db0h, xgd0, Bc, GMc, Hc);
    // 7) dec0 recurrence -> d0                         : (102400,64)
    lstm_dec<<<Bc / 8, 256, DEC_SMEM>>>((const float4*)w4d0, xgd0, bufA, 0);
    // 8) xg_dec1 = d0 @ dW1i^T + db1i + db1h           : (102400,256)
    gemm128<false, true><<<dim3(MT / 128, GMc / 128), 256>>>(bufA, dW1i, db1i, db1h, mid, MT, GMc, Mc);
    // 9) dec1 recurrence -> d1                         : (102400,64)
    lstm_dec<<<Bc / 8, 256, DEC_SMEM>>>((const float4*)w4d1, mid, bufB, 1);
    // 10) out = d1 @ out_W^T + out_b                   : (102400,256)
    gemm128<false, false><<<dim3(MT / 128, Dc / 128), 256>>>(bufB, outW, outb, nullptr, out, MT, Dc, Mc);
}

// round 4
// speedup vs baseline: 3.4143x; 1.2136x over previous
#include <cuda_runtime.h>

// ---------------- problem dims ----------------
#define Bc   1024
#define Tc   100
#define Dc   256
#define Hc   256   // encoder hidden
#define Gc   1024  // 4*Hc
#define Mc   64    // decoder hidden / bottleneck
#define GMc  256   // 4*Mc
#define KC   48    // enc k-slices cached in smem (192 KB)

typedef unsigned long long ull;
typedef unsigned int u32;

// ---------------- device scratch (no allocs allowed) ----------------
__device__ float g_xg  [(size_t)Bc * Tc * Gc];
__device__ float g_mid [(size_t)Bc * Tc * Hc];
__device__ float g_bufA[(size_t)Bc * Tc * Mc];
__device__ float g_bufB[(size_t)Bc * Tc * Mc];
__device__ float g_z   [Bc * Hc];
__device__ float g_xgd0[Bc * GMc];
__device__ float g_w4e0[(Hc * Hc + 2048) * 4];
__device__ float g_w4e1[(Hc * Hc + 2048) * 4];
__device__ float g_w4d0[(Mc * Mc + 1024) * 4];
__device__ float g_w4d1[(Mc * Mc + 1024) * 4];

// ---------------- f32x2 helpers ----------------
__device__ __forceinline__ ull pack2f(float x, float y) {
    ull r; asm("mov.b64 %0, {%1, %2};" : "=l"(r) : "f"(x), "f"(y)); return r;
}
__device__ __forceinline__ float2 unpack2f(ull v) {
    float2 r; asm("mov.b64 {%0, %1}, %2;" : "=f"(r.x), "=f"(r.y) : "l"(v)); return r;
}
__device__ __forceinline__ ull fma2f(ull a, ull b, ull c) {
    ull d; asm("fma.rn.f32x2 %0, %1, %2, %3;" : "=l"(d) : "l"(a), "l"(b), "l"(c)); return d;
}

__device__ __forceinline__ float sigf(float x) {
    return __fdividef(1.0f, 1.0f + __expf(-x));
}
__device__ __forceinline__ float tanh_(float x) {  // NaN-safe fast tanh
    return 1.0f - __fdividef(2.0f, __expf(2.0f * x) + 1.0f);
}

// ---------------- tf32 mma helpers ----------------
__device__ __forceinline__ u32 cvt_tf32(float x) {
    u32 r; asm("cvt.rna.tf32.f32 %0, %1;" : "=r"(r) : "f"(x)); return r;
}
__device__ __forceinline__ void mma_tf32(float4& d, u32 a0, u32 a1, u32 a2, u32 a3,
                                         u32 b0, u32 b1) {
    asm("mma.sync.aligned.m16n8k8.row.col.f32.tf32.tf32.f32 "
        "{%0,%1,%2,%3}, {%4,%5,%6,%7}, {%8,%9}, {%0,%1,%2,%3};"
        : "+f"(d.x), "+f"(d.y), "+f"(d.z), "+f"(d.w)
        : "r"(a0), "r"(a1), "r"(a2), "r"(a3), "r"(b0), "r"(b1));
}

// ---------------- weight prep: src (4H x H) -> dst float4[k][j] ----------------
__global__ void prep_w4(const float* __restrict__ src, float* __restrict__ dst, int H) {
    __shared__ float tile[32][33];
    int g = blockIdx.z;
    int k0 = blockIdx.x * 32, j0 = blockIdx.y * 32;
    int x = threadIdx.x, y = threadIdx.y;
#pragma unroll
    for (int i = 0; i < 32; i += 8)
        tile[y + i][x] = src[(size_t)(g * H + j0 + y + i) * H + k0 + x];
    __syncthreads();
#pragma unroll
    for (int i = 0; i < 32; i += 8)
        dst[((size_t)(k0 + y + i) * H + (j0 + x)) * 4 + g] = tile[x][y + i];
}

// ---------------- GEMM (BM=128, BN=64) fp32 for N=64 (input proj, relu) ----------------
template <bool RELU, bool HASB2>
__global__ void __launch_bounds__(256) gemm64(
    const float* __restrict__ A, const float* __restrict__ W,
    const float* __restrict__ b1, const float* __restrict__ b2,
    float* __restrict__ C, int Mdim, int Ndim, int Kdim) {
    constexpr int BK = 16;
    __shared__ float As[BK][128];
    __shared__ float Ws[BK][64];

    const int tid = threadIdx.x;
    const int tx = tid & 15;
    const int ty = tid >> 4;
    const size_t bm = (size_t)blockIdx.x * 128;
    const size_t bn = (size_t)blockIdx.y * 64;
    const int lr = tid >> 2;
    const int lk = (tid & 3) << 2;

    ull acc[4][4];
#pragma unroll
    for (int i = 0; i < 4; i++)
#pragma unroll
        for (int j = 0; j < 4; j++) acc[i][j] = 0ull;

    const float* Ap0 = A + (bm + lr) * (size_t)Kdim + lk;
    const float* Ap1 = A + (bm + lr + 64) * (size_t)Kdim + lk;
    const float* Wp  = W + (bn + lr) * (size_t)Kdim + lk;

    for (int k0 = 0; k0 < Kdim; k0 += BK) {
        float4 av0 = *(const float4*)(Ap0 + k0);
        float4 av1 = *(const float4*)(Ap1 + k0);
        float4 wv  = *(const float4*)(Wp + k0);
        __syncthreads();
        As[lk + 0][lr] = av0.x; As[lk + 1][lr] = av0.y;
        As[lk + 2][lr] = av0.z; As[lk + 3][lr] = av0.w;
        As[lk + 0][lr + 64] = av1.x; As[lk + 1][lr + 64] = av1.y;
        As[lk + 2][lr + 64] = av1.z; As[lk + 3][lr + 64] = av1.w;
        Ws[lk + 0][lr] = wv.x; Ws[lk + 1][lr] = wv.y;
        Ws[lk + 2][lr] = wv.z; Ws[lk + 3][lr] = wv.w;
        __syncthreads();
#pragma unroll
        for (int kk = 0; kk < BK; kk++) {
            float4 a0 = *(const float4*)&As[kk][ty * 8];
            float4 a1 = *(const float4*)&As[kk][ty * 8 + 4];
            float4 w4 = *(const float4*)&Ws[kk][tx * 4];
            ull a2[4] = {pack2f(a0.x, a0.y), pack2f(a0.z, a0.w),
                         pack2f(a1.x, a1.y), pack2f(a1.z, a1.w)};
            ull w2[4] = {pack2f(w4.x, w4.x), pack2f(w4.y, w4.y),
                         pack2f(w4.z, w4.z), pack2f(w4.w, w4.w)};
#pragma unroll
            for (int i = 0; i < 4; i++)
#pragma unroll
                for (int j = 0; j < 4; j++)
                    acc[i][j] = fma2f(a2[i], w2[j], acc[i][j]);
        }
    }

    float bias[4];
#pragma unroll
    for (int j = 0; j < 4; j++) {
        bias[j] = b1[bn + tx * 4 + j];
        if (HASB2) bias[j] += b2[bn + tx * 4 + j];
    }
#pragma unroll
    for (int i = 0; i < 4; i++) {
        float2 v0 = unpack2f(acc[i][0]);
        float2 v1 = unpack2f(acc[i][1]);
        float2 v2 = unpack2f(acc[i][2]);
        float2 v3 = unpack2f(acc[i][3]);
        float4 o0 = make_float4(v0.x + bias[0], v1.x + bias[1], v2.x + bias[2], v3.x + bias[3]);
        float4 o1 = make_float4(v0.y + bias[0], v1.y + bias[1], v2.y + bias[2], v3.y + bias[3]);
        if (RELU) {
            o0.x = fmaxf(o0.x, 0.f); o0.y = fmaxf(o0.y, 0.f);
            o0.z = fmaxf(o0.z, 0.f); o0.w = fmaxf(o0.w, 0.f);
            o1.x = fmaxf(o1.x, 0.f); o1.y = fmaxf(o1.y, 0.f);
            o1.z = fmaxf(o1.z, 0.f); o1.w = fmaxf(o1.w, 0.f);
        }
        size_t r0 = bm + ty * 8 + 2 * i;
        *(float4*)&C[r0 * Ndim + bn + tx * 4]       = o0;
        *(float4*)&C[(r0 + 1) * Ndim + bn + tx * 4] = o1;
    }
}

// ---------------- tf32 tensor-core GEMM (BM=128, BN=128, BK=16) ----------------
// C[M,N] = A[M,K] @ W[N,K]^T + b1 (+ b2). Fragments staged in smem in register layout.
// Warp grid 4(M) x 2(N); warp tile 32x64; per warp 2 m-tiles x 8 n-tiles of m16n8k8.
template <bool HASB2>
__global__ void __launch_bounds__(256) gemm_tf32(
    const float* __restrict__ A, const float* __restrict__ W,
    const float* __restrict__ b1, const float* __restrict__ b2,
    float* __restrict__ C, int Mdim, int Ndim, int Kdim) {
    __shared__ u32 As[2][2048];   // [k8][mtile][lane][4regs]
    __shared__ u32 Bs[2][2048];   // [k8][ntile][lane][2regs]

    const int tid = threadIdx.x;
    const int lane = tid & 31;
    const int wid = tid >> 5;
    const int wm = wid & 3;
    const int wn = wid >> 2;
    const int gid = lane >> 2;
    const int tig = lane & 3;
    const size_t bm = (size_t)blockIdx.x * 128;
    const size_t bn = (size_t)blockIdx.y * 128;

    float4 acc[2][8];
#pragma unroll
    for (int mt = 0; mt < 2; mt++)
#pragma unroll
        for (int nt = 0; nt < 8; nt++) acc[mt][nt] = make_float4(0.f, 0.f, 0.f, 0.f);

    // fill-side: each thread owns 2 float4 of A tile and 2 of W tile per stage
    int baseA[2], baseB[2];
    const float* ApG[2];
    const float* WpG[2];
#pragma unroll
    for (int i = 0; i < 2; i++) {
        int fidx = tid + 256 * i;
        int row = fidx >> 2, c4 = fidx & 3;           // row 0..127, c4 selects 4 k's
        int k8 = c4 >> 1, regK = c4 & 1;
        int mtile = row >> 4, r = row & 15;
        baseA[i] = (((k8 * 8 + mtile) * 32 + (r & 7) * 4)) * 4 + (r >> 3) + 2 * regK;
        ApG[i] = A + (bm + row) * (size_t)Kdim + c4 * 4;
        int ntile = row >> 3, ngid = row & 7;
        baseB[i] = (((k8 * 16 + ntile) * 32 + ngid * 4)) * 2 + regK;
        WpG[i] = W + (bn + row) * (size_t)Kdim + c4 * 4;
    }

    float4 av[2], wv[2];

#define TF32_LOAD(K0)                                  \
    av[0] = *(const float4*)(ApG[0] + (K0));           \
    av[1] = *(const float4*)(ApG[1] + (K0));           \
    wv[0] = *(const float4*)(WpG[0] + (K0));           \
    wv[1] = *(const float4*)(WpG[1] + (K0));

#define TF32_STORE(BUF)                                                        \
    _Pragma("unroll")                                                          \
    for (int i = 0; i < 2; i++) {                                              \
        As[BUF][baseA[i] + 0]  = cvt_tf32(av[i].x);                            \
        As[BUF][baseA[i] + 4]  = cvt_tf32(av[i].y);                            \
        As[BUF][baseA[i] + 8]  = cvt_tf32(av[i].z);                            \
        As[BUF][baseA[i] + 12] = cvt_tf32(av[i].w);                            \
        Bs[BUF][baseB[i] + 0]  = cvt_tf32(wv[i].x);                            \
        Bs[BUF][baseB[i] + 2]  = cvt_tf32(wv[i].y);                            \
        Bs[BUF][baseB[i] + 4]  = cvt_tf32(wv[i].z);                            \
        Bs[BUF][baseB[i] + 6]  = cvt_tf32(wv[i].w);                            \
    }

#define TF32_COMP(BUF)                                                             \
    _Pragma("unroll")                                                              \
    for (int k8 = 0; k8 < 2; k8++) {                                               \
        uint4 af[2]; uint2 bf[8];                                                  \
        _Pragma("unroll")                                                          \
        for (int mt = 0; mt < 2; mt++)                                             \
            af[mt] = *(const uint4*)&As[BUF][((k8 * 8 + wm * 2 + mt) * 32 + lane) * 4]; \
        _Pragma("unroll")                                                          \
        for (int nt = 0; nt < 8; nt++)                                             \
            bf[nt] = *(const uint2*)&Bs[BUF][((k8 * 16 + wn * 8 + nt) * 32 + lane) * 2]; \
        _Pragma("unroll")                                                          \
        for (int mt = 0; mt < 2; mt++)                                             \
            _Pragma("unroll")                                                      \
            for (int nt = 0; nt < 8; nt++)                                         \
                mma_tf32(acc[mt][nt], af[mt].x, af[mt].y, af[mt].z, af[mt].w,      \
                         bf[nt].x, bf[nt].y);                                      \
    }

    TF32_LOAD(0);
    TF32_STORE(0);
    __syncthreads();
    const int nb = Kdim >> 4;
#pragma unroll 1
    for (int it = 1; it < nb; it++) {
        TF32_LOAD(it * 16);
        TF32_COMP((it - 1) & 1);
        TF32_STORE(it & 1);
        __syncthreads();
    }
    TF32_COMP((nb - 1) & 1);

    // epilogue
#pragma unroll
    for (int mt = 0; mt < 2; mt++) {
        int row0 = (int)bm + wm * 32 + mt * 16 + gid;
#pragma unroll
        for (int nt = 0; nt < 8; nt++) {
            int col = (int)bn + wn * 64 + nt * 8 + 2 * tig;
            float bb0 = b1[col], bb1 = b1[col + 1];
            if (HASB2) { bb0 += b2[col]; bb1 += b2[col + 1]; }
            *(float2*)&C[(size_t)row0 * Ndim + col] =
                make_float2(acc[mt][nt].x + bb0, acc[mt][nt].y + bb1);
            *(float2*)&C[(size_t)(row0 + 8) * Ndim + col] =
                make_float2(acc[mt][nt].z + bb0, acc[mt][nt].w + bb1);
        }
    }
}

// ---------------- encoder LSTM (H=256), smem weight cache + packed h reads ----------------
#define EPROC(KK, WV)                                                              \
    {                                                                              \
        const ulonglong2* hp = (const ulonglong2*)&shc[(KK)][0];                   \
        ulonglong2 hA = hp[0], hB = hp[1];                                         \
        ull wi = pack2f((WV).x, (WV).x), wf = pack2f((WV).y, (WV).y);              \
        ull wg = pack2f((WV).z, (WV).z), wo = pack2f((WV).w, (WV).w);              \
        acc[0][0] = fma2f(hA.x, wi, acc[0][0]); acc[0][1] = fma2f(hA.y, wi, acc[0][1]); \
        acc[0][2] = fma2f(hB.x, wi, acc[0][2]); acc[0][3] = fma2f(hB.y, wi, acc[0][3]); \
        acc[1][0] = fma2f(hA.x, wf, acc[1][0]); acc[1][1] = fma2f(hA.y, wf, acc[1][1]); \
        acc[1][2] = fma2f(hB.x, wf, acc[1][2]); acc[1][3] = fma2f(hB.y, wf, acc[1][3]); \
        acc[2][0] = fma2f(hA.x, wg, acc[2][0]); acc[2][1] = fma2f(hA.y, wg, acc[2][1]); \
        acc[2][2] = fma2f(hB.x, wg, acc[2][2]); acc[2][3] = fma2f(hB.y, wg, acc[2][3]); \
        acc[3][0] = fma2f(hA.x, wo, acc[3][0]); acc[3][1] = fma2f(hA.y, wo, acc[3][1]); \
        acc[3][2] = fma2f(hB.x, wo, acc[3][2]); acc[3][3] = fma2f(hB.y, wo, acc[3][3]); \
    }

__global__ void __launch_bounds__(256, 1) lstm_enc(
    const float4* __restrict__ w4, const float* __restrict__ xg,
    float* __restrict__ h_all, float* __restrict__ z_last) {
    extern __shared__ __align__(16) char smraw[];
    float2 (*shh)[Hc][4] = (float2(*)[Hc][4])smraw;
    float4* wc = (float4*)(smraw + 2 * Hc * 4 * sizeof(float2));

    const int b0 = blockIdx.x * 8;
    const int j = threadIdx.x;

    for (int idx = threadIdx.x; idx < KC * Hc; idx += 256)
        wc[idx] = w4[idx];

    float c[8];
#pragma unroll
    for (int r = 0; r < 8; r++) c[r] = 0.f;
#pragma unroll
    for (int rp = 0; rp < 4; rp++) shh[0][j][rp] = make_float2(0.f, 0.f);
    __syncthreads();

    const float4* wj = w4 + j;
    int cur = 0;

#pragma unroll 1
    for (int t = 0; t < Tc; t++) {
        ull acc[4][4];
#pragma unroll
        for (int g = 0; g < 4; g++)
#pragma unroll
            for (int rp = 0; rp < 4; rp++) {
                float lo = xg[((size_t)(b0 + 2 * rp) * Tc + t) * Gc + g * Hc + j];
                float hi = xg[((size_t)(b0 + 2 * rp + 1) * Tc + t) * Gc + g * Hc + j];
                acc[g][rp] = pack2f(lo, hi);
            }

        const float2(*shc)[4] = shh[cur];

#pragma unroll 1
        for (int k = 0; k < KC; k += 8) {
#pragma unroll
            for (int u = 0; u < 8; u++) {
                float4 wv = wc[(k + u) * Hc + j];
                EPROC(k + u, wv);
            }
        }

        float4 wA[8], wB[8];
#pragma unroll
        for (int u = 0; u < 8; u++) wA[u] = __ldg(wj + (KC + u) * Hc);
#pragma unroll 1
        for (int k = KC; k < Hc; k += 16) {
#pragma unroll
            for (int u = 0; u < 8; u++) wB[u] = __ldg(wj + (k + 8 + u) * Hc);
#pragma unroll
            for (int u = 0; u < 8; u++) EPROC(k + u, wA[u]);
#pragma unroll
            for (int u = 0; u < 8; u++) wA[u] = __ldg(wj + (k + 16 + u) * Hc);
#pragma unroll
            for (int u = 0; u < 8; u++) EPROC(k + 8 + u, wB[u]);
        }

        int nxt = cur ^ 1;
#pragma unroll
        for (int rp = 0; rp < 4; rp++) {
            float2 iv = unpack2f(acc[0][rp]);
            float2 fv = unpack2f(acc[1][rp]);
            float2 gv = unpack2f(acc[2][rp]);
            float2 ov = unpack2f(acc[3][rp]);
            float2 hv;
            {
                float ii = sigf(iv.x), ff = sigf(fv.x);
                float gg = tanh_(gv.x), oo = sigf(ov.x);
                c[2 * rp] = ff * c[2 * rp] + ii * gg;
                hv.x = oo * tanh_(c[2 * rp]);
            }
            {
                float ii = sigf(iv.y), ff = sigf(fv.y);
                float gg = tanh_(gv.y), oo = sigf(ov.y);
                c[2 * rp + 1] = ff * c[2 * rp + 1] + ii * gg;
                hv.y = oo * tanh_(c[2 * rp + 1]);
            }
            shh[nxt][j][rp] = hv;
            if (h_all) {
                h_all[((size_t)(b0 + 2 * rp) * Tc + t) * Hc + j]     = hv.x;
                h_all[((size_t)(b0 + 2 * rp + 1) * Tc + t) * Hc + j] = hv.y;
            }
            if (z_last && t == Tc - 1) {
                z_last[(size_t)(b0 + 2 * rp) * Hc + j]     = hv.x;
                z_last[(size_t)(b0 + 2 * rp + 1) * Hc + j] = hv.y;
            }
        }
        __syncthreads();
        cur = nxt;
    }
}

// ---------------- decoder LSTM (H=64), all weights in smem ----------------
__global__ void __launch_bounds__(256) lstm_dec(
    const float4* __restrict__ w4, const float* __restrict__ xg,
    float* __restrict__ h_out, int per_t) {
    extern __shared__ __align__(16) char smraw[];
    float2 (*shh)[Mc][4] = (float2(*)[Mc][4])smraw;
    float4* wc = (float4*)(smraw + 2 * Mc * 4 * sizeof(float2));

    const int b0 = blockIdx.x * 8;
    const int j = threadIdx.x & 63;
    const int rg = threadIdx.x >> 6;

    for (int idx = threadIdx.x; idx < Mc * Mc; idx += 256)
        wc[idx] = w4[idx];
    shh[0][j][rg] = make_float2(0.f, 0.f);
    __syncthreads();

    float c0 = 0.f, c1 = 0.f;
    ull base[4];
    if (!per_t) {
#pragma unroll
        for (int g = 0; g < 4; g++)
            base[g] = pack2f(xg[(size_t)(b0 + rg) * GMc + g * Mc + j],
                             xg[(size_t)(b0 + rg + 4) * GMc + g * Mc + j]);
    }

    int cur = 0;
#pragma unroll 1
    for (int t = 0; t < Tc; t++) {
        ull acc[4];
        if (per_t) {
#pragma unroll
            for (int g = 0; g < 4; g++)
                acc[g] = pack2f(xg[((size_t)(b0 + rg) * Tc + t) * GMc + g * Mc + j],
                                xg[((size_t)(b0 + rg + 4) * Tc + t) * GMc + g * Mc + j]);
        } else {
#pragma unroll
            for (int g = 0; g < 4; g++) acc[g] = base[g];
        }

        const float2(*shc)[4] = shh[cur];
#pragma unroll 1
        for (int k = 0; k < Mc; k += 16) {
#pragma unroll
            for (int u = 0; u < 16; u++) {
                float4 wv = wc[(k + u) * Mc + j];
                ull h2 = *(const ull*)&shc[k + u][rg];
                acc[0] = fma2f(h2, pack2f(wv.x, wv.x), acc[0]);
                acc[1] = fma2f(h2, pack2f(wv.y, wv.y), acc[1]);
                acc[2] = fma2f(h2, pack2f(wv.z, wv.z), acc[2]);
                acc[3] = fma2f(h2, pack2f(wv.w, wv.w), acc[3]);
            }
        }

        float2 iv = unpack2f(acc[0]);
        float2 fv = unpack2f(acc[1]);
        float2 gv = unpack2f(acc[2]);
        float2 ov = unpack2f(acc[3]);
        c0 = sigf(fv.x) * c0 + sigf(iv.x) * tanh_(gv.x);
        float h0 = sigf(ov.x) * tanh_(c0);
        c1 = sigf(fv.y) * c1 + sigf(iv.y) * tanh_(gv.y);
        float h1 = sigf(ov.y) * tanh_(c1);

        int nxt = cur ^ 1;
        shh[nxt][j][rg] = make_float2(h0, h1);
        h_out[((size_t)(b0 + rg) * Tc + t) * Mc + j]     = h0;
        h_out[((size_t)(b0 + rg + 4) * Tc + t) * Mc + j] = h1;
        __syncthreads();
        cur = nxt;
    }
}

// ---------------- launch ----------------
extern "C" void kernel_launch(void* const* d_in, const int* in_sizes, int n_in,
                              void* d_out, int out_size) {
    const float* x    = (const float*)d_in[0];
    const float* in_W = (const float*)d_in[1];
    const float* in_b = (const float*)d_in[2];
    const float* eW0i = (const float*)d_in[3];
    const float* eW0h = (const float*)d_in[4];
    const float* eb0i = (const float*)d_in[5];
    const float* eb0h = (const float*)d_in[6];
    const float* eW1i = (const float*)d_in[7];
    const float* eW1h = (const float*)d_in[8];
    const float* eb1i = (const float*)d_in[9];
    const float* eb1h = (const float*)d_in[10];
    const float* dW0i = (const float*)d_in[11];
    const float* dW0h = (const float*)d_in[12];
    const float* db0i = (const float*)d_in[13];
    const float* db0h = (const float*)d_in[14];
    const float* dW1i = (const float*)d_in[15];
    const float* dW1h = (const float*)d_in[16];
    const float* db1i = (const float*)d_in[17];
    const float* db1h = (const float*)d_in[18];
    const float* outW = (const float*)d_in[19];
    const float* outb = (const float*)d_in[20];
    float* out = (float*)d_out;

    float *xg, *mid, *bufA, *bufB, *z, *xgd0, *w4e0, *w4e1, *w4d0, *w4d1;
    cudaGetSymbolAddress((void**)&xg,   g_xg);
    cudaGetSymbolAddress((void**)&mid,  g_mid);
    cudaGetSymbolAddress((void**)&bufA, g_bufA);
    cudaGetSymbolAddress((void**)&bufB, g_bufB);
    cudaGetSymbolAddress((void**)&z,    g_z);
    cudaGetSymbolAddress((void**)&xgd0, g_xgd0);
    cudaGetSymbolAddress((void**)&w4e0, g_w4e0);
    cudaGetSymbolAddress((void**)&w4e1, g_w4e1);
    cudaGetSymbolAddress((void**)&w4d0, g_w4d0);
    cudaGetSymbolAddress((void**)&w4d1, g_w4d1);

    const int MT = Bc * Tc;

    const int ENC_SMEM = 2 * Hc * 4 * sizeof(float2) + KC * Hc * sizeof(float4);
    const int DEC_SMEM = 2 * Mc * 4 * sizeof(float2) + Mc * Mc * sizeof(float4);
    static int configured = 0;
    if (!configured) {
        cudaFuncSetAttribute(lstm_enc, cudaFuncAttributeMaxDynamicSharedMemorySize, ENC_SMEM);
        cudaFuncSetAttribute(lstm_dec, cudaFuncAttributeMaxDynamicSharedMemorySize, DEC_SMEM);
        configured = 1;
    }

    // 1-3) weight preps (encoder + dec0)
    prep_w4<<<dim3(8, 8, 4), dim3(32, 8)>>>(eW0h, w4e0, Hc);
    prep_w4<<<dim3(8, 8, 4), dim3(32, 8)>>>(eW1h, w4e1, Hc);
    prep_w4<<<dim3(2, 2, 4), dim3(32, 8)>>>(dW0h, w4d0, Mc);
    // 4) h0 = relu(x @ in_W^T + in_b)                 : (102400,64)
    gemm64<true, false><<<dim3(MT / 128, 1), 256>>>(x, in_W, in_b, nullptr, bufA, MT, Mc, Dc);
    // 5) xg0 = h0 @ eW0i^T + eb0i + eb0h              : (102400,1024)
    gemm_tf32<true><<<dim3(MT / 128, Gc / 128), 256>>>(bufA, eW0i, eb0i, eb0h, xg, MT, Gc, Mc);
    // 6) enc0 recurrence -> h_enc0   (ncu -s 5 profiles this launch)
    lstm_enc<<<Bc / 8, 256, ENC_SMEM>>>((const float4*)w4e0, xg, mid, nullptr);
    // 7) xg1 = h_enc0 @ eW1i^T + eb1i + eb1h          : (102400,1024)
    gemm_tf32<true><<<dim3(MT / 128, Gc / 128), 256>>>(mid, eW1i, eb1i, eb1h, xg, MT, Gc, Hc);
    // 8) enc1 recurrence -> z                          : (1024,256)
    lstm_enc<<<Bc / 8, 256, ENC_SMEM>>>((const float4*)w4e1, xg, nullptr, z);
    // 9) dec1 weight prep
    prep_w4<<<dim3(2, 2, 4), dim3(32, 8)>>>(dW1h, w4d1, Mc);
    // 10) xg_dec0 = z @ dW0i^T + db0i + db0h           : (1024,256)
    gemm_tf32<true><<<dim3(Bc / 128, GMc / 128), 256>>>(z, dW0i, db0i, db0h, xgd0, Bc, GMc, Hc);
    // 11) dec0 recurrence -> d0                        : (102400,64)
    lstm_dec<<<Bc / 8, 256, DEC_SMEM>>>((const float4*)w4d0, xgd0, bufA, 0);
    // 12) xg_dec1 = d0 @ dW1i^T + db1i + db1h          : (102400,256)
    gemm_tf32<true><<<dim3(MT / 128, GMc / 128), 256>>>(bufA, dW1i, db1i, db1h, mid, MT, GMc, Mc);
    // 13) dec1 recurrence -> d1                        : (102400,64)
    lstm_dec<<<Bc / 8, 256, DEC_SMEM>>>((const float4*)w4d1, mid, bufB, 1);
    // 14) out = d1 @ out_W^T + out_b                   : (102400,256)
    gemm_tf32<false><<<dim3(MT / 128, Dc / 128), 256>>>(bufB, outW, outb, nullptr, out, MT, Dc, Mc);
}

// round 5
// speedup vs baseline: 3.7111x; 1.0869x over previous
#include <cuda_runtime.h>

// ---------------- problem dims ----------------
#define Bc   1024
#define Tc   100
#define Dc   256
#define Hc   256
#define Gc   1024
#define Mc   64
#define GMc  256

typedef unsigned long long ull;
typedef unsigned int u32;

// ---------------- device scratch ----------------
__device__ float g_xg  [(size_t)Bc * Tc * Gc];
__device__ float g_mid [(size_t)Bc * Tc * Hc];
__device__ float g_bufA[(size_t)Bc * Tc * Mc];
__device__ float g_bufB[(size_t)Bc * Tc * Mc];
__device__ float g_z   [Bc * Hc];
__device__ float g_xgd0[Bc * GMc];
__device__ u32   g_wf0 [Hc * Gc];          // enc0 Whh in B-fragment order (tf32 bits)
__device__ u32   g_wf1 [Hc * Gc];          // enc1
__device__ float g_wp  [Gc * Hc];          // permuted Wih (reused e0/e1)
__device__ float g_bp  [Gc];               // permuted combined bias
__device__ float g_w4d0[(Mc * Mc + 1024) * 4];
__device__ float g_w4d1[(Mc * Mc + 1024) * 4];

// ---------------- helpers ----------------
__device__ __forceinline__ ull pack2f(float x, float y) {
    ull r; asm("mov.b64 %0, {%1, %2};" : "=l"(r) : "f"(x), "f"(y)); return r;
}
__device__ __forceinline__ float2 unpack2f(ull v) {
    float2 r; asm("mov.b64 {%0, %1}, %2;" : "=f"(r.x), "=f"(r.y) : "l"(v)); return r;
}
__device__ __forceinline__ ull fma2f(ull a, ull b, ull c) {
    ull d; asm("fma.rn.f32x2 %0, %1, %2, %3;" : "=l"(d) : "l"(a), "l"(b), "l"(c)); return d;
}
__device__ __forceinline__ float sigf(float x) {
    return __fdividef(1.0f, 1.0f + __expf(-x));
}
__device__ __forceinline__ float tanh_(float x) {
    return 1.0f - __fdividef(2.0f, __expf(2.0f * x) + 1.0f);
}
__device__ __forceinline__ u32 cvt_tf32(float x) {
    u32 r; asm("cvt.rna.tf32.f32 %0, %1;" : "=r"(r) : "f"(x)); return r;
}
__device__ __forceinline__ void mma_tf32(float4& d, u32 a0, u32 a1, u32 a2, u32 a3,
                                         u32 b0, u32 b1) {
    asm("mma.sync.aligned.m16n8k8.row.col.f32.tf32.tf32.f32 "
        "{%0,%1,%2,%3}, {%4,%5,%6,%7}, {%8,%9}, {%0,%1,%2,%3};"
        : "+f"(d.x), "+f"(d.y), "+f"(d.z), "+f"(d.w)
        : "r"(a0), "r"(a1), "r"(a2), "r"(a3), "r"(b0), "r"(b1));
}

// gate-permutation: n' = w*128 + nt*8 + c  <->  orig = (nt&3)*256 + w*32 + (nt>>2)*8 + c

// ---------------- enc weight prep: Whh(1024x256) -> B-fragment order ----------------
// wf[t]: t = (((p*8 + w)*16 + nt)*32 + lane)*4 + reg
__global__ void prep_wfrag(const float* __restrict__ Wh, u32* __restrict__ wf) {
    int t = blockIdx.x * 256 + threadIdx.x;
    int reg = t & 3, lane = (t >> 2) & 31, nt = (t >> 7) & 15, w = (t >> 11) & 7, p = t >> 14;
    int gid = lane >> 2, tig = lane & 3;
    int orig_n = (nt & 3) * 256 + w * 32 + ((nt >> 2) << 3) + gid;
    int k = 16 * p + 8 * (reg >> 1) + tig + 4 * (reg & 1);
    wf[t] = cvt_tf32(Wh[orig_n * Hc + k]);
}

// ---------------- permute Wih rows + combined bias into gate order ----------------
__global__ void perm_wi(const float* __restrict__ Wi, const float* __restrict__ bi,
                        const float* __restrict__ bh, float* __restrict__ Wp,
                        float* __restrict__ bp, int K) {
    int np = blockIdx.x;
    int w = np >> 7, nt = (np >> 3) & 15, c = np & 7;
    int orig = (nt & 3) * 256 + w * 32 + ((nt >> 2) << 3) + c;
    for (int k = threadIdx.x; k < K; k += blockDim.x)
        Wp[(size_t)np * K + k] = Wi[(size_t)orig * K + k];
    if (threadIdx.x == 0) bp[np] = bi[orig] + bh[orig];
}

// ---------------- dec weight prep: src (4H x H) -> float4[k][j] ----------------
__global__ void prep_w4(const float* __restrict__ src, float* __restrict__ dst, int H) {
    __shared__ float tile[32][33];
    int g = blockIdx.z;
    int k0 = blockIdx.x * 32, j0 = blockIdx.y * 32;
    int x = threadIdx.x, y = threadIdx.y;
#pragma unroll
    for (int i = 0; i < 32; i += 8)
        tile[y + i][x] = src[(size_t)(g * H + j0 + y + i) * H + k0 + x];
    __syncthreads();
#pragma unroll
    for (int i = 0; i < 32; i += 8)
        dst[((size_t)(k0 + y + i) * H + (j0 + x)) * 4 + g] = tile[x][y + i];
}

// ---------------- fp32 GEMM (BM=128, BN=64), relu ----------------
template <bool RELU, bool HASB2>
__global__ void __launch_bounds__(256) gemm64(
    const float* __restrict__ A, const float* __restrict__ W,
    const float* __restrict__ b1, const float* __restrict__ b2,
    float* __restrict__ C, int Mdim, int Ndim, int Kdim) {
    constexpr int BK = 16;
    __shared__ float As[BK][128];
    __shared__ float Ws[BK][64];

    const int tid = threadIdx.x;
    const int tx = tid & 15;
    const int ty = tid >> 4;
    const size_t bm = (size_t)blockIdx.x * 128;
    const size_t bn = (size_t)blockIdx.y * 64;
    const int lr = tid >> 2;
    const int lk = (tid & 3) << 2;

    ull acc[4][4];
#pragma unroll
    for (int i = 0; i < 4; i++)
#pragma unroll
        for (int j = 0; j < 4; j++) acc[i][j] = 0ull;

    const float* Ap0 = A + (bm + lr) * (size_t)Kdim + lk;
    const float* Ap1 = A + (bm + lr + 64) * (size_t)Kdim + lk;
    const float* Wp  = W + (bn + lr) * (size_t)Kdim + lk;

    for (int k0 = 0; k0 < Kdim; k0 += BK) {
        float4 av0 = *(const float4*)(Ap0 + k0);
        float4 av1 = *(const float4*)(Ap1 + k0);
        float4 wv  = *(const float4*)(Wp + k0);
        __syncthreads();
        As[lk + 0][lr] = av0.x; As[lk + 1][lr] = av0.y;
        As[lk + 2][lr] = av0.z; As[lk + 3][lr] = av0.w;
        As[lk + 0][lr + 64] = av1.x; As[lk + 1][lr + 64] = av1.y;
        As[lk + 2][lr + 64] = av1.z; As[lk + 3][lr + 64] = av1.w;
        Ws[lk + 0][lr] = wv.x; Ws[lk + 1][lr] = wv.y;
        Ws[lk + 2][lr] = wv.z; Ws[lk + 3][lr] = wv.w;
        __syncthreads();
#pragma unroll
        for (int kk = 0; kk < BK; kk++) {
            float4 a0 = *(const float4*)&As[kk][ty * 8];
            float4 a1 = *(const float4*)&As[kk][ty * 8 + 4];
            float4 w4 = *(const float4*)&Ws[kk][tx * 4];
            ull a2[4] = {pack2f(a0.x, a0.y), pack2f(a0.z, a0.w),
                         pack2f(a1.x, a1.y), pack2f(a1.z, a1.w)};
            ull w2[4] = {pack2f(w4.x, w4.x), pack2f(w4.y, w4.y),
                         pack2f(w4.z, w4.z), pack2f(w4.w, w4.w)};
#pragma unroll
            for (int i = 0; i < 4; i++)
#pragma unroll
                for (int j = 0; j < 4; j++)
                    acc[i][j] = fma2f(a2[i], w2[j], acc[i][j]);
        }
    }

    float bias[4];
#pragma unroll
    for (int j = 0; j < 4; j++) {
        bias[j] = b1[bn + tx * 4 + j];
        if (HASB2) bias[j] += b2[bn + tx * 4 + j];
    }
#pragma unroll
    for (int i = 0; i < 4; i++) {
        float2 v0 = unpack2f(acc[i][0]);
        float2 v1 = unpack2f(acc[i][1]);
        float2 v2 = unpack2f(acc[i][2]);
        float2 v3 = unpack2f(acc[i][3]);
        float4 o0 = make_float4(v0.x + bias[0], v1.x + bias[1], v2.x + bias[2], v3.x + bias[3]);
        float4 o1 = make_float4(v0.y + bias[0], v1.y + bias[1], v2.y + bias[2], v3.y + bias[3]);
        if (RELU) {
            o0.x = fmaxf(o0.x, 0.f); o0.y = fmaxf(o0.y, 0.f);
            o0.z = fmaxf(o0.z, 0.f); o0.w = fmaxf(o0.w, 0.f);
            o1.x = fmaxf(o1.x, 0.f); o1.y = fmaxf(o1.y, 0.f);
            o1.z = fmaxf(o1.z, 0.f); o1.w = fmaxf(o1.w, 0.f);
        }
        size_t r0 = bm + ty * 8 + 2 * i;
        *(float4*)&C[r0 * Ndim + bn + tx * 4]       = o0;
        *(float4*)&C[(r0 + 1) * Ndim + bn + tx * 4] = o1;
    }
}

// ---------------- tf32 GEMM (BM=128, BN=128, BK=16), double-buffered ----------------
template <bool HASB2>
__global__ void __launch_bounds__(256) gemm_tf32(
    const float* __restrict__ A, const float* __restrict__ W,
    const float* __restrict__ b1, const float* __restrict__ b2,
    float* __restrict__ C, int Mdim, int Ndim, int Kdim) {
    __shared__ u32 As[2][2048];
    __shared__ u32 Bs[2][2048];

    const int tid = threadIdx.x;
    const int lane = tid & 31;
    const int wid = tid >> 5;
    const int wm = wid & 3;
    const int wn = wid >> 2;
    const int gid = lane >> 2;
    const int tig = lane & 3;
    const size_t bm = (size_t)blockIdx.x * 128;
    const size_t bn = (size_t)blockIdx.y * 128;

    float4 acc[2][8];
#pragma unroll
    for (int mt = 0; mt < 2; mt++)
#pragma unroll
        for (int nt = 0; nt < 8; nt++) acc[mt][nt] = make_float4(0.f, 0.f, 0.f, 0.f);

    int baseA[2], baseB[2];
    const float* ApG[2];
    const float* WpG[2];
#pragma unroll
    for (int i = 0; i < 2; i++) {
        int fidx = tid + 256 * i;
        int row = fidx >> 2, c4 = fidx & 3;
        int k8 = c4 >> 1, regK = c4 & 1;
        int mtile = row >> 4, r = row & 15;
        baseA[i] = (((k8 * 8 + mtile) * 32 + (r & 7) * 4)) * 4 + (r >> 3) + 2 * regK;
        ApG[i] = A + (bm + row) * (size_t)Kdim + c4 * 4;
        int ntile = row >> 3, ngid = row & 7;
        baseB[i] = (((k8 * 16 + ntile) * 32 + ngid * 4)) * 2 + regK;
        WpG[i] = W + (bn + row) * (size_t)Kdim + c4 * 4;
    }

    float4 av[2], wv[2];

#define TF32_LOAD(K0)                                  \
    av[0] = *(const float4*)(ApG[0] + (K0));           \
    av[1] = *(const float4*)(ApG[1] + (K0));           \
    wv[0] = *(const float4*)(WpG[0] + (K0));           \
    wv[1] = *(const float4*)(WpG[1] + (K0));

#define TF32_STORE(BUF)                                                        \
    _Pragma("unroll")                                                          \
    for (int i = 0; i < 2; i++) {                                              \
        As[BUF][baseA[i] + 0]  = cvt_tf32(av[i].x);                            \
        As[BUF][baseA[i] + 4]  = cvt_tf32(av[i].y);                            \
        As[BUF][baseA[i] + 8]  = cvt_tf32(av[i].z);                            \
        As[BUF][baseA[i] + 12] = cvt_tf32(av[i].w);                            \
        Bs[BUF][baseB[i] + 0]  = cvt_tf32(wv[i].x);                            \
        Bs[BUF][baseB[i] + 2]  = cvt_tf32(wv[i].y);                            \
        Bs[BUF][baseB[i] + 4]  = cvt_tf32(wv[i].z);                            \
        Bs[BUF][baseB[i] + 6]  = cvt_tf32(wv[i].w);                            \
    }

#define TF32_COMP(BUF)                                                             \
    _Pragma("unroll")                                                              \
    for (int k8 = 0; k8 < 2; k8++) {                                               \
        uint4 af[2]; uint2 bf[8];                                                  \
        _Pragma("unroll")                                                          \
        for (int mt = 0; mt < 2; mt++)                                             \
            af[mt] = *(const uint4*)&As[BUF][((k8 * 8 + wm * 2 + mt) * 32 + lane) * 4]; \
        _Pragma("unroll")                                                          \
        for (int nt = 0; nt < 8; nt++)                                             \
            bf[nt] = *(const uint2*)&Bs[BUF][((k8 * 16 + wn * 8 + nt) * 32 + lane) * 2]; \
        _Pragma("unroll")                                                          \
        for (int mt = 0; mt < 2; mt++)                                             \
            _Pragma("unroll")                                                      \
            for (int nt = 0; nt < 8; nt++)                                         \
                mma_tf32(acc[mt][nt], af[mt].x, af[mt].y, af[mt].z, af[mt].w,      \
                         bf[nt].x, bf[nt].y);                                      \
    }

    TF32_LOAD(0);
    TF32_STORE(0);
    __syncthreads();
    const int nb = Kdim >> 4;
#pragma unroll 1
    for (int it = 1; it < nb; it++) {
        TF32_LOAD(it * 16);
        TF32_COMP((it - 1) & 1);
        TF32_STORE(it & 1);
        __syncthreads();
    }
    TF32_COMP((nb - 1) & 1);

#pragma unroll
    for (int mt = 0; mt < 2; mt++) {
        int row0 = (int)bm + wm * 32 + mt * 16 + gid;
#pragma unroll
        for (int nt = 0; nt < 8; nt++) {
            int col = (int)bn + wn * 64 + nt * 8 + 2 * tig;
            float bb0 = b1[col], bb1 = b1[col + 1];
            if (HASB2) { bb0 += b2[col]; bb1 += b2[col + 1]; }
            *(float2*)&C[(size_t)row0 * Ndim + col] =
                make_float2(acc[mt][nt].x + bb0, acc[mt][nt].y + bb1);
            *(float2*)&C[(size_t)(row0 + 8) * Ndim + col] =
                make_float2(acc[mt][nt].z + bb0, acc[mt][nt].w + bb1);
        }
    }
}

// ---------------- tensor-core encoder LSTM: 16 rows/CTA, 64 CTAs ----------------
// smem: hs[2][256*24] u32 (tf32 h, stride 24, conflict-free A frags) + wc cache (2 k8-pairs/warp)
#define HS_WORDS 6144
#define WC_U4    (8 * 2 * 16 * 32)     // 8192 uint4 = 128 KB

__global__ void __launch_bounds__(256, 1) lstm_enc_tc(
    const uint4* __restrict__ wf, const float* __restrict__ xg,
    float* __restrict__ h_all, float* __restrict__ z_last) {
    extern __shared__ __align__(16) u32 sm[];
    u32* hsbuf[2] = {sm, sm + HS_WORDS};
    uint4* wc = (uint4*)(sm + 2 * HS_WORDS);

    const int tid = threadIdx.x;
    const int lane = tid & 31, w = tid >> 5;
    const int gid = lane >> 2, tig = lane & 3;
    const int b0 = blockIdx.x * 16;

    // cache pairs p=0,1 for this warp (coalesced per-warp copy)
#pragma unroll
    for (int i = 0; i < 32; i++) {
        int idx = i * 32 + lane;                    // (p,nt,lane')
        int p = idx >> 9, nt = (idx >> 5) & 15, ln = idx & 31;
        wc[((w * 2 + p) * 16 + nt) * 32 + ln] = wf[((p * 8 + w) * 16 + nt) * 32 + ln];
    }
    for (int i = tid; i < HS_WORDS; i += 256) hsbuf[0][i] = 0;
    __syncthreads();

    float4 acc[16];
    float cst[16];
#pragma unroll
    for (int i = 0; i < 16; i++) cst[i] = 0.f;

    const size_t ro0 = ((size_t)(b0 + gid) * Tc) * Gc;
    const size_t ro1 = ((size_t)(b0 + gid + 8) * Tc) * Gc;
    const int ncol = w * 128 + 2 * tig;
    int cur = 0;

#pragma unroll 1
    for (int t = 0; t < Tc; t++) {
        const u32* hc = hsbuf[cur];
        u32* hn = hsbuf[cur ^ 1];

        // init acc from xg (already permuted, biases included)
        const float* xr0 = xg + ro0 + (size_t)t * Gc + ncol;
        const float* xr1 = xg + ro1 + (size_t)t * Gc + ncol;
#pragma unroll
        for (int nt = 0; nt < 16; nt++) {
            float2 lo = *(const float2*)(xr0 + nt * 8);
            float2 hi = *(const float2*)(xr1 + nt * 8);
            acc[nt] = make_float4(lo.x, lo.y, hi.x, hi.y);
        }

        uint4 bufA[8], bufB[8];
        // preload half0 of p=0 from smem cache
#pragma unroll
        for (int i = 0; i < 8; i++) bufA[i] = wc[((w * 2 + 0) * 16 + i) * 32 + lane];

#pragma unroll 4
        for (int p = 0; p < 16; p++) {
            const int k0 = p * 16;
            u32 a[8];
            a[0] = hc[(k0 + tig) * 24 + gid];
            a[1] = hc[(k0 + tig) * 24 + gid + 8];
            a[2] = hc[(k0 + tig + 4) * 24 + gid];
            a[3] = hc[(k0 + tig + 4) * 24 + gid + 8];
            a[4] = hc[(k0 + 8 + tig) * 24 + gid];
            a[5] = hc[(k0 + 8 + tig) * 24 + gid + 8];
            a[6] = hc[(k0 + 8 + tig + 4) * 24 + gid];
            a[7] = hc[(k0 + 8 + tig + 4) * 24 + gid + 8];

            // prefetch half1 of p
            if (p < 2) {
#pragma unroll
                for (int i = 0; i < 8; i++)
                    bufB[i] = wc[((w * 2 + p) * 16 + 8 + i) * 32 + lane];
            } else {
#pragma unroll
                for (int i = 0; i < 8; i++)
                    bufB[i] = wf[((p * 8 + w) * 16 + 8 + i) * 32 + lane];
            }
#pragma unroll
            for (int nt = 0; nt < 8; nt++) {
                mma_tf32(acc[nt], a[0], a[1], a[2], a[3], bufA[nt].x, bufA[nt].y);
                mma_tf32(acc[nt], a[4], a[5], a[6], a[7], bufA[nt].z, bufA[nt].w);
            }
            // prefetch half0 of p+1
            if (p < 15) {
                if (p + 1 < 2) {
#pragma unroll
                    for (int i = 0; i < 8; i++)
                        bufA[i] = wc[((w * 2 + p + 1) * 16 + i) * 32 + lane];
                } else {
#pragma unroll
                    for (int i = 0; i < 8; i++)
                        bufA[i] = wf[(((p + 1) * 8 + w) * 16 + i) * 32 + lane];
                }
            }
#pragma unroll
            for (int nt = 0; nt < 8; nt++) {
                mma_tf32(acc[8 + nt], a[0], a[1], a[2], a[3], bufB[nt].x, bufB[nt].y);
                mma_tf32(acc[8 + nt], a[4], a[5], a[6], a[7], bufB[nt].z, bufB[nt].w);
            }
        }

        // epilogue: groups g -> tiles 4g..4g+3 = i,f,g,o for j-octet g
#pragma unroll
        for (int g = 0; g < 4; g++) {
            float4 I = acc[4 * g + 0], F = acc[4 * g + 1];
            float4 G = acc[4 * g + 2], O = acc[4 * g + 3];
            int j0 = w * 32 + g * 8 + 2 * tig;
            float h[4];
            {
                float cc = sigf(F.x) * cst[g * 4 + 0] + sigf(I.x) * tanh_(G.x);
                cst[g * 4 + 0] = cc; h[0] = sigf(O.x) * tanh_(cc);
            }
            {
                float cc = sigf(F.y) * cst[g * 4 + 1] + sigf(I.y) * tanh_(G.y);
                cst[g * 4 + 1] = cc; h[1] = sigf(O.y) * tanh_(cc);
            }
            {
                float cc = sigf(F.z) * cst[g * 4 + 2] + sigf(I.z) * tanh_(G.z);
                cst[g * 4 + 2] = cc; h[2] = sigf(O.z) * tanh_(cc);
            }
            {
                float cc = sigf(F.w) * cst[g * 4 + 3] + sigf(I.w) * tanh_(G.w);
                cst[g * 4 + 3] = cc; h[3] = sigf(O.w) * tanh_(cc);
            }
            hn[j0 * 24 + gid]           = cvt_tf32(h[0]);
            hn[(j0 + 1) * 24 + gid]     = cvt_tf32(h[1]);
            hn[j0 * 24 + gid + 8]       = cvt_tf32(h[2]);
            hn[(j0 + 1) * 24 + gid + 8] = cvt_tf32(h[3]);
            if (h_all) {
                *(float2*)&h_all[((size_t)(b0 + gid) * Tc + t) * Hc + j0] =
                    make_float2(h[0], h[1]);
                *(float2*)&h_all[((size_t)(b0 + gid + 8) * Tc + t) * Hc + j0] =
                    make_float2(h[2], h[3]);
            }
            if (z_last && t == Tc - 1) {
                *(float2*)&z_last[(size_t)(b0 + gid) * Hc + j0] = make_float2(h[0], h[1]);
                *(float2*)&z_last[(size_t)(b0 + gid + 8) * Hc + j0] = make_float2(h[2], h[3]);
            }
        }
        __syncthreads();
        cur ^= 1;
    }
}

// ---------------- decoder LSTM (H=64), all weights in smem ----------------
__global__ void __launch_bounds__(256) lstm_dec(
    const float4* __restrict__ w4, const float* __restrict__ xg,
    float* __restrict__ h_out, int per_t) {
    extern __shared__ __align__(16) char smraw[];
    float2 (*shh)[Mc][4] = (float2(*)[Mc][4])smraw;
    float4* wc = (float4*)(smraw + 2 * Mc * 4 * sizeof(float2));

    const int b0 = blockIdx.x * 8;
    const int j = threadIdx.x & 63;
    const int rg = threadIdx.x >> 6;

    for (int idx = threadIdx.x; idx < Mc * Mc; idx += 256)
        wc[idx] = w4[idx];
    shh[0][j][rg] = make_float2(0.f, 0.f);
    __syncthreads();

    float c0 = 0.f, c1 = 0.f;
    ull base[4];
    if (!per_t) {
#pragma unroll
        for (int g = 0; g < 4; g++)
            base[g] = pack2f(xg[(size_t)(b0 + rg) * GMc + g * Mc + j],
                             xg[(size_t)(b0 + rg + 4) * GMc + g * Mc + j]);
    }

    int cur = 0;
#pragma unroll 1
    for (int t = 0; t < Tc; t++) {
        ull acc[4];
        if (per_t) {
#pragma unroll
            for (int g = 0; g < 4; g++)
                acc[g] = pack2f(xg[((size_t)(b0 + rg) * Tc + t) * GMc + g * Mc + j],
                                xg[((size_t)(b0 + rg + 4) * Tc + t) * GMc + g * Mc + j]);
        } else {
#pragma unroll
            for (int g = 0; g < 4; g++) acc[g] = base[g];
        }

        const float2(*shc)[4] = shh[cur];
#pragma unroll 1
        for (int k = 0; k < Mc; k += 16) {
#pragma unroll
            for (int u = 0; u < 16; u++) {
                float4 wv = wc[(k + u) * Mc + j];
                ull h2 = *(const ull*)&shc[k + u][rg];
                acc[0] = fma2f(h2, pack2f(wv.x, wv.x), acc[0]);
                acc[1] = fma2f(h2, pack2f(wv.y, wv.y), acc[1]);
                acc[2] = fma2f(h2, pack2f(wv.z, wv.z), acc[2]);
                acc[3] = fma2f(h2, pack2f(wv.w, wv.w), acc[3]);
            }
        }

        float2 iv = unpack2f(acc[0]);
        float2 fv = unpack2f(acc[1]);
        float2 gv = unpack2f(acc[2]);
        float2 ov = unpack2f(acc[3]);
        c0 = sigf(fv.x) * c0 + sigf(iv.x) * tanh_(gv.x);
        float h0 = sigf(ov.x) * tanh_(c0);
        c1 = sigf(fv.y) * c1 + sigf(iv.y) * tanh_(gv.y);
        float h1 = sigf(ov.y) * tanh_(c1);

        int nxt = cur ^ 1;
        shh[nxt][j][rg] = make_float2(h0, h1);
        h_out[((size_t)(b0 + rg) * Tc + t) * Mc + j]     = h0;
        h_out[((size_t)(b0 + rg + 4) * Tc + t) * Mc + j] = h1;
        __syncthreads();
        cur = nxt;
    }
}

// ---------------- launch ----------------
extern "C" void kernel_launch(void* const* d_in, const int* in_sizes, int n_in,
                              void* d_out, int out_size) {
    const float* x    = (const float*)d_in[0];
    const float* in_W = (const float*)d_in[1];
    const float* in_b = (const float*)d_in[2];
    const float* eW0i = (const float*)d_in[3];
    const float* eW0h = (const float*)d_in[4];
    const float* eb0i = (const float*)d_in[5];
    const float* eb0h = (const float*)d_in[6];
    const float* eW1i = (const float*)d_in[7];
    const float* eW1h = (const float*)d_in[8];
    const float* eb1i = (const float*)d_in[9];
    const float* eb1h = (const float*)d_in[10];
    const float* dW0i = (const float*)d_in[11];
    const float* dW0h = (const float*)d_in[12];
    const float* db0i = (const float*)d_in[13];
    const float* db0h = (const float*)d_in[14];
    const float* dW1i = (const float*)d_in[15];
    const float* dW1h = (const float*)d_in[16];
    const float* db1i = (const float*)d_in[17];
    const float* db1h = (const float*)d_in[18];
    const float* outW = (const float*)d_in[19];
    const float* outb = (const float*)d_in[20];
    float* out = (float*)d_out;

    float *xg, *mid, *bufA, *bufB, *z, *xgd0, *wp, *bp, *w4d0, *w4d1;
    u32 *wf0, *wf1;
    cudaGetSymbolAddress((void**)&xg,   g_xg);
    cudaGetSymbolAddress((void**)&mid,  g_mid);
    cudaGetSymbolAddress((void**)&bufA, g_bufA);
    cudaGetSymbolAddress((void**)&bufB, g_bufB);
    cudaGetSymbolAddress((void**)&z,    g_z);
    cudaGetSymbolAddress((void**)&xgd0, g_xgd0);
    cudaGetSymbolAddress((void**)&wf0,  g_wf0);
    cudaGetSymbolAddress((void**)&wf1,  g_wf1);
    cudaGetSymbolAddress((void**)&wp,   g_wp);
    cudaGetSymbolAddress((void**)&bp,   g_bp);
    cudaGetSymbolAddress((void**)&w4d0, g_w4d0);
    cudaGetSymbolAddress((void**)&w4d1, g_w4d1);

    const int MT = Bc * Tc;

    const int ENC_SMEM = 2 * HS_WORDS * 4 + WC_U4 * 16;                 // 48 KB + 128 KB
    const int DEC_SMEM = 2 * Mc * 4 * sizeof(float2) + Mc * Mc * sizeof(float4);
    static int configured = 0;
    if (!configured) {
        cudaFuncSetAttribute(lstm_enc_tc, cudaFuncAttributeMaxDynamicSharedMemorySize, ENC_SMEM);
        cudaFuncSetAttribute(lstm_dec, cudaFuncAttributeMaxDynamicSharedMemorySize, DEC_SMEM);
        configured = 1;
    }

    // 1-2) enc Whh fragment preps
    prep_wfrag<<<1024, 256>>>(eW0h, wf0);
    prep_wfrag<<<1024, 256>>>(eW1h, wf1);
    // 3) permute enc0 Wih + bias
    perm_wi<<<Gc, 64>>>(eW0i, eb0i, eb0h, wp, bp, Mc);
    // 4) h0 = relu(x @ in_W^T + in_b)
    gemm64<true, false><<<dim3(MT / 128, 1), 256>>>(x, in_W, in_b, nullptr, bufA, MT, Mc, Dc);
    // 5) xg0 (permuted cols) = h0 @ wp^T + bp
    gemm_tf32<false><<<dim3(MT / 128, Gc / 128), 256>>>(bufA, wp, bp, nullptr, xg, MT, Gc, Mc);
    // 6) enc0 recurrence -> h_enc0 (ncu profiles this)
    lstm_enc_tc<<<Bc / 16, 256, ENC_SMEM>>>((const uint4*)wf0, xg, mid, nullptr);
    // 7) permute enc1 Wih + bias
    perm_wi<<<Gc, 256>>>(eW1i, eb1i, eb1h, wp, bp, Hc);
    // 8) xg1 (permuted) = h_enc0 @ wp^T + bp
    gemm_tf32<false><<<dim3(MT / 128, Gc / 128), 256>>>(mid, wp, bp, nullptr, xg, MT, Gc, Hc);
    // 9) enc1 recurrence -> z
    lstm_enc_tc<<<Bc / 16, 256, ENC_SMEM>>>((const uint4*)wf1, xg, nullptr, z);
    // 10-11) dec weight preps
    prep_w4<<<dim3(2, 2, 4), dim3(32, 8)>>>(dW0h, w4d0, Mc);
    prep_w4<<<dim3(2, 2, 4), dim3(32, 8)>>>(dW1h, w4d1, Mc);
    // 12) xg_dec0 = z @ dW0i^T + db0i + db0h (t-const)
    gemm_tf32<true><<<dim3(Bc / 128, GMc / 128), 256>>>(z, dW0i, db0i, db0h, xgd0, Bc, GMc, Hc);
    // 13) dec0 -> d0
    lstm_dec<<<Bc / 8, 256, DEC_SMEM>>>((const float4*)w4d0, xgd0, bufA, 0);
    // 14) xg_dec1 = d0 @ dW1i^T + db1i + db1h
    gemm_tf32<true><<<dim3(MT / 128, GMc / 128), 256>>>(bufA, dW1i, db1i, db1h, mid, MT, GMc, Mc);
    // 15) dec1 -> d1
    lstm_dec<<<Bc / 8, 256, DEC_SMEM>>>((const float4*)w4d1, mid, bufB, 1);
    // 16) out = d1 @ out_W^T + out_b
    gemm_tf32<false><<<dim3(MT / 128, Dc / 128), 256>>>(bufB, outW, outb, nullptr, out, MT, Dc, Mc);
}

// round 6
// speedup vs baseline: 4.8747x; 1.3135x over previous
#include <cuda_runtime.h>

// ---------------- problem dims ----------------
#define Bc   1024
#define Tc   100
#define Dc   256
#define Hc   256
#define Gc   1024
#define Mc   64
#define GMc  256

typedef unsigned long long ull;
typedef unsigned int u32;

// ---------------- device scratch ----------------
__device__ float g_xg  [(size_t)Bc * Tc * Gc];
__device__ float g_mid [(size_t)Bc * Tc * Hc];
__device__ float g_bufA[(size_t)Bc * Tc * Mc];
__device__ float g_bufB[(size_t)Bc * Tc * Mc];
__device__ float g_z   [Bc * Hc];
__device__ float g_xgd0[Bc * GMc];
__device__ u32   g_wf0 [Hc * Gc];
__device__ u32   g_wf1 [Hc * Gc];
__device__ float g_wp  [Gc * Hc];
__device__ float g_bp  [Gc];
__device__ float g_w4d0[(Mc * Mc + 1024) * 4];
__device__ float g_w4d1[(Mc * Mc + 1024) * 4];

// ---------------- helpers ----------------
__device__ __forceinline__ ull pack2f(float x, float y) {
    ull r; asm("mov.b64 %0, {%1, %2};" : "=l"(r) : "f"(x), "f"(y)); return r;
}
__device__ __forceinline__ float2 unpack2f(ull v) {
    float2 r; asm("mov.b64 {%0, %1}, %2;" : "=f"(r.x), "=f"(r.y) : "l"(v)); return r;
}
__device__ __forceinline__ ull fma2f(ull a, ull b, ull c) {
    ull d; asm("fma.rn.f32x2 %0, %1, %2, %3;" : "=l"(d) : "l"(a), "l"(b), "l"(c)); return d;
}
__device__ __forceinline__ float sigf(float x) {
    return __fdividef(1.0f, 1.0f + __expf(-x));
}
__device__ __forceinline__ float tanh_(float x) {
    return 1.0f - __fdividef(2.0f, __expf(2.0f * x) + 1.0f);
}
__device__ __forceinline__ u32 cvt_tf32(float x) {
    u32 r; asm("cvt.rna.tf32.f32 %0, %1;" : "=r"(r) : "f"(x)); return r;
}
__device__ __forceinline__ void mma_tf32(float4& d, u32 a0, u32 a1, u32 a2, u32 a3,
                                         u32 b0, u32 b1) {
    asm("mma.sync.aligned.m16n8k8.row.col.f32.tf32.tf32.f32 "
        "{%0,%1,%2,%3}, {%4,%5,%6,%7}, {%8,%9}, {%0,%1,%2,%3};"
        : "+f"(d.x), "+f"(d.y), "+f"(d.z), "+f"(d.w)
        : "r"(a0), "r"(a1), "r"(a2), "r"(a3), "r"(b0), "r"(b1));
}

// split-2 gate permutation:
//   n' = rank*512 + w*64 + nt*8 + c,  nt = g*4+gate? NO: gate = nt&3, g = nt>>2
//   orig = gate*256 + (rank*128 + w*16 + g*8 + c)

// ---------------- fused enc prep: Whh fragments + Wih/bias permutation ----------------
__global__ void prep_enc(const float* __restrict__ Wh, const float* __restrict__ Wi,
                         const float* __restrict__ bi, const float* __restrict__ bh,
                         u32* __restrict__ wf, float* __restrict__ Wp,
                         float* __restrict__ bp, int K) {
    int bx = blockIdx.x;
    if (bx < 1024) {
        // wf[t], t = (((p*16 + slot)*8 + nt)*32 + lane)*4 + reg ; slot = rank*8+w
        int t = bx * 256 + threadIdx.x;
        int reg = t & 3, lane = (t >> 2) & 31, nt = (t >> 7) & 7, s = (t >> 10) & 15, p = t >> 14;
        int gid = lane >> 2, tig = lane & 3;
        int rank = s >> 3, w = s & 7, gate = nt & 3, g = nt >> 2;
        int orig_n = gate * 256 + rank * 128 + w * 16 + g * 8 + gid;
        int k = 16 * p + 8 * (reg >> 1) + tig + 4 * (reg & 1);
        wf[t] = cvt_tf32(Wh[orig_n * Hc + k]);
    } else {
        int np = bx - 1024;
        int rank = np >> 9, w = (np >> 6) & 7, nt = (np >> 3) & 7, c = np & 7;
        int gate = nt & 3, g = nt >> 2;
        int orig = gate * 256 + rank * 128 + w * 16 + g * 8 + c;
        for (int k = threadIdx.x; k < K; k += blockDim.x)
            Wp[(size_t)np * K + k] = Wi[(size_t)orig * K + k];
        if (threadIdx.x == 0) bp[np] = bi[orig] + bh[orig];
    }
}

// ---------------- dec weight prep ----------------
__global__ void prep_w4(const float* __restrict__ src, float* __restrict__ dst, int H) {
    __shared__ float tile[32][33];
    int g = blockIdx.z;
    int k0 = blockIdx.x * 32, j0 = blockIdx.y * 32;
    int x = threadIdx.x, y = threadIdx.y;
#pragma unroll
    for (int i = 0; i < 32; i += 8)
        tile[y + i][x] = src[(size_t)(g * H + j0 + y + i) * H + k0 + x];
    __syncthreads();
#pragma unroll
    for (int i = 0; i < 32; i += 8)
        dst[((size_t)(k0 + y + i) * H + (j0 + x)) * 4 + g] = tile[x][y + i];
}

// ---------------- fp32 GEMM (BM=128, BN=64), relu ----------------
template <bool RELU, bool HASB2>
__global__ void __launch_bounds__(256) gemm64(
    const float* __restrict__ A, const float* __restrict__ W,
    const float* __restrict__ b1, const float* __restrict__ b2,
    float* __restrict__ C, int Mdim, int Ndim, int Kdim) {
    constexpr int BK = 16;
    __shared__ float As[BK][128];
    __shared__ float Ws[BK][64];

    const int tid = threadIdx.x;
    const int tx = tid & 15;
    const int ty = tid >> 4;
    const size_t bm = (size_t)blockIdx.x * 128;
    const size_t bn = (size_t)blockIdx.y * 64;
    const int lr = tid >> 2;
    const int lk = (tid & 3) << 2;

    ull acc[4][4];
#pragma unroll
    for (int i = 0; i < 4; i++)
#pragma unroll
        for (int j = 0; j < 4; j++) acc[i][j] = 0ull;

    const float* Ap0 = A + (bm + lr) * (size_t)Kdim + lk;
    const float* Ap1 = A + (bm + lr + 64) * (size_t)Kdim + lk;
    const float* Wpt = W + (bn + lr) * (size_t)Kdim + lk;

    for (int k0 = 0; k0 < Kdim; k0 += BK) {
        float4 av0 = *(const float4*)(Ap0 + k0);
        float4 av1 = *(const float4*)(Ap1 + k0);
        float4 wv  = *(const float4*)(Wpt + k0);
        __syncthreads();
        As[lk + 0][lr] = av0.x; As[lk + 1][lr] = av0.y;
        As[lk + 2][lr] = av0.z; As[lk + 3][lr] = av0.w;
        As[lk + 0][lr + 64] = av1.x; As[lk + 1][lr + 64] = av1.y;
        As[lk + 2][lr + 64] = av1.z; As[lk + 3][lr + 64] = av1.w;
        Ws[lk + 0][lr] = wv.x; Ws[lk + 1][lr] = wv.y;
        Ws[lk + 2][lr] = wv.z; Ws[lk + 3][lr] = wv.w;
        __syncthreads();
#pragma unroll
        for (int kk = 0; kk < BK; kk++) {
            float4 a0 = *(const float4*)&As[kk][ty * 8];
            float4 a1 = *(const float4*)&As[kk][ty * 8 + 4];
            float4 w4 = *(const float4*)&Ws[kk][tx * 4];
            ull a2[4] = {pack2f(a0.x, a0.y), pack2f(a0.z, a0.w),
                         pack2f(a1.x, a1.y), pack2f(a1.z, a1.w)};
            ull w2[4] = {pack2f(w4.x, w4.x), pack2f(w4.y, w4.y),
                         pack2f(w4.z, w4.z), pack2f(w4.w, w4.w)};
#pragma unroll
            for (int i = 0; i < 4; i++)
#pragma unroll
                for (int j = 0; j < 4; j++)
                    acc[i][j] = fma2f(a2[i], w2[j], acc[i][j]);
        }
    }

    float bias[4];
#pragma unroll
    for (int j = 0; j < 4; j++) {
        bias[j] = b1[bn + tx * 4 + j];
        if (HASB2) bias[j] += b2[bn + tx * 4 + j];
    }
#pragma unroll
    for (int i = 0; i < 4; i++) {
        float2 v0 = unpack2f(acc[i][0]);
        float2 v1 = unpack2f(acc[i][1]);
        float2 v2 = unpack2f(acc[i][2]);
        float2 v3 = unpack2f(acc[i][3]);
        float4 o0 = make_float4(v0.x + bias[0], v1.x + bias[1], v2.x + bias[2], v3.x + bias[3]);
        float4 o1 = make_float4(v0.y + bias[0], v1.y + bias[1], v2.y + bias[2], v3.y + bias[3]);
        if (RELU) {
            o0.x = fmaxf(o0.x, 0.f); o0.y = fmaxf(o0.y, 0.f);
            o0.z = fmaxf(o0.z, 0.f); o0.w = fmaxf(o0.w, 0.f);
            o1.x = fmaxf(o1.x, 0.f); o1.y = fmaxf(o1.y, 0.f);
            o1.z = fmaxf(o1.z, 0.f); o1.w = fmaxf(o1.w, 0.f);
        }
        size_t r0 = bm + ty * 8 + 2 * i;
        *(float4*)&C[r0 * Ndim + bn + tx * 4]       = o0;
        *(float4*)&C[(r0 + 1) * Ndim + bn + tx * 4] = o1;
    }
}

// ---------------- tf32 GEMM (BM=128, BN=128, BK=16), double-buffered ----------------
template <bool HASB2>
__global__ void __launch_bounds__(256) gemm_tf32(
    const float* __restrict__ A, const float* __restrict__ W,
    const float* __restrict__ b1, const float* __restrict__ b2,
    float* __restrict__ C, int Mdim, int Ndim, int Kdim) {
    __shared__ u32 As[2][2048];
    __shared__ u32 Bs[2][2048];

    const int tid = threadIdx.x;
    const int lane = tid & 31;
    const int wid = tid >> 5;
    const int wm = wid & 3;
    const int wn = wid >> 2;
    const int gid = lane >> 2;
    const int tig = lane & 3;
    const size_t bm = (size_t)blockIdx.x * 128;
    const size_t bn = (size_t)blockIdx.y * 128;

    float4 acc[2][8];
#pragma unroll
    for (int mt = 0; mt < 2; mt++)
#pragma unroll
        for (int nt = 0; nt < 8; nt++) acc[mt][nt] = make_float4(0.f, 0.f, 0.f, 0.f);

    int baseA[2], baseB[2];
    const float* ApG[2];
    const float* WpG[2];
#pragma unroll
    for (int i = 0; i < 2; i++) {
        int fidx = tid + 256 * i;
        int row = fidx >> 2, c4 = fidx & 3;
        int k8 = c4 >> 1, regK = c4 & 1;
        int mtile = row >> 4, r = row & 15;
        baseA[i] = (((k8 * 8 + mtile) * 32 + (r & 7) * 4)) * 4 + (r >> 3) + 2 * regK;
        ApG[i] = A + (bm + row) * (size_t)Kdim + c4 * 4;
        int ntile = row >> 3, ngid = row & 7;
        baseB[i] = (((k8 * 16 + ntile) * 32 + ngid * 4)) * 2 + regK;
        WpG[i] = W + (bn + row) * (size_t)Kdim + c4 * 4;
    }

    float4 av[2], wv[2];

#define TF32_LOAD(K0)                                  \
    av[0] = *(const float4*)(ApG[0] + (K0));           \
    av[1] = *(const float4*)(ApG[1] + (K0));           \
    wv[0] = *(const float4*)(WpG[0] + (K0));           \
    wv[1] = *(const float4*)(WpG[1] + (K0));

#define TF32_STORE(BUF)                                                        \
    _Pragma("unroll")                                                          \
    for (int i = 0; i < 2; i++) {                                              \
        As[BUF][baseA[i] + 0]  = cvt_tf32(av[i].x);                            \
        As[BUF][baseA[i] + 4]  = cvt_tf32(av[i].y);                            \
        As[BUF][baseA[i] + 8]  = cvt_tf32(av[i].z);                            \
        As[BUF][baseA[i] + 12] = cvt_tf32(av[i].w);                            \
        Bs[BUF][baseB[i] + 0]  = cvt_tf32(wv[i].x);                            \
        Bs[BUF][baseB[i] + 2]  = cvt_tf32(wv[i].y);                            \
        Bs[BUF][baseB[i] + 4]  = cvt_tf32(wv[i].z);                            \
        Bs[BUF][baseB[i] + 6]  = cvt_tf32(wv[i].w);                            \
    }

#define TF32_COMP(BUF)                                                             \
    _Pragma("unroll")                                                              \
    for (int k8 = 0; k8 < 2; k8++) {                                               \
        uint4 af[2]; uint2 bf[8];                                                  \
        _Pragma("unroll")                                                          \
        for (int mt = 0; mt < 2; mt++)                                             \
            af[mt] = *(const uint4*)&As[BUF][((k8 * 8 + wm * 2 + mt) * 32 + lane) * 4]; \
        _Pragma("unroll")                                                          \
        for (int nt = 0; nt < 8; nt++)                                             \
            bf[nt] = *(const uint2*)&Bs[BUF][((k8 * 16 + wn * 8 + nt) * 32 + lane) * 2]; \
        _Pragma("unroll")                                                          \
        for (int mt = 0; mt < 2; mt++)                                             \
            _Pragma("unroll")                                                      \
            for (int nt = 0; nt < 8; nt++)                                         \
                mma_tf32(acc[mt][nt], af[mt].x, af[mt].y, af[mt].z, af[mt].w,      \
                         bf[nt].x, bf[nt].y);                                      \
    }

    TF32_LOAD(0);
    TF32_STORE(0);
    __syncthreads();
    const int nb = Kdim >> 4;
#pragma unroll 1
    for (int it = 1; it < nb; it++) {
        TF32_LOAD(it * 16);
        TF32_COMP((it - 1) & 1);
        TF32_STORE(it & 1);
        __syncthreads();
    }
    TF32_COMP((nb - 1) & 1);

#pragma unroll
    for (int mt = 0; mt < 2; mt++) {
        int row0 = (int)bm + wm * 32 + mt * 16 + gid;
#pragma unroll
        for (int nt = 0; nt < 8; nt++) {
            int col = (int)bn + wn * 64 + nt * 8 + 2 * tig;
            float bb0 = b1[col], bb1 = b1[col + 1];
            if (HASB2) { bb0 += b2[col]; bb1 += b2[col + 1]; }
            *(float2*)&C[(size_t)row0 * Ndim + col] =
                make_float2(acc[mt][nt].x + bb0, acc[mt][nt].y + bb1);
            *(float2*)&C[(size_t)(row0 + 8) * Ndim + col] =
                make_float2(acc[mt][nt].z + bb0, acc[mt][nt].w + bb1);
        }
    }
}

// ---------------- cluster-2 tensor-core encoder LSTM ----------------
// 128 CTAs = 64 clusters x 2. Each CTA: 16 batch rows x 512 gate cols.
// smem: hs[2][6144] u32 (48 KB) + wc cache (NC p-slices, 32 KB each)
#define HS_WORDS 6144
#define NCC 5
#define ENC2_WC_U4 (NCC * 2048)

__global__ void __launch_bounds__(256, 1) __cluster_dims__(2, 1, 1)
lstm_enc_tc2(const uint4* __restrict__ wf, const float* __restrict__ xg,
             float* __restrict__ h_all, float* __restrict__ z_last) {
    extern __shared__ __align__(16) u32 sm[];
    u32* hs0 = sm;
    u32* hs1 = sm + HS_WORDS;
    uint4* wc = (uint4*)(sm + 2 * HS_WORDS);

    const int tid = threadIdx.x, lane = tid & 31, w = tid >> 5;
    const int gid = lane >> 2, tig = lane & 3;
    u32 rank;
    asm("mov.u32 %0, %%cluster_ctarank;" : "=r"(rank));
    const int b0 = (blockIdx.x >> 1) * 16;
    const int slot = (int)rank * 8 + w;

    u32 smb;
    asm("{ .reg .u64 t; cvta.to.shared.u64 t, %1; cvt.u32.u64 %0, t; }"
        : "=r"(smb) : "l"((void*)sm));

    // cache first NCC p-slices of this CTA's weight slice
    for (int i = tid; i < ENC2_WC_U4; i += 256) {
        int p = i >> 11, w2 = (i >> 8) & 7;
        wc[i] = wf[(p * 16 + (int)rank * 8 + w2) * 256 + (i & 255)];
    }
    for (int i = tid; i < HS_WORDS; i += 256) hs0[i] = 0;
    asm volatile("barrier.cluster.arrive.aligned;" ::: "memory");
    asm volatile("barrier.cluster.wait.aligned;" ::: "memory");

    float4 acc[8];
    float cst[8];
#pragma unroll
    for (int i = 0; i < 8; i++) cst[i] = 0.f;

    const size_t ro0 = ((size_t)(b0 + gid) * Tc) * Gc;
    const size_t ro1 = ((size_t)(b0 + gid + 8) * Tc) * Gc;
    const int ncol = (int)rank * 512 + w * 64 + 2 * tig;
    int cur = 0;

#define LOADB2(dst, P)                                                          \
    do {                                                                        \
        if ((P) < NCC) {                                                        \
            _Pragma("unroll")                                                   \
            for (int i_ = 0; i_ < 8; i_++)                                      \
                dst[i_] = wc[(P) * 2048 + w * 256 + i_ * 32 + lane];            \
        } else {                                                                \
            _Pragma("unroll")                                                   \
            for (int i_ = 0; i_ < 8; i_++)                                      \
                dst[i_] = wf[((P) * 16 + slot) * 256 + i_ * 32 + lane];         \
        }                                                                       \
    } while (0)

#define LDA2(K0)                                   \
    a[0] = hc[((K0) + tig) * 24 + gid];            \
    a[1] = hc[((K0) + tig) * 24 + gid + 8];        \
    a[2] = hc[((K0) + tig + 4) * 24 + gid];        \
    a[3] = hc[((K0) + tig + 4) * 24 + gid + 8];    \
    a[4] = hc[((K0) + 8 + tig) * 24 + gid];        \
    a[5] = hc[((K0) + 8 + tig) * 24 + gid + 8];    \
    a[6] = hc[((K0) + 8 + tig + 4) * 24 + gid];    \
    a[7] = hc[((K0) + 8 + tig + 4) * 24 + gid + 8];

#define DOMMA2(B)                                                           \
    _Pragma("unroll")                                                       \
    for (int nt = 0; nt < 8; nt++) {                                        \
        mma_tf32(acc[nt], a[0], a[1], a[2], a[3], B[nt].x, B[nt].y);        \
        mma_tf32(acc[nt], a[4], a[5], a[6], a[7], B[nt].z, B[nt].w);        \
    }

#pragma unroll 1
    for (int t = 0; t < Tc; t++) {
        const u32* hc = cur ? hs1 : hs0;
        u32* hn = cur ? hs0 : hs1;
        const u32 hn_byte = (cur ? 0u : (u32)HS_WORDS) * 4u;

        const float* xr0 = xg + ro0 + (size_t)t * Gc + ncol;
        const float* xr1 = xg + ro1 + (size_t)t * Gc + ncol;
#pragma unroll
        for (int nt = 0; nt < 8; nt++) {
            float2 lo = *(const float2*)(xr0 + nt * 8);
            float2 hi = *(const float2*)(xr1 + nt * 8);
            acc[nt] = make_float4(lo.x, lo.y, hi.x, hi.y);
        }

        uint4 bA[8], bB[8];
        LOADB2(bA, 0);
#pragma unroll
        for (int pp = 0; pp < 8; pp++) {
            u32 a[8];
            LDA2(pp * 32);
            LOADB2(bB, 2 * pp + 1);
            DOMMA2(bA);
            LDA2(pp * 32 + 16);
            if (pp < 7) LOADB2(bA, 2 * pp + 2);
            DOMMA2(bB);
        }

        // epilogue: g in {0,1}: tiles 4g..4g+3 = i,f,g,o
#pragma unroll
        for (int g = 0; g < 2; g++) {
            float4 I = acc[4 * g + 0], F = acc[4 * g + 1];
            float4 G = acc[4 * g + 2], O = acc[4 * g + 3];
            int j0 = (int)rank * 128 + w * 16 + g * 8 + 2 * tig;
            float h[4];
            {
                float cc = sigf(F.x) * cst[g * 4 + 0] + sigf(I.x) * tanh_(G.x);
                cst[g * 4 + 0] = cc; h[0] = sigf(O.x) * tanh_(cc);
            }
            {
                float cc = sigf(F.y) * cst[g * 4 + 1] + sigf(I.y) * tanh_(G.y);
                cst[g * 4 + 1] = cc; h[1] = sigf(O.y) * tanh_(cc);
            }
            {
                float cc = sigf(F.z) * cst[g * 4 + 2] + sigf(I.z) * tanh_(G.z);
                cst[g * 4 + 2] = cc; h[2] = sigf(O.z) * tanh_(cc);
            }
            {
                float cc = sigf(F.w) * cst[g * 4 + 3] + sigf(I.w) * tanh_(G.w);
                cst[g * 4 + 3] = cc; h[3] = sigf(O.w) * tanh_(cc);
            }
            u32 v0 = cvt_tf32(h[0]), v1 = cvt_tf32(h[1]);
            u32 v2 = cvt_tf32(h[2]), v3 = cvt_tf32(h[3]);
            // local h
            hn[j0 * 24 + gid]           = v0;
            hn[(j0 + 1) * 24 + gid]     = v1;
            hn[j0 * 24 + gid + 8]       = v2;
            hn[(j0 + 1) * 24 + gid + 8] = v3;
            // remote h to peer CTA (same offsets)
            u32 la = smb + hn_byte + (u32)(j0 * 24 + gid) * 4u;
            u32 ra;
            asm("mapa.shared::cluster.u32 %0, %1, %2;" : "=r"(ra) : "r"(la), "r"(rank ^ 1u));
            asm volatile("st.shared::cluster.u32 [%0], %1;" :: "r"(ra), "r"(v0));
            asm volatile("st.shared::cluster.u32 [%0+96], %1;" :: "r"(ra), "r"(v1));
            asm volatile("st.shared::cluster.u32 [%0+32], %1;" :: "r"(ra), "r"(v2));
            asm volatile("st.shared::cluster.u32 [%0+128], %1;" :: "r"(ra), "r"(v3));

            if (h_all) {
                *(float2*)&h_all[((size_t)(b0 + gid) * Tc + t) * Hc + j0] =
                    make_float2(h[0], h[1]);
                *(float2*)&h_all[((size_t)(b0 + gid + 8) * Tc + t) * Hc + j0] =
                    make_float2(h[2], h[3]);
            }
            if (z_last && t == Tc - 1) {
                *(float2*)&z_last[(size_t)(b0 + gid) * Hc + j0] = make_float2(h[0], h[1]);
                *(float2*)&z_last[(size_t)(b0 + gid + 8) * Hc + j0] = make_float2(h[2], h[3]);
            }
        }
        asm volatile("barrier.cluster.arrive.aligned;" ::: "memory");
        asm volatile("barrier.cluster.wait.aligned;" ::: "memory");
        cur ^= 1;
    }
}

// ---------------- decoder LSTM (H=64), all weights in smem ----------------
__global__ void __launch_bounds__(256) lstm_dec(
    const float4* __restrict__ w4, const float* __restrict__ xg,
    float* __restrict__ h_out, int per_t) {
    extern __shared__ __align__(16) char smraw[];
    float2 (*shh)[Mc][4] = (float2(*)[Mc][4])smraw;
    float4* wc = (float4*)(smraw + 2 * Mc * 4 * sizeof(float2));

    const int b0 = blockIdx.x * 8;
    const int j = threadIdx.x & 63;
    const int rg = threadIdx.x >> 6;

    for (int idx = threadIdx.x; idx < Mc * Mc; idx += 256)
        wc[idx] = w4[idx];
    shh[0][j][rg] = make_float2(0.f, 0.f);
    __syncthreads();

    float c0 = 0.f, c1 = 0.f;
    ull base[4];
    if (!per_t) {
#pragma unroll
        for (int g = 0; g < 4; g++)
            base[g] = pack2f(xg[(size_t)(b0 + rg) * GMc + g * Mc + j],
                             xg[(size_t)(b0 + rg + 4) * GMc + g * Mc + j]);
    }

    int cur = 0;
#pragma unroll 1
    for (int t = 0; t < Tc; t++) {
        ull acc[4];
        if (per_t) {
#pragma unroll
            for (int g = 0; g < 4; g++)
                acc[g] = pack2f(xg[((size_t)(b0 + rg) * Tc + t) * GMc + g * Mc + j],
                                xg[((size_t)(b0 + rg + 4) * Tc + t) * GMc + g * Mc + j]);
        } else {
#pragma unroll
            for (int g = 0; g < 4; g++) acc[g] = base[g];
        }

        const float2(*shc)[4] = shh[cur];
#pragma unroll 1
        for (int k = 0; k < Mc; k += 16) {
#pragma unroll
            for (int u = 0; u < 16; u++) {
                float4 wv = wc[(k + u) * Mc + j];
                ull h2 = *(const ull*)&shc[k + u][rg];
                acc[0] = fma2f(h2, pack2f(wv.x, wv.x), acc[0]);
                acc[1] = fma2f(h2, pack2f(wv.y, wv.y), acc[1]);
                acc[2] = fma2f(h2, pack2f(wv.z, wv.z), acc[2]);
                acc[3] = fma2f(h2, pack2f(wv.w, wv.w), acc[3]);
            }
        }

        float2 iv = unpack2f(acc[0]);
        float2 fv = unpack2f(acc[1]);
        float2 gv = unpack2f(acc[2]);
        float2 ov = unpack2f(acc[3]);
        c0 = sigf(fv.x) * c0 + sigf(iv.x) * tanh_(gv.x);
        float h0 = sigf(ov.x) * tanh_(c0);
        c1 = sigf(fv.y) * c1 + sigf(iv.y) * tanh_(gv.y);
        float h1 = sigf(ov.y) * tanh_(c1);

        int nxt = cur ^ 1;
        shh[nxt][j][rg] = make_float2(h0, h1);
        h_out[((size_t)(b0 + rg) * Tc + t) * Mc + j]     = h0;
        h_out[((size_t)(b0 + rg + 4) * Tc + t) * Mc + j] = h1;
        __syncthreads();
        cur = nxt;
    }
}

// ---------------- launch ----------------
extern "C" void kernel_launch(void* const* d_in, const int* in_sizes, int n_in,
                              void* d_out, int out_size) {
    const float* x    = (const float*)d_in[0];
    const float* in_W = (const float*)d_in[1];
    const float* in_b = (const float*)d_in[2];
    const float* eW0i = (const float*)d_in[3];
    const float* eW0h = (const float*)d_in[4];
    const float* eb0i = (const float*)d_in[5];
    const float* eb0h = (const float*)d_in[6];
    const float* eW1i = (const float*)d_in[7];
    const float* eW1h = (const float*)d_in[8];
    const float* eb1i = (const float*)d_in[9];
    const float* eb1h = (const float*)d_in[10];
    const float* dW0i = (const float*)d_in[11];
    const float* dW0h = (const float*)d_in[12];
    const float* db0i = (const float*)d_in[13];
    const float* db0h = (const float*)d_in[14];
    const float* dW1i = (const float*)d_in[15];
    const float* dW1h = (const float*)d_in[16];
    const float* db1i = (const float*)d_in[17];
    const float* db1h = (const float*)d_in[18];
    const float* outW = (const float*)d_in[19];
    const float* outb = (const float*)d_in[20];
    float* out = (float*)d_out;

    float *xg, *mid, *bufA, *bufB, *z, *xgd0, *wp, *bp, *w4d0, *w4d1;
    u32 *wf0, *wf1;
    cudaGetSymbolAddress((void**)&xg,   g_xg);
    cudaGetSymbolAddress((void**)&mid,  g_mid);
    cudaGetSymbolAddress((void**)&bufA, g_bufA);
    cudaGetSymbolAddress((void**)&bufB, g_bufB);
    cudaGetSymbolAddress((void**)&z,    g_z);
    cudaGetSymbolAddress((void**)&xgd0, g_xgd0);
    cudaGetSymbolAddress((void**)&wf0,  g_wf0);
    cudaGetSymbolAddress((void**)&wf1,  g_wf1);
    cudaGetSymbolAddress((void**)&wp,   g_wp);
    cudaGetSymbolAddress((void**)&bp,   g_bp);
    cudaGetSymbolAddress((void**)&w4d0, g_w4d0);
    cudaGetSymbolAddress((void**)&w4d1, g_w4d1);

    const int MT = Bc * Tc;

    const int ENC_SMEM = 2 * HS_WORDS * 4 + ENC2_WC_U4 * 16;   // 48 KB + 160 KB
    const int DEC_SMEM = 2 * Mc * 4 * sizeof(float2) + Mc * Mc * sizeof(float4);
    static int configured = 0;
    if (!configured) {
        cudaFuncSetAttribute(lstm_enc_tc2, cudaFuncAttributeMaxDynamicSharedMemorySize, ENC_SMEM);
        cudaFuncSetAttribute(lstm_dec, cudaFuncAttributeMaxDynamicSharedMemorySize, DEC_SMEM);
        configured = 1;
    }

    // 1) enc0 prep (wf0 + wp/bp)
    prep_enc<<<2048, 256>>>(eW0h, eW0i, eb0i, eb0h, wf0, wp, bp, Mc);
    // 2) h0 = relu(x @ in_W^T + in_b)
    gemm64<true, false><<<dim3(MT / 128, 1), 256>>>(x, in_W, in_b, nullptr, bufA, MT, Mc, Dc);
    // 3) xg0 (permuted) = h0 @ wp^T + bp
    gemm_tf32<false><<<dim3(MT / 128, Gc / 128), 256>>>(bufA, wp, bp, nullptr, xg, MT, Gc, Mc);
    // 4) enc0 recurrence -> h_enc0   (ncu profiles launch #4)
    lstm_enc_tc2<<<128, 256, ENC_SMEM>>>((const uint4*)wf0, xg, mid, nullptr);
    // 5) enc1 prep
    prep_enc<<<2048, 256>>>(eW1h, eW1i, eb1i, eb1h, wf1, wp, bp, Hc);
    // 6) xg1 (permuted) = h_enc0 @ wp^T + bp
    gemm_tf32<false><<<dim3(MT / 128, Gc / 128), 256>>>(mid, wp, bp, nullptr, xg, MT, Gc, Hc);
    // 7) enc1 recurrence -> z
    lstm_enc_tc2<<<128, 256, ENC_SMEM>>>((const uint4*)wf1, xg, nullptr, z);
    // 8-9) dec preps
    prep_w4<<<dim3(2, 2, 4), dim3(32, 8)>>>(dW0h, w4d0, Mc);
    prep_w4<<<dim3(2, 2, 4), dim3(32, 8)>>>(dW1h, w4d1, Mc);
    // 10) xg_dec0 = z @ dW0i^T + db0i + db0h (t-const)
    gemm_tf32<true><<<dim3(Bc / 128, GMc / 128), 256>>>(z, dW0i, db0i, db0h, xgd0, Bc, GMc, Hc);
    // 11) dec0 -> d0
    lstm_dec<<<Bc / 8, 256, DEC_SMEM>>>((const float4*)w4d0, xgd0, bufA, 0);
    // 12) xg_dec1 = d0 @ dW1i^T + db1i + db1h
    gemm_tf32<true><<<dim3(MT / 128, GMc / 128), 256>>>(bufA, dW1i, db1i, db1h, mid, MT, GMc, Mc);
    // 13) dec1 -> d1
    lstm_dec<<<Bc / 8, 256, DEC_SMEM>>>((const float4*)w4d1, mid, bufB, 1);
    // 14) out = d1 @ out_W^T + out_b
    gemm_tf32<false><<<dim3(MT / 128, Dc / 128), 256>>>(bufB, outW, outb, nullptr, out, MT, Dc, Mc);
}

// round 7
// speedup vs baseline: 6.0377x; 1.2386x over previous
#include <cuda_runtime.h>
#include <cuda_fp16.h>

// ---------------- problem dims ----------------
#define Bc   1024
#define Tc   100
#define Dc   256
#define Hc   256
#define Gc   1024
#define Mc   64
#define GMc  256

typedef unsigned long long ull;
typedef unsigned int u32;

// ---------------- device scratch ----------------
__device__ float g_xg  [(size_t)Bc * Tc * Gc];
__device__ float g_mid [(size_t)Bc * Tc * Hc];
__device__ float g_bufA[(size_t)Bc * Tc * Mc];
__device__ float g_bufB[(size_t)Bc * Tc * Mc];
__device__ float g_z   [Bc * Hc];
__device__ float g_xgd0[Bc * GMc];
__device__ uint4 g_wh0 [32768];            // enc0 Whh fp16 B-fragments (512 KB)
__device__ uint4 g_wh1 [32768];            // enc1
__device__ float g_wp  [Gc * Hc];
__device__ float g_bp  [Gc];
__device__ float g_w4d0[(Mc * Mc + 1024) * 4];
__device__ float g_w4d1[(Mc * Mc + 1024) * 4];

// ---------------- helpers ----------------
__device__ __forceinline__ ull pack2f(float x, float y) {
    ull r; asm("mov.b64 %0, {%1, %2};" : "=l"(r) : "f"(x), "f"(y)); return r;
}
__device__ __forceinline__ float2 unpack2f(ull v) {
    float2 r; asm("mov.b64 {%0, %1}, %2;" : "=f"(r.x), "=f"(r.y) : "l"(v)); return r;
}
__device__ __forceinline__ ull fma2f(ull a, ull b, ull c) {
    ull d; asm("fma.rn.f32x2 %0, %1, %2, %3;" : "=l"(d) : "l"(a), "l"(b), "l"(c)); return d;
}
__device__ __forceinline__ float sigf(float x) {
    return __fdividef(1.0f, 1.0f + __expf(-x));
}
__device__ __forceinline__ float tanh_(float x) {
    return 1.0f - __fdividef(2.0f, __expf(2.0f * x) + 1.0f);
}
__device__ __forceinline__ u32 cvt_tf32(float x) {
    u32 r; asm("cvt.rna.tf32.f32 %0, %1;" : "=r"(r) : "f"(x)); return r;
}
__device__ __forceinline__ void mma_tf32(float4& d, u32 a0, u32 a1, u32 a2, u32 a3,
                                         u32 b0, u32 b1) {
    asm("mma.sync.aligned.m16n8k8.row.col.f32.tf32.tf32.f32 "
        "{%0,%1,%2,%3}, {%4,%5,%6,%7}, {%8,%9}, {%0,%1,%2,%3};"
        : "+f"(d.x), "+f"(d.y), "+f"(d.z), "+f"(d.w)
        : "r"(a0), "r"(a1), "r"(a2), "r"(a3), "r"(b0), "r"(b1));
}
__device__ __forceinline__ void mma_f16(float4& d, u32 a0, u32 a1, u32 a2, u32 a3,
                                        u32 b0, u32 b1) {
    asm("mma.sync.aligned.m16n8k16.row.col.f32.f16.f16.f32 "
        "{%0,%1,%2,%3}, {%4,%5,%6,%7}, {%8,%9}, {%0,%1,%2,%3};"
        : "+f"(d.x), "+f"(d.y), "+f"(d.z), "+f"(d.w)
        : "r"(a0), "r"(a1), "r"(a2), "r"(a3), "r"(b0), "r"(b1));
}
__device__ __forceinline__ u32 packh2(float a, float b) {
    __half2 h = __floats2half2_rn(a, b);
    return *(u32*)&h;
}

// gate-col permutation (cluster-2): n' = rank*512 + w*64 + nt*8 + c
//   gate = nt&3, g = nt>>2;  orig = gate*256 + rank*128 + w*16 + g*8 + c

// ---------------- enc prep: Whh -> fp16 B-fragments, Wih/bias permute ----------------
__global__ void prep_enc16(const float* __restrict__ Wh, const float* __restrict__ Wi,
                           const float* __restrict__ bi, const float* __restrict__ bh,
                           uint2* __restrict__ wh, float* __restrict__ Wp,
                           float* __restrict__ bp, int K) {
    int bx = blockIdx.x;
    if (bx < 256) {
        // t2 = (((c*2+rank)*8 + w)*8 + nt)*32 + lane
        int t2 = bx * 256 + threadIdx.x;
        int lane = t2 & 31, nt = (t2 >> 5) & 7, w = (t2 >> 8) & 7;
        int rank = (t2 >> 11) & 1, c = t2 >> 12;
        int gid = lane >> 2, tt = lane & 3;
        int gate = nt & 3, g = nt >> 2;
        int n = gate * 256 + rank * 128 + w * 16 + g * 8 + gid;
        int k0 = 16 * c + 2 * tt;
        uint2 v;
        v.x = packh2(Wh[(size_t)n * Hc + k0],     Wh[(size_t)n * Hc + k0 + 1]);
        v.y = packh2(Wh[(size_t)n * Hc + k0 + 8], Wh[(size_t)n * Hc + k0 + 9]);
        wh[t2] = v;
    } else {
        int np = bx - 256;
        int rank = np >> 9, w = (np >> 6) & 7, nt = (np >> 3) & 7, c = np & 7;
        int gate = nt & 3, g = nt >> 2;
        int orig = gate * 256 + rank * 128 + w * 16 + g * 8 + c;
        for (int k = threadIdx.x; k < K; k += blockDim.x)
            Wp[(size_t)np * K + k] = Wi[(size_t)orig * K + k];
        if (threadIdx.x == 0) bp[np] = bi[orig] + bh[orig];
    }
}

// ---------------- dec weight prep ----------------
__global__ void prep_w4(const float* __restrict__ src, float* __restrict__ dst, int H) {
    __shared__ float tile[32][33];
    int g = blockIdx.z;
    int k0 = blockIdx.x * 32, j0 = blockIdx.y * 32;
    int x = threadIdx.x, y = threadIdx.y;
#pragma unroll
    for (int i = 0; i < 32; i += 8)
        tile[y + i][x] = src[(size_t)(g * H + j0 + y + i) * H + k0 + x];
    __syncthreads();
#pragma unroll
    for (int i = 0; i < 32; i += 8)
        dst[((size_t)(k0 + y + i) * H + (j0 + x)) * 4 + g] = tile[x][y + i];
}

// ---------------- fp32 GEMM (BM=128, BN=64), relu ----------------
template <bool RELU, bool HASB2>
__global__ void __launch_bounds__(256) gemm64(
    const float* __restrict__ A, const float* __restrict__ W,
    const float* __restrict__ b1, const float* __restrict__ b2,
    float* __restrict__ C, int Mdim, int Ndim, int Kdim) {
    constexpr int BK = 16;
    __shared__ float As[BK][128];
    __shared__ float Ws[BK][64];

    const int tid = threadIdx.x;
    const int tx = tid & 15;
    const int ty = tid >> 4;
    const size_t bm = (size_t)blockIdx.x * 128;
    const size_t bn = (size_t)blockIdx.y * 64;
    const int lr = tid >> 2;
    const int lk = (tid & 3) << 2;

    ull acc[4][4];
#pragma unroll
    for (int i = 0; i < 4; i++)
#pragma unroll
        for (int j = 0; j < 4; j++) acc[i][j] = 0ull;

    const float* Ap0 = A + (bm + lr) * (size_t)Kdim + lk;
    const float* Ap1 = A + (bm + lr + 64) * (size_t)Kdim + lk;
    const float* Wpt = W + (bn + lr) * (size_t)Kdim + lk;

    for (int k0 = 0; k0 < Kdim; k0 += BK) {
        float4 av0 = *(const float4*)(Ap0 + k0);
        float4 av1 = *(const float4*)(Ap1 + k0);
        float4 wv  = *(const float4*)(Wpt + k0);
        __syncthreads();
        As[lk + 0][lr] = av0.x; As[lk + 1][lr] = av0.y;
        As[lk + 2][lr] = av0.z; As[lk + 3][lr] = av0.w;
        As[lk + 0][lr + 64] = av1.x; As[lk + 1][lr + 64] = av1.y;
        As[lk + 2][lr + 64] = av1.z; As[lk + 3][lr + 64] = av1.w;
        Ws[lk + 0][lr] = wv.x; Ws[lk + 1][lr] = wv.y;
        Ws[lk + 2][lr] = wv.z; Ws[lk + 3][lr] = wv.w;
        __syncthreads();
#pragma unroll
        for (int kk = 0; kk < BK; kk++) {
            float4 a0 = *(const float4*)&As[kk][ty * 8];
            float4 a1 = *(const float4*)&As[kk][ty * 8 + 4];
            float4 w4 = *(const float4*)&Ws[kk][tx * 4];
            ull a2[4] = {pack2f(a0.x, a0.y), pack2f(a0.z, a0.w),
                         pack2f(a1.x, a1.y), pack2f(a1.z, a1.w)};
            ull w2[4] = {pack2f(w4.x, w4.x), pack2f(w4.y, w4.y),
                         pack2f(w4.z, w4.z), pack2f(w4.w, w4.w)};
#pragma unroll
            for (int i = 0; i < 4; i++)
#pragma unroll
                for (int j = 0; j < 4; j++)
                    acc[i][j] = fma2f(a2[i], w2[j], acc[i][j]);
        }
    }

    float bias[4];
#pragma unroll
    for (int j = 0; j < 4; j++) {
        bias[j] = b1[bn + tx * 4 + j];
        if (HASB2) bias[j] += b2[bn + tx * 4 + j];
    }
#pragma unroll
    for (int i = 0; i < 4; i++) {
        float2 v0 = unpack2f(acc[i][0]);
        float2 v1 = unpack2f(acc[i][1]);
        float2 v2 = unpack2f(acc[i][2]);
        float2 v3 = unpack2f(acc[i][3]);
        float4 o0 = make_float4(v0.x + bias[0], v1.x + bias[1], v2.x + bias[2], v3.x + bias[3]);
        float4 o1 = make_float4(v0.y + bias[0], v1.y + bias[1], v2.y + bias[2], v3.y + bias[3]);
        if (RELU) {
            o0.x = fmaxf(o0.x, 0.f); o0.y = fmaxf(o0.y, 0.f);
            o0.z = fmaxf(o0.z, 0.f); o0.w = fmaxf(o0.w, 0.f);
            o1.x = fmaxf(o1.x, 0.f); o1.y = fmaxf(o1.y, 0.f);
            o1.z = fmaxf(o1.z, 0.f); o1.w = fmaxf(o1.w, 0.f);
        }
        size_t r0 = bm + ty * 8 + 2 * i;
        *(float4*)&C[r0 * Ndim + bn + tx * 4]       = o0;
        *(float4*)&C[(r0 + 1) * Ndim + bn + tx * 4] = o1;
    }
}

// ---------------- tf32 GEMM (BM=128, BN=128, BK=16), double-buffered ----------------
template <bool HASB2>
__global__ void __launch_bounds__(256) gemm_tf32(
    const float* __restrict__ A, const float* __restrict__ W,
    const float* __restrict__ b1, const float* __restrict__ b2,
    float* __restrict__ C, int Mdim, int Ndim, int Kdim) {
    __shared__ u32 As[2][2048];
    __shared__ u32 Bs[2][2048];

    const int tid = threadIdx.x;
    const int lane = tid & 31;
    const int wid = tid >> 5;
    const int wm = wid & 3;
    const int wn = wid >> 2;
    const int gid = lane >> 2;
    const int tig = lane & 3;
    const size_t bm = (size_t)blockIdx.x * 128;
    const size_t bn = (size_t)blockIdx.y * 128;

    float4 acc[2][8];
#pragma unroll
    for (int mt = 0; mt < 2; mt++)
#pragma unroll
        for (int nt = 0; nt < 8; nt++) acc[mt][nt] = make_float4(0.f, 0.f, 0.f, 0.f);

    int baseA[2], baseB[2];
    const float* ApG[2];
    const float* WpG[2];
#pragma unroll
    for (int i = 0; i < 2; i++) {
        int fidx = tid + 256 * i;
        int row = fidx >> 2, c4 = fidx & 3;
        int k8 = c4 >> 1, regK = c4 & 1;
        int mtile = row >> 4, r = row & 15;
        baseA[i] = (((k8 * 8 + mtile) * 32 + (r & 7) * 4)) * 4 + (r >> 3) + 2 * regK;
        ApG[i] = A + (bm + row) * (size_t)Kdim + c4 * 4;
        int ntile = row >> 3, ngid = row & 7;
        baseB[i] = (((k8 * 16 + ntile) * 32 + ngid * 4)) * 2 + regK;
        WpG[i] = W + (bn + row) * (size_t)Kdim + c4 * 4;
    }

    float4 av[2], wv[2];

#define TF32_LOAD(K0)                                  \
    av[0] = *(const float4*)(ApG[0] + (K0));           \
    av[1] = *(const float4*)(ApG[1] + (K0));           \
    wv[0] = *(const float4*)(WpG[0] + (K0));           \
    wv[1] = *(const float4*)(WpG[1] + (K0));

#define TF32_STORE(BUF)                                                        \
    _Pragma("unroll")                                                          \
    for (int i = 0; i < 2; i++) {                                              \
        As[BUF][baseA[i] + 0]  = cvt_tf32(av[i].x);                            \
        As[BUF][baseA[i] + 4]  = cvt_tf32(av[i].y);                            \
        As[BUF][baseA[i] + 8]  = cvt_tf32(av[i].z);                            \
        As[BUF][baseA[i] + 12] = cvt_tf32(av[i].w);                            \
        Bs[BUF][baseB[i] + 0]  = cvt_tf32(wv[i].x);                            \
        Bs[BUF][baseB[i] + 2]  = cvt_tf32(wv[i].y);                            \
        Bs[BUF][baseB[i] + 4]  = cvt_tf32(wv[i].z);                            \
        Bs[BUF][baseB[i] + 6]  = cvt_tf32(wv[i].w);                            \
    }

#define TF32_COMP(BUF)                                                             \
    _Pragma("unroll")                                                              \
    for (int k8 = 0; k8 < 2; k8++) {                                               \
        uint4 af[2]; uint2 bf[8];                                                  \
        _Pragma("unroll")                                                          \
        for (int mt = 0; mt < 2; mt++)                                             \
            af[mt] = *(const uint4*)&As[BUF][((k8 * 8 + wm * 2 + mt) * 32 + lane) * 4]; \
        _Pragma("unroll")                                                          \
        for (int nt = 0; nt < 8; nt++)                                             \
            bf[nt] = *(const uint2*)&Bs[BUF][((k8 * 16 + wn * 8 + nt) * 32 + lane) * 2]; \
        _Pragma("unroll")                                                          \
        for (int mt = 0; mt < 2; mt++)                                             \
            _Pragma("unroll")                                                      \
            for (int nt = 0; nt < 8; nt++)                                         \
                mma_tf32(acc[mt][nt], af[mt].x, af[mt].y, af[mt].z, af[mt].w,      \
                         bf[nt].x, bf[nt].y);                                      \
    }

    TF32_LOAD(0);
    TF32_STORE(0);
    __syncthreads();
    const int nb = Kdim >> 4;
#pragma unroll 1
    for (int it = 1; it < nb; it++) {
        TF32_LOAD(it * 16);
        TF32_COMP((it - 1) & 1);
        TF32_STORE(it & 1);
        __syncthreads();
    }
    TF32_COMP((nb - 1) & 1);

#pragma unroll
    for (int mt = 0; mt < 2; mt++) {
        int row0 = (int)bm + wm * 32 + mt * 16 + gid;
#pragma unroll
        for (int nt = 0; nt < 8; nt++) {
            int col = (int)bn + wn * 64 + nt * 8 + 2 * tig;
            float bb0 = b1[col], bb1 = b1[col + 1];
            if (HASB2) { bb0 += b2[col]; bb1 += b2[col + 1]; }
            *(float2*)&C[(size_t)row0 * Ndim + col] =
                make_float2(acc[mt][nt].x + bb0, acc[mt][nt].y + bb1);
            *(float2*)&C[(size_t)(row0 + 8) * Ndim + col] =
                make_float2(acc[mt][nt].z + bb0, acc[mt][nt].w + bb1);
        }
    }
}

// ---------------- cluster-2 fp16 tensor-core encoder LSTM ----------------
// 128 CTAs = 64 clusters x 2. CTA: 16 rows x 512 gate cols. fp16 weights/h, fp32 acc.
// smem: hs[2][3072 u32] (24 KB) + 8 resident chunks (128 KB) + 4 staging slots (64 KB)
#define HS_BYTES 12288
#define RES_OFF  (2 * HS_BYTES)           // 24576
#define STG_OFF  (RES_OFF + 8 * 16384)    // 155648
#define ENC_SMEM (STG_OFF + 4 * 16384)    // 221184

#define CP_WAIT(n) asm volatile("cp.async.wait_group " #n ";" ::: "memory")

__global__ void __launch_bounds__(256, 1) __cluster_dims__(2, 1, 1)
lstm_enc_f16(const uint2* __restrict__ wh, const float* __restrict__ xg,
             float* __restrict__ h_all, float* __restrict__ z_last) {
    extern __shared__ __align__(16) char sm[];
    const int tid = threadIdx.x, lane = tid & 31, w = tid >> 5;
    const int gid = lane >> 2, tg = lane & 3;
    u32 rank;
    asm("mov.u32 %0, %%cluster_ctarank;" : "=r"(rank));
    const int b0 = (blockIdx.x >> 1) * 16;

    u32 smb;
    asm("{ .reg .u64 t; cvta.to.shared.u64 t, %1; cvt.u32.u64 %0, t; }"
        : "=r"(smb) : "l"((void*)sm));

    // per-warp copy: warp w owns bytes [w*2048, (w+1)*2048) of each 16 KB chunk
#define ISSUE_TO(c, byteoff)                                                     \
    {                                                                            \
        u32 dst_ = smb + (byteoff) + w * 2048 + lane * 16;                       \
        const uint2* src_ = wh + ((c) * 2 + (int)rank) * 2048 + w * 256 + lane * 2; \
        _Pragma("unroll")                                                        \
        for (int i_ = 0; i_ < 4; i_++)                                           \
            asm volatile("cp.async.cg.shared.global [%0], [%1], 16;"             \
                         :: "r"(dst_ + i_ * 512), "l"(src_ + i_ * 64) : "memory"); \
        asm volatile("cp.async.commit_group;" ::: "memory");                     \
    }
#define ISSUE(c) ISSUE_TO(c, STG_OFF + ((c) & 3) * 16384)

    // prologue: residents 0..7 + staging 8..11
#pragma unroll
    for (int c = 0; c < 8; c++) ISSUE_TO(c, RES_OFF + c * 16384);
#pragma unroll
    for (int c = 8; c < 12; c++) ISSUE(c);

    // zero h buffer 0
    for (int i = tid; i < HS_BYTES / 4; i += 256) ((u32*)sm)[i] = 0;
    CP_WAIT(0);
    asm volatile("barrier.cluster.arrive.aligned;" ::: "memory");
    asm volatile("barrier.cluster.wait.aligned;" ::: "memory");

    float4 acc[8];
    float cst[8];
#pragma unroll
    for (int i = 0; i < 8; i++) cst[i] = 0.f;

    const size_t ro0 = ((size_t)(b0 + gid) * Tc) * Gc;
    const size_t ro1 = ((size_t)(b0 + gid + 8) * Tc) * Gc;
    const int ncol = (int)rank * 512 + w * 64 + 2 * tg;
    int cur = 0;

#define CHUNK(c, byteoff)                                                        \
    {                                                                            \
        const u32* hp_ = hc + (c) * 192;                                         \
        u32 a0_ = hp_[tg * 24 + gid];                                            \
        u32 a1_ = hp_[tg * 24 + gid + 8];                                        \
        u32 a2_ = hp_[(4 + tg) * 24 + gid];                                      \
        u32 a3_ = hp_[(4 + tg) * 24 + gid + 8];                                  \
        const uint2* bp_ = (const uint2*)(sm + (byteoff)) + w * 256 + lane;      \
        _Pragma("unroll")                                                        \
        for (int nt_ = 0; nt_ < 8; nt_++) {                                      \
            uint2 b_ = bp_[nt_ * 32];                                            \
            mma_f16(acc[nt_], a0_, a1_, a2_, a3_, b_.x, b_.y);                   \
        }                                                                        \
    }
#define CHUNK_S(c) CHUNK(c, STG_OFF + ((c) & 3) * 16384)

#pragma unroll 1
    for (int t = 0; t < Tc; t++) {
        const u32* hc = (const u32*)(sm + cur * HS_BYTES);
        u32* hn = (u32*)(sm + (cur ^ 1) * HS_BYTES);

        // xg loads: issued now, consumed in epilogue
        float2 xv0[8], xv1[8];
        const float* xr0 = xg + ro0 + (size_t)t * Gc + ncol;
        const float* xr1 = xg + ro1 + (size_t)t * Gc + ncol;
#pragma unroll
        for (int nt = 0; nt < 8; nt++) {
            xv0[nt] = *(const float2*)(xr0 + nt * 8);
            xv1[nt] = *(const float2*)(xr1 + nt * 8);
        }
#pragma unroll
        for (int nt = 0; nt < 8; nt++) acc[nt] = make_float4(0.f, 0.f, 0.f, 0.f);

        if ((t & 1) == 0) {   // ascending: slots hold 8,9,10,11
            CHUNK_S(8);  ISSUE(12);
            CHUNK_S(9);  ISSUE(13);
            CHUNK_S(10); ISSUE(14);
            CHUNK_S(11); ISSUE(15);
#pragma unroll
            for (int c = 0; c < 8; c++) CHUNK(c, RES_OFF + c * 16384);
            CP_WAIT(3); CHUNK_S(12);
            CP_WAIT(2); CHUNK_S(13);
            CP_WAIT(1); CHUNK_S(14);
            CP_WAIT(0); CHUNK_S(15);
        } else {              // descending: slots hold 12,13,14,15
            CHUNK_S(15); ISSUE(11);
            CHUNK_S(14); ISSUE(10);
            CHUNK_S(13); ISSUE(9);
            CHUNK_S(12); ISSUE(8);
#pragma unroll
            for (int c = 0; c < 8; c++) CHUNK(c, RES_OFF + c * 16384);
            CP_WAIT(3); CHUNK_S(11);
            CP_WAIT(2); CHUNK_S(10);
            CP_WAIT(1); CHUNK_S(9);
            CP_WAIT(0); CHUNK_S(8);
        }

        // epilogue
        const u32 hn_byte = (u32)((cur ^ 1) * HS_BYTES);
#pragma unroll
        for (int g = 0; g < 2; g++) {
            float4 I = acc[4 * g + 0], F = acc[4 * g + 1];
            float4 G = acc[4 * g + 2], O = acc[4 * g + 3];
            I.x += xv0[4 * g + 0].x; I.y += xv0[4 * g + 0].y;
            I.z += xv1[4 * g + 0].x; I.w += xv1[4 * g + 0].y;
            F.x += xv0[4 * g + 1].x; F.y += xv0[4 * g + 1].y;
            F.z += xv1[4 * g + 1].x; F.w += xv1[4 * g + 1].y;
            G.x += xv0[4 * g + 2].x; G.y += xv0[4 * g + 2].y;
            G.z += xv1[4 * g + 2].x; G.w += xv1[4 * g + 2].y;
            O.x += xv0[4 * g + 3].x; O.y += xv0[4 * g + 3].y;
            O.z += xv1[4 * g + 3].x; O.w += xv1[4 * g + 3].y;

            float h[4];
            {
                float cc = sigf(F.x) * cst[g * 4 + 0] + sigf(I.x) * tanh_(G.x);
                cst[g * 4 + 0] = cc; h[0] = sigf(O.x) * tanh_(cc);
            }
            {
                float cc = sigf(F.y) * cst[g * 4 + 1] + sigf(I.y) * tanh_(G.y);
                cst[g * 4 + 1] = cc; h[1] = sigf(O.y) * tanh_(cc);
            }
            {
                float cc = sigf(F.z) * cst[g * 4 + 2] + sigf(I.z) * tanh_(G.z);
                cst[g * 4 + 2] = cc; h[2] = sigf(O.z) * tanh_(cc);
            }
            {
                float cc = sigf(F.w) * cst[g * 4 + 3] + sigf(I.w) * tanh_(G.w);
                cst[g * 4 + 3] = cc; h[3] = sigf(O.w) * tanh_(cc);
            }

            u32 p01 = packh2(h[0], h[1]);
            u32 p23 = packh2(h[2], h[3]);
            int k2 = (int)rank * 64 + w * 8 + g * 4 + tg;   // j0 = 2*k2
            hn[k2 * 24 + gid]     = p01;
            hn[k2 * 24 + gid + 8] = p23;
            u32 la = smb + hn_byte + (u32)(k2 * 24 + gid) * 4u;
            u32 ra;
            asm("mapa.shared::cluster.u32 %0, %1, %2;" : "=r"(ra) : "r"(la), "r"(rank ^ 1u));
            asm volatile("st.shared::cluster.u32 [%0], %1;" :: "r"(ra), "r"(p01));
            asm volatile("st.shared::cluster.u32 [%0+32], %1;" :: "r"(ra), "r"(p23));

            int j0 = 2 * k2;
            if (h_all) {
                *(float2*)&h_all[((size_t)(b0 + gid) * Tc + t) * Hc + j0] =
                    make_float2(h[0], h[1]);
                *(float2*)&h_all[((size_t)(b0 + gid + 8) * Tc + t) * Hc + j0] =
                    make_float2(h[2], h[3]);
            }
            if (z_last && t == Tc - 1) {
                *(float2*)&z_last[(size_t)(b0 + gid) * Hc + j0] = make_float2(h[0], h[1]);
                *(float2*)&z_last[(size_t)(b0 + gid + 8) * Hc + j0] = make_float2(h[2], h[3]);
            }
        }
        asm volatile("barrier.cluster.arrive.aligned;" ::: "memory");
        asm volatile("barrier.cluster.wait.aligned;" ::: "memory");
        cur ^= 1;
    }
}

// ---------------- decoder LSTM (H=64), all weights in smem ----------------
__global__ void __launch_bounds__(256) lstm_dec(
    const float4* __restrict__ w4, const float* __restrict__ xg,
    float* __restrict__ h_out, int per_t) {
    extern __shared__ __align__(16) char smraw[];
    float2 (*shh)[Mc][4] = (float2(*)[Mc][4])smraw;
    float4* wc = (float4*)(smraw + 2 * Mc * 4 * sizeof(float2));

    const int b0 = blockIdx.x * 8;
    const int j = threadIdx.x & 63;
    const int rg = threadIdx.x >> 6;

    for (int idx = threadIdx.x; idx < Mc * Mc; idx += 256)
        wc[idx] = w4[idx];
    shh[0][j][rg] = make_float2(0.f, 0.f);
    __syncthreads();

    float c0 = 0.f, c1 = 0.f;
    ull base[4];
    if (!per_t) {
#pragma unroll
        for (int g = 0; g < 4; g++)
            base[g] = pack2f(xg[(size_t)(b0 + rg) * GMc + g * Mc + j],
                             xg[(size_t)(b0 + rg + 4) * GMc + g * Mc + j]);
    }

    int cur = 0;
#pragma unroll 1
    for (int t = 0; t < Tc; t++) {
        ull acc[4];
        if (per_t) {
#pragma unroll
            for (int g = 0; g < 4; g++)
                acc[g] = pack2f(xg[((size_t)(b0 + rg) * Tc + t) * GMc + g * Mc + j],
                                xg[((size_t)(b0 + rg + 4) * Tc + t) * GMc + g * Mc + j]);
        } else {
#pragma unroll
            for (int g = 0; g < 4; g++) acc[g] = base[g];
        }

        const float2(*shc)[4] = shh[cur];
#pragma unroll 1
        for (int k = 0; k < Mc; k += 16) {
#pragma unroll
            for (int u = 0; u < 16; u++) {
                float4 wv = wc[(k + u) * Mc + j];
                ull h2 = *(const ull*)&shc[k + u][rg];
                acc[0] = fma2f(h2, pack2f(wv.x, wv.x), acc[0]);
                acc[1] = fma2f(h2, pack2f(wv.y, wv.y), acc[1]);
                acc[2] = fma2f(h2, pack2f(wv.z, wv.z), acc[2]);
                acc[3] = fma2f(h2, pack2f(wv.w, wv.w), acc[3]);
            }
        }

        float2 iv = unpack2f(acc[0]);
        float2 fv = unpack2f(acc[1]);
        float2 gv = unpack2f(acc[2]);
        float2 ov = unpack2f(acc[3]);
        c0 = sigf(fv.x) * c0 + sigf(iv.x) * tanh_(gv.x);
        float h0 = sigf(ov.x) * tanh_(c0);
        c1 = sigf(fv.y) * c1 + sigf(iv.y) * tanh_(gv.y);
        float h1 = sigf(ov.y) * tanh_(c1);

        int nxt = cur ^ 1;
        shh[nxt][j][rg] = make_float2(h0, h1);
        h_out[((size_t)(b0 + rg) * Tc + t) * Mc + j]     = h0;
        h_out[((size_t)(b0 + rg + 4) * Tc + t) * Mc + j] = h1;
        __syncthreads();
        cur = nxt;
    }
}

// ---------------- launch ----------------
extern "C" void kernel_launch(void* const* d_in, const int* in_sizes, int n_in,
                              void* d_out, int out_size) {
    const float* x    = (const float*)d_in[0];
    const float* in_W = (const float*)d_in[1];
    const float* in_b = (const float*)d_in[2];
    const float* eW0i = (const float*)d_in[3];
    const float* eW0h = (const float*)d_in[4];
    const float* eb0i = (const float*)d_in[5];
    const float* eb0h = (const float*)d_in[6];
    const float* eW1i = (const float*)d_in[7];
    const float* eW1h = (const float*)d_in[8];
    const float* eb1i = (const float*)d_in[9];
    const float* eb1h = (const float*)d_in[10];
    const float* dW0i = (const float*)d_in[11];
    const float* dW0h = (const float*)d_in[12];
    const float* db0i = (const float*)d_in[13];
    const float* db0h = (const float*)d_in[14];
    const float* dW1i = (const float*)d_in[15];
    const float* dW1h = (const float*)d_in[16];
    const float* db1i = (const float*)d_in[17];
    const float* db1h = (const float*)d_in[18];
    const float* outW = (const float*)d_in[19];
    const float* outb = (const float*)d_in[20];
    float* out = (float*)d_out;

    float *xg, *mid, *bufA, *bufB, *z, *xgd0, *wp, *bp, *w4d0, *w4d1;
    uint2 *wh0, *wh1;
    cudaGetSymbolAddress((void**)&xg,   g_xg);
    cudaGetSymbolAddress((void**)&mid,  g_mid);
    cudaGetSymbolAddress((void**)&bufA, g_bufA);
    cudaGetSymbolAddress((void**)&bufB, g_bufB);
    cudaGetSymbolAddress((void**)&z,    g_z);
    cudaGetSymbolAddress((void**)&xgd0, g_xgd0);
    cudaGetSymbolAddress((void**)&wh0,  g_wh0);
    cudaGetSymbolAddress((void**)&wh1,  g_wh1);
    cudaGetSymbolAddress((void**)&wp,   g_wp);
    cudaGetSymbolAddress((void**)&bp,   g_bp);
    cudaGetSymbolAddress((void**)&w4d0, g_w4d0);
    cudaGetSymbolAddress((void**)&w4d1, g_w4d1);

    const int MT = Bc * Tc;
    const int DEC_SMEM = 2 * Mc * 4 * sizeof(float2) + Mc * Mc * sizeof(float4);
    static int configured = 0;
    if (!configured) {
        cudaFuncSetAttribute(lstm_enc_f16, cudaFuncAttributeMaxDynamicSharedMemorySize, ENC_SMEM);
        cudaFuncSetAttribute(lstm_dec, cudaFuncAttributeMaxDynamicSharedMemorySize, DEC_SMEM);
        configured = 1;
    }

    // 1) enc0 prep
    prep_enc16<<<1280, 256>>>(eW0h, eW0i, eb0i, eb0h, wh0, wp, bp, Mc);
    // 2) h0 = relu(x @ in_W^T + in_b)
    gemm64<true, false><<<dim3(MT / 128, 1), 256>>>(x, in_W, in_b, nullptr, bufA, MT, Mc, Dc);
    // 3) xg0 (permuted) = h0 @ wp^T + bp
    gemm_tf32<false><<<dim3(MT / 128, Gc / 128), 256>>>(bufA, wp, bp, nullptr, xg, MT, Gc, Mc);
    // 4) enc0 recurrence -> h_enc0 (ncu profiles this)
    lstm_enc_f16<<<128, 256, ENC_SMEM>>>(wh0, xg, mid, nullptr);
    // 5) enc1 prep
    prep_enc16<<<1280, 256>>>(eW1h, eW1i, eb1i, eb1h, wh1, wp, bp, Hc);
    // 6) xg1 (permuted) = h_enc0 @ wp^T + bp
    gemm_tf32<false><<<dim3(MT / 128, Gc / 128), 256>>>(mid, wp, bp, nullptr, xg, MT, Gc, Hc);
    // 7) enc1 recurrence -> z
    lstm_enc_f16<<<128, 256, ENC_SMEM>>>(wh1, xg, nullptr, z);
    // 8-9) dec preps
    prep_w4<<<dim3(2, 2, 4), dim3(32, 8)>>>(dW0h, w4d0, Mc);
    prep_w4<<<dim3(2, 2, 4), dim3(32, 8)>>>(dW1h, w4d1, Mc);
    // 10) xg_dec0 = z @ dW0i^T + db0i + db0h (t-const)
    gemm_tf32<true><<<dim3(Bc / 128, GMc / 128), 256>>>(z, dW0i, db0i, db0h, xgd0, Bc, GMc, Hc);
    // 11) dec0 -> d0
    lstm_dec<<<Bc / 8, 256, DEC_SMEM>>>((const float4*)w4d0, xgd0, bufA, 0);
    // 12) xg_dec1 = d0 @ dW1i^T + db1i + db1h
    gemm_tf32<true><<<dim3(MT / 128, GMc / 128), 256>>>(bufA, dW1i, db1i, db1h, mid, MT, GMc, Mc);
    // 13) dec1 -> d1
    lstm_dec<<<Bc / 8, 256, DEC_SMEM>>>((const float4*)w4d1, mid, bufB, 1);
    // 14) out = d1 @ out_W^T + out_b
    gemm_tf32<false><<<dim3(MT / 128, Dc / 128), 256>>>(bufB, outW, outb, nullptr, out, MT, Dc, Mc);
}

// round 8
// speedup vs baseline: 6.1883x; 1.0249x over previous
#include <cuda_runtime.h>
#include <cuda_fp16.h>

// ---------------- problem dims ----------------
#define Bc   1024
#define Tc   100
#define Dc   256
#define Hc   256
#define Gc   1024
#define Mc   64
#define GMc  256

typedef unsigned long long ull;
typedef unsigned int u32;

// ---------------- device scratch ----------------
__device__ float g_xg  [(size_t)Bc * Tc * Gc / 2];  // fp16 xg (210 MB as half)
__device__ float g_mid [(size_t)Bc * Tc * Hc];
__device__ float g_bufA[(size_t)Bc * Tc * Mc];
__device__ float g_bufB[(size_t)Bc * Tc * Mc];
__device__ float g_z   [Bc * Hc];
__device__ float g_xgd0[Bc * GMc];
__device__ uint4 g_wh0 [32768];            // enc0 Whh fp16 B-fragments (512 KB)
__device__ uint4 g_wh1 [32768];            // enc1
__device__ float g_wp  [Gc * Hc];
__device__ float g_bp  [Gc];
__device__ float g_w4d0[(Mc * Mc + 1024) * 4];
__device__ float g_w4d1[(Mc * Mc + 1024) * 4];

// ---------------- helpers ----------------
__device__ __forceinline__ ull pack2f(float x, float y) {
    ull r; asm("mov.b64 %0, {%1, %2};" : "=l"(r) : "f"(x), "f"(y)); return r;
}
__device__ __forceinline__ float2 unpack2f(ull v) {
    float2 r; asm("mov.b64 {%0, %1}, %2;" : "=f"(r.x), "=f"(r.y) : "l"(v)); return r;
}
__device__ __forceinline__ ull fma2f(ull a, ull b, ull c) {
    ull d; asm("fma.rn.f32x2 %0, %1, %2, %3;" : "=l"(d) : "l"(a), "l"(b), "l"(c)); return d;
}
__device__ __forceinline__ float sigf(float x) {
    return __fdividef(1.0f, 1.0f + __expf(-x));
}
__device__ __forceinline__ float tanh_(float x) {
    return 1.0f - __fdividef(2.0f, __expf(2.0f * x) + 1.0f);
}
__device__ __forceinline__ u32 cvt_tf32(float x) {
    u32 r; asm("cvt.rna.tf32.f32 %0, %1;" : "=r"(r) : "f"(x)); return r;
}
__device__ __forceinline__ void mma_tf32(float4& d, u32 a0, u32 a1, u32 a2, u32 a3,
                                         u32 b0, u32 b1) {
    asm("mma.sync.aligned.m16n8k8.row.col.f32.tf32.tf32.f32 "
        "{%0,%1,%2,%3}, {%4,%5,%6,%7}, {%8,%9}, {%0,%1,%2,%3};"
        : "+f"(d.x), "+f"(d.y), "+f"(d.z), "+f"(d.w)
        : "r"(a0), "r"(a1), "r"(a2), "r"(a3), "r"(b0), "r"(b1));
}
__device__ __forceinline__ void mma_f16(float4& d, u32 a0, u32 a1, u32 a2, u32 a3,
                                        u32 b0, u32 b1) {
    asm("mma.sync.aligned.m16n8k16.row.col.f32.f16.f16.f32 "
        "{%0,%1,%2,%3}, {%4,%5,%6,%7}, {%8,%9}, {%0,%1,%2,%3};"
        : "+f"(d.x), "+f"(d.y), "+f"(d.z), "+f"(d.w)
        : "r"(a0), "r"(a1), "r"(a2), "r"(a3), "r"(b0), "r"(b1));
}
__device__ __forceinline__ u32 packh2(float a, float b) {
    __half2 h = __floats2half2_rn(a, b);
    return *(u32*)&h;
}
__device__ __forceinline__ float2 unpackh2(u32 v) {
    return __half22float2(*(__half2*)&v);
}

// gate-col permutation (cluster-2, 16 warps): n' = rank*512 + w*32 + gate*8 + c
//   orig = gate*256 + rank*128 + w*8 + c

// ---------------- enc prep: Whh -> fp16 B-fragments, Wih/bias permute ----------------
__global__ void prep_enc16(const float* __restrict__ Wh, const float* __restrict__ Wi,
                           const float* __restrict__ bi, const float* __restrict__ bh,
                           uint2* __restrict__ wh, float* __restrict__ Wp,
                           float* __restrict__ bp, int K) {
    int bx = blockIdx.x;
    if (bx < 256) {
        // t2 = (((c*2+rank)*16 + w)*4 + nt)*32 + lane
        int t2 = bx * 256 + threadIdx.x;
        int lane = t2 & 31, nt = (t2 >> 5) & 3, w = (t2 >> 7) & 15;
        int rank = (t2 >> 11) & 1, c = t2 >> 12;
        int gid = lane >> 2, tt = lane & 3;
        int n = nt * 256 + rank * 128 + w * 8 + gid;
        int k0 = 16 * c + 2 * tt;
        uint2 v;
        v.x = packh2(Wh[(size_t)n * Hc + k0],     Wh[(size_t)n * Hc + k0 + 1]);
        v.y = packh2(Wh[(size_t)n * Hc + k0 + 8], Wh[(size_t)n * Hc + k0 + 9]);
        wh[t2] = v;
    } else {
        int np = bx - 256;
        int rank = np >> 9, w = (np >> 5) & 15, nt = (np >> 3) & 3, c = np & 7;
        int orig = nt * 256 + rank * 128 + w * 8 + c;
        for (int k = threadIdx.x; k < K; k += blockDim.x)
            Wp[(size_t)np * K + k] = Wi[(size_t)orig * K + k];
        if (threadIdx.x == 0) bp[np] = bi[orig] + bh[orig];
    }
}

// ---------------- dec weight prep ----------------
__global__ void prep_w4(const float* __restrict__ src, float* __restrict__ dst, int H) {
    __shared__ float tile[32][33];
    int g = blockIdx.z;
    int k0 = blockIdx.x * 32, j0 = blockIdx.y * 32;
    int x = threadIdx.x, y = threadIdx.y;
#pragma unroll
    for (int i = 0; i < 32; i += 8)
        tile[y + i][x] = src[(size_t)(g * H + j0 + y + i) * H + k0 + x];
    __syncthreads();
#pragma unroll
    for (int i = 0; i < 32; i += 8)
        dst[((size_t)(k0 + y + i) * H + (j0 + x)) * 4 + g] = tile[x][y + i];
}

// ---------------- fp32 GEMM (BM=128, BN=64), relu ----------------
template <bool RELU, bool HASB2>
__global__ void __launch_bounds__(256) gemm64(
    const float* __restrict__ A, const float* __restrict__ W,
    const float* __restrict__ b1, const float* __restrict__ b2,
    float* __restrict__ C, int Mdim, int Ndim, int Kdim) {
    constexpr int BK = 16;
    __shared__ float As[BK][128];
    __shared__ float Ws[BK][64];

    const int tid = threadIdx.x;
    const int tx = tid & 15;
    const int ty = tid >> 4;
    const size_t bm = (size_t)blockIdx.x * 128;
    const size_t bn = (size_t)blockIdx.y * 64;
    const int lr = tid >> 2;
    const int lk = (tid & 3) << 2;

    ull acc[4][4];
#pragma unroll
    for (int i = 0; i < 4; i++)
#pragma unroll
        for (int j = 0; j < 4; j++) acc[i][j] = 0ull;

    const float* Ap0 = A + (bm + lr) * (size_t)Kdim + lk;
    const float* Ap1 = A + (bm + lr + 64) * (size_t)Kdim + lk;
    const float* Wpt = W + (bn + lr) * (size_t)Kdim + lk;

    for (int k0 = 0; k0 < Kdim; k0 += BK) {
        float4 av0 = *(const float4*)(Ap0 + k0);
        float4 av1 = *(const float4*)(Ap1 + k0);
        float4 wv  = *(const float4*)(Wpt + k0);
        __syncthreads();
        As[lk + 0][lr] = av0.x; As[lk + 1][lr] = av0.y;
        As[lk + 2][lr] = av0.z; As[lk + 3][lr] = av0.w;
        As[lk + 0][lr + 64] = av1.x; As[lk + 1][lr + 64] = av1.y;
        As[lk + 2][lr + 64] = av1.z; As[lk + 3][lr + 64] = av1.w;
        Ws[lk + 0][lr] = wv.x; Ws[lk + 1][lr] = wv.y;
        Ws[lk + 2][lr] = wv.z; Ws[lk + 3][lr] = wv.w;
        __syncthreads();
#pragma unroll
        for (int kk = 0; kk < BK; kk++) {
            float4 a0 = *(const float4*)&As[kk][ty * 8];
            float4 a1 = *(const float4*)&As[kk][ty * 8 + 4];
            float4 w4 = *(const float4*)&Ws[kk][tx * 4];
            ull a2[4] = {pack2f(a0.x, a0.y), pack2f(a0.z, a0.w),
                         pack2f(a1.x, a1.y), pack2f(a1.z, a1.w)};
            ull w2[4] = {pack2f(w4.x, w4.x), pack2f(w4.y, w4.y),
                         pack2f(w4.z, w4.z), pack2f(w4.w, w4.w)};
#pragma unroll
            for (int i = 0; i < 4; i++)
#pragma unroll
                for (int j = 0; j < 4; j++)
                    acc[i][j] = fma2f(a2[i], w2[j], acc[i][j]);
        }
    }

    float bias[4];
#pragma unroll
    for (int j = 0; j < 4; j++) {
        bias[j] = b1[bn + tx * 4 + j];
        if (HASB2) bias[j] += b2[bn + tx * 4 + j];
    }
#pragma unroll
    for (int i = 0; i < 4; i++) {
        float2 v0 = unpack2f(acc[i][0]);
        float2 v1 = unpack2f(acc[i][1]);
        float2 v2 = unpack2f(acc[i][2]);
        float2 v3 = unpack2f(acc[i][3]);
        float4 o0 = make_float4(v0.x + bias[0], v1.x + bias[1], v2.x + bias[2], v3.x + bias[3]);
        float4 o1 = make_float4(v0.y + bias[0], v1.y + bias[1], v2.y + bias[2], v3.y + bias[3]);
        if (RELU) {
            o0.x = fmaxf(o0.x, 0.f); o0.y = fmaxf(o0.y, 0.f);
            o0.z = fmaxf(o0.z, 0.f); o0.w = fmaxf(o0.w, 0.f);
            o1.x = fmaxf(o1.x, 0.f); o1.y = fmaxf(o1.y, 0.f);
            o1.z = fmaxf(o1.z, 0.f); o1.w = fmaxf(o1.w, 0.f);
        }
        size_t r0 = bm + ty * 8 + 2 * i;
        *(float4*)&C[r0 * Ndim + bn + tx * 4]       = o0;
        *(float4*)&C[(r0 + 1) * Ndim + bn + tx * 4] = o1;
    }
}

// ---------------- tf32 GEMM (BM=128, BN=128, BK=16), optional fp16 output ----------------
template <bool HASB2, bool HOUT>
__global__ void __launch_bounds__(256) gemm_tf32(
    const float* __restrict__ A, const float* __restrict__ W,
    const float* __restrict__ b1, const float* __restrict__ b2,
    float* __restrict__ C, int Mdim, int Ndim, int Kdim) {
    __shared__ u32 As[2][2048];
    __shared__ u32 Bs[2][2048];

    const int tid = threadIdx.x;
    const int lane = tid & 31;
    const int wid = tid >> 5;
    const int wm = wid & 3;
    const int wn = wid >> 2;
    const int gid = lane >> 2;
    const int tig = lane & 3;
    const size_t bm = (size_t)blockIdx.x * 128;
    const size_t bn = (size_t)blockIdx.y * 128;

    float4 acc[2][8];
#pragma unroll
    for (int mt = 0; mt < 2; mt++)
#pragma unroll
        for (int nt = 0; nt < 8; nt++) acc[mt][nt] = make_float4(0.f, 0.f, 0.f, 0.f);

    int baseA[2], baseB[2];
    const float* ApG[2];
    const float* WpG[2];
#pragma unroll
    for (int i = 0; i < 2; i++) {
        int fidx = tid + 256 * i;
        int row = fidx >> 2, c4 = fidx & 3;
        int k8 = c4 >> 1, regK = c4 & 1;
        int mtile = row >> 4, r = row & 15;
        baseA[i] = (((k8 * 8 + mtile) * 32 + (r & 7) * 4)) * 4 + (r >> 3) + 2 * regK;
        ApG[i] = A + (bm + row) * (size_t)Kdim + c4 * 4;
        int ntile = row >> 3, ngid = row & 7;
        baseB[i] = (((k8 * 16 + ntile) * 32 + ngid * 4)) * 2 + regK;
        WpG[i] = W + (bn + row) * (size_t)Kdim + c4 * 4;
    }

    float4 av[2], wv[2];

#define TF32_LOAD(K0)                                  \
    av[0] = *(const float4*)(ApG[0] + (K0));           \
    av[1] = *(const float4*)(ApG[1] + (K0));           \
    wv[0] = *(const float4*)(WpG[0] + (K0));           \
    wv[1] = *(const float4*)(WpG[1] + (K0));

#define TF32_STORE(BUF)                                                        \
    _Pragma("unroll")                                                          \
    for (int i = 0; i < 2; i++) {                                              \
        As[BUF][baseA[i] + 0]  = cvt_tf32(av[i].x);                            \
        As[BUF][baseA[i] + 4]  = cvt_tf32(av[i].y);                            \
        As[BUF][baseA[i] + 8]  = cvt_tf32(av[i].z);                            \
        As[BUF][baseA[i] + 12] = cvt_tf32(av[i].w);                            \
        Bs[BUF][baseB[i] + 0]  = cvt_tf32(wv[i].x);                            \
        Bs[BUF][baseB[i] + 2]  = cvt_tf32(wv[i].y);                            \
        Bs[BUF][baseB[i] + 4]  = cvt_tf32(wv[i].z);                            \
        Bs[BUF][baseB[i] + 6]  = cvt_tf32(wv[i].w);                            \
    }

#define TF32_COMP(BUF)                                                             \
    _Pragma("unroll")                                                              \
    for (int k8 = 0; k8 < 2; k8++) {                                               \
        uint4 af[2]; uint2 bf[8];                                                  \
        _Pragma("unroll")                                                          \
        for (int mt = 0; mt < 2; mt++)                                             \
            af[mt] = *(const uint4*)&As[BUF][((k8 * 8 + wm * 2 + mt) * 32 + lane) * 4]; \
        _Pragma("unroll")                                                          \
        for (int nt = 0; nt < 8; nt++)                                             \
            bf[nt] = *(const uint2*)&Bs[BUF][((k8 * 16 + wn * 8 + nt) * 32 + lane) * 2]; \
        _Pragma("unroll")                                                          \
        for (int mt = 0; mt < 2; mt++)                                             \
            _Pragma("unroll")                                                      \
            for (int nt = 0; nt < 8; nt++)                                         \
                mma_tf32(acc[mt][nt], af[mt].x, af[mt].y, af[mt].z, af[mt].w,      \
                         bf[nt].x, bf[nt].y);                                      \
    }

    TF32_LOAD(0);
    TF32_STORE(0);
    __syncthreads();
    const int nb = Kdim >> 4;
#pragma unroll 1
    for (int it = 1; it < nb; it++) {
        TF32_LOAD(it * 16);
        TF32_COMP((it - 1) & 1);
        TF32_STORE(it & 1);
        __syncthreads();
    }
    TF32_COMP((nb - 1) & 1);

#pragma unroll
    for (int mt = 0; mt < 2; mt++) {
        int row0 = (int)bm + wm * 32 + mt * 16 + gid;
#pragma unroll
        for (int nt = 0; nt < 8; nt++) {
            int col = (int)bn + wn * 64 + nt * 8 + 2 * tig;
            float bb0 = b1[col], bb1 = b1[col + 1];
            if (HASB2) { bb0 += b2[col]; bb1 += b2[col + 1]; }
            if (HOUT) {
                u32* Ch = (u32*)C;
                Ch[((size_t)row0 * Ndim + col) >> 1] =
                    packh2(acc[mt][nt].x + bb0, acc[mt][nt].y + bb1);
                Ch[((size_t)(row0 + 8) * Ndim + col) >> 1] =
                    packh2(acc[mt][nt].z + bb0, acc[mt][nt].w + bb1);
            } else {
                *(float2*)&C[(size_t)row0 * Ndim + col] =
                    make_float2(acc[mt][nt].x + bb0, acc[mt][nt].y + bb1);
                *(float2*)&C[(size_t)(row0 + 8) * Ndim + col] =
                    make_float2(acc[mt][nt].z + bb0, acc[mt][nt].w + bb1);
            }
        }
    }
}

// ---------------- cluster-2 fp16 encoder LSTM, 512 threads ----------------
// 128 CTAs = 64 clusters x 2. CTA: 16 rows x 512 gate cols, 16 warps x 4 n-tiles.
#define HS_BYTES 12288
#define RES_OFF  (2 * HS_BYTES)           // 24576
#define STG_OFF  (RES_OFF + 8 * 16384)    // 155648
#define ENC_SMEM (STG_OFF + 4 * 16384)    // 221184

#define CP_WAIT(n) asm volatile("cp.async.wait_group " #n ";" ::: "memory")
#define CL_ARRIVE() asm volatile("barrier.cluster.arrive.aligned;" ::: "memory")
#define CL_WAIT()   asm volatile("barrier.cluster.wait.aligned;" ::: "memory")

__global__ void __launch_bounds__(512, 1) __cluster_dims__(2, 1, 1)
lstm_enc_f16(const uint2* __restrict__ wh, const __half* __restrict__ xgh,
             float* __restrict__ h_all, float* __restrict__ z_last) {
    extern __shared__ __align__(16) char sm[];
    const int tid = threadIdx.x, lane = tid & 31, w = tid >> 5;   // w: 0..15
    const int gid = lane >> 2, tg = lane & 3;
    u32 rank;
    asm("mov.u32 %0, %%cluster_ctarank;" : "=r"(rank));
    const int b0 = (blockIdx.x >> 1) * 16;

    u32 smb;
    asm("{ .reg .u64 t; cvta.to.shared.u64 t, %1; cvt.u32.u64 %0, t; }"
        : "=r"(smb) : "l"((void*)sm));

    // warp w copies bytes [w*1024, (w+1)*1024) of each 16 KB chunk (= its own B slice)
#define ISSUE_TO(c, byteoff)                                                     \
    {                                                                            \
        u32 dst_ = smb + (byteoff) + w * 1024 + lane * 16;                       \
        const uint2* src_ = wh + ((c) * 2 + (int)rank) * 2048 + w * 128 + lane * 2; \
        asm volatile("cp.async.cg.shared.global [%0], [%1], 16;"                 \
                     :: "r"(dst_), "l"(src_) : "memory");                        \
        asm volatile("cp.async.cg.shared.global [%0], [%1], 16;"                 \
                     :: "r"(dst_ + 512), "l"(src_ + 64) : "memory");             \
        asm volatile("cp.async.commit_group;" ::: "memory");                     \
    }
#define ISSUE(c) ISSUE_TO(c, STG_OFF + ((c) & 3) * 16384)

    // prologue: residents 0..7 + staging 8..11
#pragma unroll
    for (int c = 0; c < 8; c++) ISSUE_TO(c, RES_OFF + c * 16384);
#pragma unroll
    for (int c = 8; c < 12; c++) ISSUE(c);

    for (int i = tid; i < HS_BYTES / 4; i += 512) ((u32*)sm)[i] = 0;
    CP_WAIT(0);
    CL_ARRIVE();          // paired with the wait at top of t=0

    float4 acc[4];
    float cst[4] = {0.f, 0.f, 0.f, 0.f};

    const size_t ro0 = ((size_t)(b0 + gid) * Tc) * Gc;
    const size_t ro1 = ((size_t)(b0 + gid + 8) * Tc) * Gc;
    const int ncol = (int)rank * 512 + w * 32 + 2 * tg;
    const int k2 = (int)rank * 64 + w * 4 + tg;   // h col-pair owned by this thread
    const int j0 = 2 * k2;
    int cur = 0;

#define CHUNK(c, byteoff)                                                        \
    {                                                                            \
        const u32* hp_ = hc + (c) * 192;                                         \
        u32 a0_ = hp_[tg * 24 + gid];                                            \
        u32 a1_ = hp_[tg * 24 + gid + 8];                                        \
        u32 a2_ = hp_[(4 + tg) * 24 + gid];                                      \
        u32 a3_ = hp_[(4 + tg) * 24 + gid + 8];                                  \
        const uint2* bp_ = (const uint2*)(sm + (byteoff)) + w * 128 + lane;      \
        _Pragma("unroll")                                                        \
        for (int nt_ = 0; nt_ < 4; nt_++) {                                      \
            uint2 b_ = bp_[nt_ * 32];                                            \
            mma_f16(acc[nt_], a0_, a1_, a2_, a3_, b_.x, b_.y);                   \
        }                                                                        \
    }
#define CHUNK_S(c) CHUNK(c, STG_OFF + ((c) & 3) * 16384)

#pragma unroll 1
    for (int t = 0; t < Tc; t++) {
        const u32* hc = (const u32*)(sm + cur * HS_BYTES);
        u32* hn = (u32*)(sm + (cur ^ 1) * HS_BYTES);

        // xg (fp16) loads: issued before the cluster wait, consumed in epilogue
        u32 xv0[4], xv1[4];
        const __half* xr0 = xgh + ro0 + (size_t)t * Gc + ncol;
        const __half* xr1 = xgh + ro1 + (size_t)t * Gc + ncol;
#pragma unroll
        for (int nt = 0; nt < 4; nt++) {
            xv0[nt] = *(const u32*)(xr0 + nt * 8);
            xv1[nt] = *(const u32*)(xr1 + nt * 8);
        }
#pragma unroll
        for (int nt = 0; nt < 4; nt++) acc[nt] = make_float4(0.f, 0.f, 0.f, 0.f);

        CL_WAIT();   // peer h (and at t=0, init) now visible; xg LDGs already in flight

        if ((t & 1) == 0) {   // slots hold 8,9,10,11
            CHUNK_S(8);  ISSUE(12);
            CHUNK_S(9);  ISSUE(13);
            CHUNK_S(10); ISSUE(14);
            CHUNK_S(11); ISSUE(15);
#pragma unroll
            for (int c = 0; c < 8; c++) CHUNK(c, RES_OFF + c * 16384);
            CP_WAIT(3); CHUNK_S(12);
            CP_WAIT(2); CHUNK_S(13);
            CP_WAIT(1); CHUNK_S(14);
            CP_WAIT(0); CHUNK_S(15);
        } else {              // slots hold 12,13,14,15
            CHUNK_S(15); ISSUE(11);
            CHUNK_S(14); ISSUE(10);
            CHUNK_S(13); ISSUE(9);
            CHUNK_S(12); ISSUE(8);
#pragma unroll
            for (int c = 0; c < 8; c++) CHUNK(c, RES_OFF + c * 16384);
            CP_WAIT(3); CHUNK_S(11);
            CP_WAIT(2); CHUNK_S(10);
            CP_WAIT(1); CHUNK_S(9);
            CP_WAIT(0); CHUNK_S(8);
        }

        // epilogue: acc[0..3] = I,F,G,O for cols (j0, j0+1) x rows (gid, gid+8)
        {
            float4 I = acc[0], F = acc[1], G = acc[2], O = acc[3];
            float2 xi0 = unpackh2(xv0[0]), xi1 = unpackh2(xv1[0]);
            float2 xf0 = unpackh2(xv0[1]), xf1 = unpackh2(xv1[1]);
            float2 xg0 = unpackh2(xv0[2]), xg1 = unpackh2(xv1[2]);
            float2 xo0 = unpackh2(xv0[3]), xo1 = unpackh2(xv1[3]);
            I.x += xi0.x; I.y += xi0.y; I.z += xi1.x; I.w += xi1.y;
            F.x += xf0.x; F.y += xf0.y; F.z += xf1.x; F.w += xf1.y;
            G.x += xg0.x; G.y += xg0.y; G.z += xg1.x; G.w += xg1.y;
            O.x += xo0.x; O.y += xo0.y; O.z += xo1.x; O.w += xo1.y;

            float h[4];
            {
                float cc = sigf(F.x) * cst[0] + sigf(I.x) * tanh_(G.x);
                cst[0] = cc; h[0] = sigf(O.x) * tanh_(cc);
            }
            {
                float cc = sigf(F.y) * cst[1] + sigf(I.y) * tanh_(G.y);
                cst[1] = cc; h[1] = sigf(O.y) * tanh_(cc);
            }
            {
                float cc = sigf(F.z) * cst[2] + sigf(I.z) * tanh_(G.z);
                cst[2] = cc; h[2] = sigf(O.z) * tanh_(cc);
            }
            {
                float cc = sigf(F.w) * cst[3] + sigf(I.w) * tanh_(G.w);
                cst[3] = cc; h[3] = sigf(O.w) * tanh_(cc);
            }

            u32 p01 = packh2(h[0], h[1]);
            u32 p23 = packh2(h[2], h[3]);
            const u32 hn_byte = (u32)((cur ^ 1) * HS_BYTES);
            hn[k2 * 24 + gid]     = p01;
            hn[k2 * 24 + gid + 8] = p23;
            u32 la = smb + hn_byte + (u32)(k2 * 24 + gid) * 4u;
            u32 ra;
            asm("mapa.shared::cluster.u32 %0, %1, %2;" : "=r"(ra) : "r"(la), "r"(rank ^ 1u));
            asm volatile("st.shared::cluster.u32 [%0], %1;" :: "r"(ra), "r"(p01));
            asm volatile("st.shared::cluster.u32 [%0+32], %1;" :: "r"(ra), "r"(p23));

            if (h_all) {
                *(float2*)&h_all[((size_t)(b0 + gid) * Tc + t) * Hc + j0] =
                    make_float2(h[0], h[1]);
                *(float2*)&h_all[((size_t)(b0 + gid + 8) * Tc + t) * Hc + j0] =
                    make_float2(h[2], h[3]);
            }
            if (z_last && t == Tc - 1) {
                *(float2*)&z_last[(size_t)(b0 + gid) * Hc + j0] = make_float2(h[0], h[1]);
                *(float2*)&z_last[(size_t)(b0 + gid + 8) * Hc + j0] = make_float2(h[2], h[3]);
            }
        }
        CL_ARRIVE();
        cur ^= 1;
    }
    CL_WAIT();   // drain: peer stores complete before smem teardown
}

// ---------------- decoder LSTM (H=64), all weights in smem ----------------
__global__ void __launch_bounds__(256) lstm_dec(
    const float4* __restrict__ w4, const float* __restrict__ xg,
    float* __restrict__ h_out, int per_t) {
    extern __shared__ __align__(16) char smraw[];
    float2 (*shh)[Mc][4] = (float2(*)[Mc][4])smraw;
    float4* wc = (float4*)(smraw + 2 * Mc * 4 * sizeof(float2));

    const int b0 = blockIdx.x * 8;
    const int j = threadIdx.x & 63;
    const int rg = threadIdx.x >> 6;

    for (int idx = threadIdx.x; idx < Mc * Mc; idx += 256)
        wc[idx] = w4[idx];
    shh[0][j][rg] = make_float2(0.f, 0.f);
    __syncthreads();

    float c0 = 0.f, c1 = 0.f;
    ull base[4];
    if (!per_t) {
#pragma unroll
        for (int g = 0; g < 4; g++)
            base[g] = pack2f(xg[(size_t)(b0 + rg) * GMc + g * Mc + j],
                             xg[(size_t)(b0 + rg + 4) * GMc + g * Mc + j]);
    }

    int cur = 0;
#pragma unroll 1
    for (int t = 0; t < Tc; t++) {
        ull acc[4];
        if (per_t) {
#pragma unroll
            for (int g = 0; g < 4; g++)
                acc[g] = pack2f(xg[((size_t)(b0 + rg) * Tc + t) * GMc + g * Mc + j],
                                xg[((size_t)(b0 + rg + 4) * Tc + t) * GMc + g * Mc + j]);
        } else {
#pragma unroll
            for (int g = 0; g < 4; g++) acc[g] = base[g];
        }

        const float2(*shc)[4] = shh[cur];
#pragma unroll 1
        for (int k = 0; k < Mc; k += 16) {
#pragma unroll
            for (int u = 0; u < 16; u++) {
                float4 wv = wc[(k + u) * Mc + j];
                ull h2 = *(const ull*)&shc[k + u][rg];
                acc[0] = fma2f(h2, pack2f(wv.x, wv.x), acc[0]);
                acc[1] = fma2f(h2, pack2f(wv.y, wv.y), acc[1]);
                acc[2] = fma2f(h2, pack2f(wv.z, wv.z), acc[2]);
                acc[3] = fma2f(h2, pack2f(wv.w, wv.w), acc[3]);
            }
        }

        float2 iv = unpack2f(acc[0]);
        float2 fv = unpack2f(acc[1]);
        float2 gv = unpack2f(acc[2]);
        float2 ov = unpack2f(acc[3]);
        c0 = sigf(fv.x) * c0 + sigf(iv.x) * tanh_(gv.x);
        float h0 = sigf(ov.x) * tanh_(c0);
        c1 = sigf(fv.y) * c1 + sigf(iv.y) * tanh_(gv.y);
        float h1 = sigf(ov.y) * tanh_(c1);

        int nxt = cur ^ 1;
        shh[nxt][j][rg] = make_float2(h0, h1);
        h_out[((size_t)(b0 + rg) * Tc + t) * Mc + j]     = h0;
        h_out[((size_t)(b0 + rg + 4) * Tc + t) * Mc + j] = h1;
        __syncthreads();
        cur = nxt;
    }
}

// ---------------- launch ----------------
extern "C" void kernel_launch(void* const* d_in, const int* in_sizes, int n_in,
                              void* d_out, int out_size) {
    const float* x    = (const float*)d_in[0];
    const float* in_W = (const float*)d_in[1];
    const float* in_b = (const float*)d_in[2];
    const float* eW0i = (const float*)d_in[3];
    const float* eW0h = (const float*)d_in[4];
    const float* eb0i = (const float*)d_in[5];
    const float* eb0h = (const float*)d_in[6];
    const float* eW1i = (const float*)d_in[7];
    const float* eW1h = (const float*)d_in[8];
    const float* eb1i = (const float*)d_in[9];
    const float* eb1h = (const float*)d_in[10];
    const float* dW0i = (const float*)d_in[11];
    const float* dW0h = (const float*)d_in[12];
    const float* db0i = (const float*)d_in[13];
    const float* db0h = (const float*)d_in[14];
    const float* dW1i = (const float*)d_in[15];
    const float* dW1h = (const float*)d_in[16];
    const float* db1i = (const float*)d_in[17];
    const float* db1h = (const float*)d_in[18];
    const float* outW = (const float*)d_in[19];
    const float* outb = (const float*)d_in[20];
    float* out = (float*)d_out;

    float *xg, *mid, *bufA, *bufB, *z, *xgd0, *wp, *bp, *w4d0, *w4d1;
    uint2 *wh0, *wh1;
    cudaGetSymbolAddress((void**)&xg,   g_xg);
    cudaGetSymbolAddress((void**)&mid,  g_mid);
    cudaGetSymbolAddress((void**)&bufA, g_bufA);
    cudaGetSymbolAddress((void**)&bufB, g_bufB);
    cudaGetSymbolAddress((void**)&z,    g_z);
    cudaGetSymbolAddress((void**)&xgd0, g_xgd0);
    cudaGetSymbolAddress((void**)&wh0,  g_wh0);
    cudaGetSymbolAddress((void**)&wh1,  g_wh1);
    cudaGetSymbolAddress((void**)&wp,   g_wp);
    cudaGetSymbolAddress((void**)&bp,   g_bp);
    cudaGetSymbolAddress((void**)&w4d0, g_w4d0);
    cudaGetSymbolAddress((void**)&w4d1, g_w4d1);

    const int MT = Bc * Tc;
    const int DEC_SMEM = 2 * Mc * 4 * sizeof(float2) + Mc * Mc * sizeof(float4);
    static int configured = 0;
    if (!configured) {
        cudaFuncSetAttribute(lstm_enc_f16, cudaFuncAttributeMaxDynamicSharedMemorySize, ENC_SMEM);
        cudaFuncSetAttribute(lstm_dec, cudaFuncAttributeMaxDynamicSharedMemorySize, DEC_SMEM);
        configured = 1;
    }

    // 1) enc0 prep
    prep_enc16<<<1280, 256>>>(eW0h, eW0i, eb0i, eb0h, wh0, wp, bp, Mc);
    // 2) h0 = relu(x @ in_W^T + in_b)
    gemm64<true, false><<<dim3(MT / 128, 1), 256>>>(x, in_W, in_b, nullptr, bufA, MT, Mc, Dc);
    // 3) xg0 (permuted, fp16) = h0 @ wp^T + bp
    gemm_tf32<false, true><<<dim3(MT / 128, Gc / 128), 256>>>(bufA, wp, bp, nullptr, xg, MT, Gc, Mc);
    // 4) enc0 recurrence -> h_enc0 (ncu profiles this)
    lstm_enc_f16<<<128, 512, ENC_SMEM>>>(wh0, (const __half*)xg, mid, nullptr);
    // 5) enc1 prep
    prep_enc16<<<1280, 256>>>(eW1h, eW1i, eb1i, eb1h, wh1, wp, bp, Hc);
    // 6) xg1 (permuted, fp16) = h_enc0 @ wp^T + bp
    gemm_tf32<false, true><<<dim3(MT / 128, Gc / 128), 256>>>(mid, wp, bp, nullptr, xg, MT, Gc, Hc);
    // 7) enc1 recurrence -> z
    lstm_enc_f16<<<128, 512, ENC_SMEM>>>(wh1, (const __half*)xg, nullptr, z);
    // 8-9) dec preps
    prep_w4<<<dim3(2, 2, 4), dim3(32, 8)>>>(dW0h, w4d0, Mc);
    prep_w4<<<dim3(2, 2, 4), dim3(32, 8)>>>(dW1h, w4d1, Mc);
    // 10) xg_dec0 = z @ dW0i^T + db0i + db0h (t-const, fp32)
    gemm_tf32<true, false><<<dim3(Bc / 128, GMc / 128), 256>>>(z, dW0i, db0i, db0h, xgd0, Bc, GMc, Hc);
    // 11) dec0 -> d0
    lstm_dec<<<Bc / 8, 256, DEC_SMEM>>>((const float4*)w4d0, xgd0, bufA, 0);
    // 12) xg_dec1 = d0 @ dW1i^T + db1i + db1h (fp32)
    gemm_tf32<true, false><<<dim3(MT / 128, GMc / 128), 256>>>(bufA, dW1i, db1i, db1h, mid, MT, GMc, Mc);
    // 13) dec1 -> d1
    lstm_dec<<<Bc / 8, 256, DEC_SMEM>>>((const float4*)w4d1, mid, bufB, 1);
    // 14) out = d1 @ out_W^T + out_b
    gemm_tf32<false, false><<<dim3(MT / 128, Dc / 128), 256>>>(bufB, outW, outb, nullptr, out, MT, Dc, Mc);
}